// round 2
// baseline (speedup 1.0000x reference)
#include <cuda_runtime.h>
#include <math.h>

#define DMODEL 4096
#define NH 32
#define NKV 4
#define HD 128
#define S_MAX 2048

// Scratch (no allocations allowed): Q/K/V post-projection + attention output.
__device__ float g_q[S_MAX * NH * HD];
__device__ float g_k[S_MAX * NKV * HD];
__device__ float g_v[S_MAX * NKV * HD];
__device__ float g_o[S_MAX * NH * HD];

// ---------------------------------------------------------------------------
// SGEMM: C[M,N] = A[M,K] @ B[K,N], row-major, fp32.
// 128x128 block tile, BK=8, 256 threads, 8x8 accumulators per thread.
// M,N,K assumed multiples of 128/128/8 (true for all calls here).
// ---------------------------------------------------------------------------
__global__ __launch_bounds__(256) void sgemm_kernel(const float* __restrict__ A,
                                                    const float* __restrict__ B,
                                                    float* __restrict__ C,
                                                    int M, int N, int K) {
    __shared__ float As[8][128];   // k-major (A transposed into smem)
    __shared__ float Bs[8][128];

    const int tid = threadIdx.x;
    const int tx = tid & 15;       // 0..15 -> N direction
    const int ty = tid >> 4;       // 0..15 -> M direction

    const float* Ab = A + (size_t)blockIdx.y * 128 * K;
    const float* Bb = B + (size_t)blockIdx.x * 128;

    // Load indices: A tile 128x8 (one float4 per thread), B tile 8x128.
    const int arow = tid >> 1;
    const int acol = (tid & 1) * 4;
    const int brow = tid >> 5;
    const int bcol = (tid & 31) * 4;

    float acc[8][8];
#pragma unroll
    for (int i = 0; i < 8; i++)
#pragma unroll
        for (int j = 0; j < 8; j++) acc[i][j] = 0.0f;

    for (int k0 = 0; k0 < K; k0 += 8) {
        float4 av = *(const float4*)(Ab + (size_t)arow * K + k0 + acol);
        As[acol + 0][arow] = av.x;
        As[acol + 1][arow] = av.y;
        As[acol + 2][arow] = av.z;
        As[acol + 3][arow] = av.w;
        *(float4*)&Bs[brow][bcol] =
            *(const float4*)(Bb + (size_t)(k0 + brow) * N + bcol);
        __syncthreads();

#pragma unroll
        for (int kk = 0; kk < 8; kk++) {
            float a[8], b[8];
#pragma unroll
            for (int i = 0; i < 8; i++) a[i] = As[kk][ty * 8 + i];
#pragma unroll
            for (int j = 0; j < 8; j++) b[j] = Bs[kk][tx * 8 + j];
#pragma unroll
            for (int i = 0; i < 8; i++)
#pragma unroll
                for (int j = 0; j < 8; j++)
                    acc[i][j] = fmaf(a[i], b[j], acc[i][j]);
        }
        __syncthreads();
    }

    float* Cb = C + ((size_t)blockIdx.y * 128 + ty * 8) * N
                  + (size_t)blockIdx.x * 128 + tx * 8;
#pragma unroll
    for (int i = 0; i < 8; i++) {
#pragma unroll
        for (int j = 0; j < 8; j += 4) {
            float4 o4 = make_float4(acc[i][j], acc[i][j + 1],
                                    acc[i][j + 2], acc[i][j + 3]);
            *(float4*)(Cb + (size_t)i * N + j) = o4;
        }
    }
}

// ---------------------------------------------------------------------------
// YaRN RoPE, in place on x laid out (S, nheads, 128).
// grid (S, nheads), 64 threads: thread j rotates the (j, j+64) pair.
// All math in fp32 to track the numpy reference exactly.
// ---------------------------------------------------------------------------
__global__ __launch_bounds__(64) void rope_kernel(float* __restrict__ x, int nheads) {
    const int s = blockIdx.x;
    const int h = blockIdx.y;
    const int j = threadIdx.x;   // 0..63 frequency index

    const float expo = (float)(2 * j) / 128.0f;
    float invf = 1.0f / powf(10000.0f, expo);
    const float wl = 6.283185307179586f / invf;           // wavelength
    const float r = 163840.0f / wl;                        // MAX_SEQ / wavelength
    float gamma = (r - 1.0f) / 31.0f;                      // (r-alpha)/(beta-alpha)
    gamma = fminf(fmaxf(gamma, 0.0f), 1.0f);
    invf = invf * ((1.0f - gamma) / 80.0f + gamma);        // yarn-adjusted inv_freq
    // angle = (t * inv_freq) / sqrt(0.1*ln(80)+1)
    const float ang = ((float)s * invf) / 1.19925088f;
    const float c = cosf(ang);
    const float sn = sinf(ang);

    float* base = x + ((size_t)s * nheads + h) * HD;
    const float x1 = base[j];
    const float x2 = base[j + 64];
    base[j]      = x1 * c - x2 * sn;   // x1*cos + (-x2)*sin
    base[j + 64] = x2 * c + x1 * sn;   // x2*cos + ( x1)*sin
}

// ---------------------------------------------------------------------------
// Causal GQA flash attention, fp32 online softmax.
// One block of 128 threads per (query position s, head h).
// Q/O layout (S, NH, HD); K/V layout (S, NKV, HD). kv head = h/8.
// ---------------------------------------------------------------------------
__global__ __launch_bounds__(128) void attn_kernel(const float* __restrict__ Q,
                                                   const float* __restrict__ K,
                                                   const float* __restrict__ V,
                                                   float* __restrict__ O) {
    const int s = blockIdx.x;
    const int h = blockIdx.y;
    const int kvh = h >> 3;
    const int tid = threadIdx.x;       // 0..127 == output dim
    const int lane = tid & 31;
    const int warp = tid >> 5;

    __shared__ float qs[128];
    __shared__ float sc[32];
    __shared__ float ps[32];

    qs[tid] = Q[((size_t)s * NH + h) * HD + tid];
    __syncthreads();

    float m = -1e30f, l = 0.0f, acc = 0.0f;
    const float scale = 0.08838834764831845f;   // 1/sqrt(128)
    const float* Vb = V + (size_t)kvh * HD + tid;

    for (int t0 = 0; t0 <= s; t0 += 32) {
        const int nk = min(32, s - t0 + 1);

        // Scores: warp w computes dots for keys w*8 .. w*8+7.
#pragma unroll
        for (int kk = 0; kk < 8; kk++) {
            const int ti = warp * 8 + kk;
            if (ti < nk) {
                const float* kr = K + ((size_t)(t0 + ti) * NKV + kvh) * HD;
                float p = qs[lane]      * kr[lane]
                        + qs[lane + 32] * kr[lane + 32]
                        + qs[lane + 64] * kr[lane + 64]
                        + qs[lane + 96] * kr[lane + 96];
#pragma unroll
                for (int off = 16; off; off >>= 1)
                    p += __shfl_xor_sync(0xffffffffu, p, off);
                if (lane == 0) sc[ti] = p * scale;
            }
        }
        __syncthreads();

        // Online softmax update (every thread tracks identical m, l).
        float mt = m;
        for (int t = 0; t < nk; t++) mt = fmaxf(mt, sc[t]);
        if (tid < nk) ps[tid] = __expf(sc[tid] - mt);
        __syncthreads();

        const float alpha = __expf(m - mt);
        m = mt;
        acc *= alpha;
        l *= alpha;

        const float* vp = Vb + (size_t)t0 * (NKV * HD);
#pragma unroll 8
        for (int t = 0; t < nk; t++) {
            const float p = ps[t];
            acc = fmaf(p, vp[(size_t)t * (NKV * HD)], acc);
            l += p;
        }
        __syncthreads();   // protect sc/ps before next tile overwrites
    }

    O[((size_t)s * NH + h) * HD + tid] = acc / l;
}

// ---------------------------------------------------------------------------
// Launch
// ---------------------------------------------------------------------------
extern "C" void kernel_launch(void* const* d_in, const int* in_sizes, int n_in,
                              void* d_out, int out_size) {
    const float* x  = (const float*)d_in[0];
    const float* wq = (const float*)d_in[1];
    const float* wk = (const float*)d_in[2];
    const float* wv = (const float*)d_in[3];
    const float* wo = (const float*)d_in[4];
    float* out = (float*)d_out;

    const int S = in_sizes[0] / DMODEL;   // 2048

    float *q, *k, *v, *o;
    cudaGetSymbolAddress((void**)&q, g_q);
    cudaGetSymbolAddress((void**)&k, g_k);
    cudaGetSymbolAddress((void**)&v, g_v);
    cudaGetSymbolAddress((void**)&o, g_o);

    // Projections
    sgemm_kernel<<<dim3((NH * HD) / 128, S / 128), 256>>>(x, wq, q, S, NH * HD, DMODEL);
    sgemm_kernel<<<dim3((NKV * HD) / 128, S / 128), 256>>>(x, wk, k, S, NKV * HD, DMODEL);
    sgemm_kernel<<<dim3((NKV * HD) / 128, S / 128), 256>>>(x, wv, v, S, NKV * HD, DMODEL);

    // RoPE (YaRN)
    rope_kernel<<<dim3(S, NH), 64>>>(q, NH);
    rope_kernel<<<dim3(S, NKV), 64>>>(k, NKV);

    // Causal GQA attention
    attn_kernel<<<dim3(S, NH), 128>>>(q, k, v, o);

    // Output projection
    sgemm_kernel<<<dim3(DMODEL / 128, S / 128), 256>>>(o, wo, out, S, DMODEL, DMODEL);
}

// round 3
// speedup vs baseline: 1.3170x; 1.3170x over previous
#include <cuda_runtime.h>
#include <cuda_bf16.h>
#include <mma.h>
#include <math.h>

using namespace nvcuda;

#define DMODEL 4096
#define NH 32
#define NKV 4
#define HD 128
#define S_MAX 2048

// fp32 activations
__device__ float g_q[S_MAX * NH * HD];
__device__ float g_k[S_MAX * NKV * HD];
__device__ float g_v[S_MAX * NKV * HD];
__device__ float g_o[S_MAX * NH * HD];

// split-bf16 operands (hi + lo representation of fp32)
__device__ __nv_bfloat16 g_xh[S_MAX * DMODEL],  g_xl[S_MAX * DMODEL];
__device__ __nv_bfloat16 g_wqh[DMODEL * NH * HD],  g_wql[DMODEL * NH * HD];
__device__ __nv_bfloat16 g_wkh[DMODEL * NKV * HD], g_wkl[DMODEL * NKV * HD];
__device__ __nv_bfloat16 g_wvh[DMODEL * NKV * HD], g_wvl[DMODEL * NKV * HD];
__device__ __nv_bfloat16 g_woh[NH * HD * DMODEL],  g_wol[NH * HD * DMODEL];
__device__ __nv_bfloat16 g_oh[S_MAX * NH * HD],    g_ol[S_MAX * NH * HD];

// ---------------------------------------------------------------------------
// fp32 -> (hi, lo) bf16 split.  x = hi + lo with ~2^-18 relative error.
// 4 elements per thread (counts are multiples of 1024).
// ---------------------------------------------------------------------------
__global__ __launch_bounds__(256) void split_kernel(const float4* __restrict__ x,
                                                    uint2* __restrict__ hi,
                                                    uint2* __restrict__ lo,
                                                    int n4) {
    int i = blockIdx.x * 256 + threadIdx.x;
    if (i >= n4) return;
    float4 v = x[i];
    union { __nv_bfloat16 b[4]; uint2 u; } H, L;
    H.b[0] = __float2bfloat16(v.x);
    H.b[1] = __float2bfloat16(v.y);
    H.b[2] = __float2bfloat16(v.z);
    H.b[3] = __float2bfloat16(v.w);
    L.b[0] = __float2bfloat16(v.x - __bfloat162float(H.b[0]));
    L.b[1] = __float2bfloat16(v.y - __bfloat162float(H.b[1]));
    L.b[2] = __float2bfloat16(v.z - __bfloat162float(H.b[2]));
    L.b[3] = __float2bfloat16(v.w - __bfloat162float(H.b[3]));
    hi[i] = H.u;
    lo[i] = L.u;
}

// ---------------------------------------------------------------------------
// Split-bf16 tensor-core GEMM: C = Ahi*Bhi + Ahi*Blo + Alo*Bhi  (fp32 accum).
// 128x128 block tile, BK=32, 256 threads, warp tile 32x64 (wmma 16x16x16).
// M,N multiples of 128; K multiple of 32.
// ---------------------------------------------------------------------------
#define BM 128
#define BN 128
#define BK 32

__global__ __launch_bounds__(256, 2) void gemm_bf16split(
    const __nv_bfloat16* __restrict__ Ah, const __nv_bfloat16* __restrict__ Al,
    const __nv_bfloat16* __restrict__ Bh, const __nv_bfloat16* __restrict__ Bl,
    float* __restrict__ C, int M, int N, int K) {
    __shared__ __nv_bfloat16 sAh[BM][BK + 8];
    __shared__ __nv_bfloat16 sAl[BM][BK + 8];
    __shared__ __nv_bfloat16 sBh[BK][BN + 8];
    __shared__ __nv_bfloat16 sBl[BK][BN + 8];

    const int tid = threadIdx.x;
    const int warp = tid >> 5;
    const int wm = warp >> 1;   // 0..3 -> M
    const int wn = warp & 1;    // 0..1 -> N

    const size_t arow0 = (size_t)blockIdx.y * BM;
    const size_t bcol0 = (size_t)blockIdx.x * BN;

    wmma::fragment<wmma::accumulator, 16, 16, 16, float> acc[2][4];
#pragma unroll
    for (int i = 0; i < 2; i++)
#pragma unroll
        for (int j = 0; j < 4; j++) wmma::fill_fragment(acc[i][j], 0.0f);

    for (int k0 = 0; k0 < K; k0 += BK) {
#pragma unroll
        for (int it = 0; it < 2; it++) {
            int v = tid + it * 256;
            int ar = v >> 2, ac = (v & 3) * 8;
            *(uint4*)&sAh[ar][ac] = *(const uint4*)(Ah + (arow0 + ar) * K + k0 + ac);
            *(uint4*)&sAl[ar][ac] = *(const uint4*)(Al + (arow0 + ar) * K + k0 + ac);
            int br = v >> 4, bc = (v & 15) * 8;
            *(uint4*)&sBh[br][bc] = *(const uint4*)(Bh + (size_t)(k0 + br) * N + bcol0 + bc);
            *(uint4*)&sBl[br][bc] = *(const uint4*)(Bl + (size_t)(k0 + br) * N + bcol0 + bc);
        }
        __syncthreads();

#pragma unroll
        for (int kt = 0; kt < 2; kt++) {
            wmma::fragment<wmma::matrix_a, 16, 16, 16, __nv_bfloat16, wmma::row_major> ah[2], al[2];
            wmma::fragment<wmma::matrix_b, 16, 16, 16, __nv_bfloat16, wmma::row_major> bh[4], bl[4];
#pragma unroll
            for (int i = 0; i < 2; i++) {
                wmma::load_matrix_sync(ah[i], &sAh[wm * 32 + i * 16][kt * 16], BK + 8);
                wmma::load_matrix_sync(al[i], &sAl[wm * 32 + i * 16][kt * 16], BK + 8);
            }
#pragma unroll
            for (int j = 0; j < 4; j++) {
                wmma::load_matrix_sync(bh[j], &sBh[kt * 16][wn * 64 + j * 16], BN + 8);
                wmma::load_matrix_sync(bl[j], &sBl[kt * 16][wn * 64 + j * 16], BN + 8);
            }
#pragma unroll
            for (int i = 0; i < 2; i++)
#pragma unroll
                for (int j = 0; j < 4; j++) {
                    wmma::mma_sync(acc[i][j], ah[i], bh[j], acc[i][j]);
                    wmma::mma_sync(acc[i][j], ah[i], bl[j], acc[i][j]);
                    wmma::mma_sync(acc[i][j], al[i], bh[j], acc[i][j]);
                }
        }
        __syncthreads();
    }

#pragma unroll
    for (int i = 0; i < 2; i++)
#pragma unroll
        for (int j = 0; j < 4; j++)
            wmma::store_matrix_sync(
                &C[(arow0 + wm * 32 + i * 16) * N + bcol0 + wn * 64 + j * 16],
                acc[i][j], N, wmma::mem_row_major);
}

// ---------------------------------------------------------------------------
// YaRN RoPE, in place on x laid out (S, nheads, 128).
// ---------------------------------------------------------------------------
__global__ __launch_bounds__(64) void rope_kernel(float* __restrict__ x, int nheads) {
    const int s = blockIdx.x;
    const int h = blockIdx.y;
    const int j = threadIdx.x;   // 0..63 frequency index

    const float expo = (float)(2 * j) / 128.0f;
    float invf = 1.0f / powf(10000.0f, expo);
    const float wl = 6.283185307179586f / invf;
    const float r = 163840.0f / wl;
    float gamma = (r - 1.0f) / 31.0f;
    gamma = fminf(fmaxf(gamma, 0.0f), 1.0f);
    invf = invf * ((1.0f - gamma) / 80.0f + gamma);
    const float ang = ((float)s * invf) / 1.19925088f;
    const float c = cosf(ang);
    const float sn = sinf(ang);

    float* base = x + ((size_t)s * nheads + h) * HD;
    const float x1 = base[j];
    const float x2 = base[j + 64];
    base[j]      = x1 * c - x2 * sn;
    base[j + 64] = x2 * c + x1 * sn;
}

// ---------------------------------------------------------------------------
// Causal GQA flash attention, fp32 online softmax.
// One block of 128 threads per (query position s, head h).
// ---------------------------------------------------------------------------
__global__ __launch_bounds__(128) void attn_kernel(const float* __restrict__ Q,
                                                   const float* __restrict__ K,
                                                   const float* __restrict__ V,
                                                   float* __restrict__ O) {
    const int s = blockIdx.x;
    const int h = blockIdx.y;
    const int kvh = h >> 3;
    const int tid = threadIdx.x;
    const int lane = tid & 31;
    const int warp = tid >> 5;

    __shared__ float qs[128];
    __shared__ float sc[32];
    __shared__ float ps[32];

    qs[tid] = Q[((size_t)s * NH + h) * HD + tid];
    __syncthreads();

    float m = -1e30f, l = 0.0f, acc = 0.0f;
    const float scale = 0.08838834764831845f;
    const float* Vb = V + (size_t)kvh * HD + tid;

    for (int t0 = 0; t0 <= s; t0 += 32) {
        const int nk = min(32, s - t0 + 1);

#pragma unroll
        for (int kk = 0; kk < 8; kk++) {
            const int ti = warp * 8 + kk;
            if (ti < nk) {
                const float* kr = K + ((size_t)(t0 + ti) * NKV + kvh) * HD;
                float p = qs[lane]      * kr[lane]
                        + qs[lane + 32] * kr[lane + 32]
                        + qs[lane + 64] * kr[lane + 64]
                        + qs[lane + 96] * kr[lane + 96];
#pragma unroll
                for (int off = 16; off; off >>= 1)
                    p += __shfl_xor_sync(0xffffffffu, p, off);
                if (lane == 0) sc[ti] = p * scale;
            }
        }
        __syncthreads();

        float mt = m;
        for (int t = 0; t < nk; t++) mt = fmaxf(mt, sc[t]);
        if (tid < nk) ps[tid] = __expf(sc[tid] - mt);
        __syncthreads();

        const float alpha = __expf(m - mt);
        m = mt;
        acc *= alpha;
        l *= alpha;

        const float* vp = Vb + (size_t)t0 * (NKV * HD);
#pragma unroll 8
        for (int t = 0; t < nk; t++) {
            const float p = ps[t];
            acc = fmaf(p, vp[(size_t)t * (NKV * HD)], acc);
            l += p;
        }
        __syncthreads();
    }

    O[((size_t)s * NH + h) * HD + tid] = acc / l;
}

// ---------------------------------------------------------------------------
// Launch
// ---------------------------------------------------------------------------
extern "C" void kernel_launch(void* const* d_in, const int* in_sizes, int n_in,
                              void* d_out, int out_size) {
    const float* x  = (const float*)d_in[0];
    const float* wq = (const float*)d_in[1];
    const float* wk = (const float*)d_in[2];
    const float* wv = (const float*)d_in[3];
    const float* wo = (const float*)d_in[4];
    float* out = (float*)d_out;

    const int S = in_sizes[0] / DMODEL;   // 2048

    float *q, *k, *v, *o;
    cudaGetSymbolAddress((void**)&q, g_q);
    cudaGetSymbolAddress((void**)&k, g_k);
    cudaGetSymbolAddress((void**)&v, g_v);
    cudaGetSymbolAddress((void**)&o, g_o);

    __nv_bfloat16 *xh, *xl, *wqh, *wql, *wkh, *wkl, *wvh, *wvl, *woh, *wol, *oh, *ol;
    cudaGetSymbolAddress((void**)&xh, g_xh);   cudaGetSymbolAddress((void**)&xl, g_xl);
    cudaGetSymbolAddress((void**)&wqh, g_wqh); cudaGetSymbolAddress((void**)&wql, g_wql);
    cudaGetSymbolAddress((void**)&wkh, g_wkh); cudaGetSymbolAddress((void**)&wkl, g_wkl);
    cudaGetSymbolAddress((void**)&wvh, g_wvh); cudaGetSymbolAddress((void**)&wvl, g_wvl);
    cudaGetSymbolAddress((void**)&woh, g_woh); cudaGetSymbolAddress((void**)&wol, g_wol);
    cudaGetSymbolAddress((void**)&oh, g_oh);   cudaGetSymbolAddress((void**)&ol, g_ol);

    auto split = [](const float* p, __nv_bfloat16* h, __nv_bfloat16* l, int count) {
        int n4 = count / 4;
        split_kernel<<<(n4 + 255) / 256, 256>>>((const float4*)p, (uint2*)h, (uint2*)l, n4);
    };

    // Split all GEMM operands to (hi, lo) bf16.
    split(x,  xh,  xl,  S * DMODEL);
    split(wq, wqh, wql, DMODEL * NH * HD);
    split(wk, wkh, wkl, DMODEL * NKV * HD);
    split(wv, wvh, wvl, DMODEL * NKV * HD);
    split(wo, woh, wol, NH * HD * DMODEL);

    // Projections (tensor cores, split-bf16 = fp32-accurate)
    gemm_bf16split<<<dim3((NH * HD) / BN, S / BM), 256>>>(xh, xl, wqh, wql, q, S, NH * HD, DMODEL);
    gemm_bf16split<<<dim3((NKV * HD) / BN, S / BM), 256>>>(xh, xl, wkh, wkl, k, S, NKV * HD, DMODEL);
    gemm_bf16split<<<dim3((NKV * HD) / BN, S / BM), 256>>>(xh, xl, wvh, wvl, v, S, NKV * HD, DMODEL);

    // RoPE (YaRN)
    rope_kernel<<<dim3(S, NH), 64>>>(q, NH);
    rope_kernel<<<dim3(S, NKV), 64>>>(k, NKV);

    // Causal GQA attention
    attn_kernel<<<dim3(S, NH), 128>>>(q, k, v, o);

    // Output projection
    split(o, oh, ol, S * NH * HD);
    gemm_bf16split<<<dim3(DMODEL / BN, S / BM), 256>>>(oh, ol, woh, wol, out, S, DMODEL, DMODEL);
}

// round 4
// speedup vs baseline: 3.4756x; 2.6390x over previous
#include <cuda_runtime.h>
#include <cuda_bf16.h>
#include <mma.h>
#include <math.h>
#include <stdint.h>

using namespace nvcuda;

#define DMODEL 4096
#define NH 32
#define NKV 4
#define HD 128
#define S_MAX 2048

// fp32 activations
__device__ float g_q[S_MAX * NH * HD];
__device__ float g_k[S_MAX * NKV * HD];
__device__ float g_v[S_MAX * NKV * HD];
__device__ float g_o[S_MAX * NH * HD];

// split-bf16 operands (hi + lo representation of fp32)
__device__ __nv_bfloat16 g_xh[S_MAX * DMODEL],  g_xl[S_MAX * DMODEL];
__device__ __nv_bfloat16 g_wqh[DMODEL * NH * HD],  g_wql[DMODEL * NH * HD];
__device__ __nv_bfloat16 g_wkh[DMODEL * NKV * HD], g_wkl[DMODEL * NKV * HD];
__device__ __nv_bfloat16 g_wvh[DMODEL * NKV * HD], g_wvl[DMODEL * NKV * HD];
__device__ __nv_bfloat16 g_woh[NH * HD * DMODEL],  g_wol[NH * HD * DMODEL];
__device__ __nv_bfloat16 g_oh[S_MAX * NH * HD],    g_ol[S_MAX * NH * HD];

// ---------------------------------------------------------------------------
// fp32 -> (hi, lo) bf16 split.
// ---------------------------------------------------------------------------
__global__ __launch_bounds__(256) void split_kernel(const float4* __restrict__ x,
                                                    uint2* __restrict__ hi,
                                                    uint2* __restrict__ lo,
                                                    int n4) {
    int i = blockIdx.x * 256 + threadIdx.x;
    if (i >= n4) return;
    float4 v = x[i];
    union { __nv_bfloat16 b[4]; uint2 u; } H, L;
    H.b[0] = __float2bfloat16(v.x);
    H.b[1] = __float2bfloat16(v.y);
    H.b[2] = __float2bfloat16(v.z);
    H.b[3] = __float2bfloat16(v.w);
    L.b[0] = __float2bfloat16(v.x - __bfloat162float(H.b[0]));
    L.b[1] = __float2bfloat16(v.y - __bfloat162float(H.b[1]));
    L.b[2] = __float2bfloat16(v.z - __bfloat162float(H.b[2]));
    L.b[3] = __float2bfloat16(v.w - __bfloat162float(H.b[3]));
    hi[i] = H.u;
    lo[i] = L.u;
}

// ---------------------------------------------------------------------------
// Split-bf16 tensor-core GEMM (unchanged from R2).
// ---------------------------------------------------------------------------
#define BM 128
#define BN 128
#define BK 32

__global__ __launch_bounds__(256, 2) void gemm_bf16split(
    const __nv_bfloat16* __restrict__ Ah, const __nv_bfloat16* __restrict__ Al,
    const __nv_bfloat16* __restrict__ Bh, const __nv_bfloat16* __restrict__ Bl,
    float* __restrict__ C, int M, int N, int K) {
    __shared__ __nv_bfloat16 sAh[BM][BK + 8];
    __shared__ __nv_bfloat16 sAl[BM][BK + 8];
    __shared__ __nv_bfloat16 sBh[BK][BN + 8];
    __shared__ __nv_bfloat16 sBl[BK][BN + 8];

    const int tid = threadIdx.x;
    const int warp = tid >> 5;
    const int wm = warp >> 1;
    const int wn = warp & 1;

    const size_t arow0 = (size_t)blockIdx.y * BM;
    const size_t bcol0 = (size_t)blockIdx.x * BN;

    wmma::fragment<wmma::accumulator, 16, 16, 16, float> acc[2][4];
#pragma unroll
    for (int i = 0; i < 2; i++)
#pragma unroll
        for (int j = 0; j < 4; j++) wmma::fill_fragment(acc[i][j], 0.0f);

    for (int k0 = 0; k0 < K; k0 += BK) {
#pragma unroll
        for (int it = 0; it < 2; it++) {
            int v = tid + it * 256;
            int ar = v >> 2, ac = (v & 3) * 8;
            *(uint4*)&sAh[ar][ac] = *(const uint4*)(Ah + (arow0 + ar) * K + k0 + ac);
            *(uint4*)&sAl[ar][ac] = *(const uint4*)(Al + (arow0 + ar) * K + k0 + ac);
            int br = v >> 4, bc = (v & 15) * 8;
            *(uint4*)&sBh[br][bc] = *(const uint4*)(Bh + (size_t)(k0 + br) * N + bcol0 + bc);
            *(uint4*)&sBl[br][bc] = *(const uint4*)(Bl + (size_t)(k0 + br) * N + bcol0 + bc);
        }
        __syncthreads();

#pragma unroll
        for (int kt = 0; kt < 2; kt++) {
            wmma::fragment<wmma::matrix_a, 16, 16, 16, __nv_bfloat16, wmma::row_major> ah[2], al[2];
            wmma::fragment<wmma::matrix_b, 16, 16, 16, __nv_bfloat16, wmma::row_major> bh[4], bl[4];
#pragma unroll
            for (int i = 0; i < 2; i++) {
                wmma::load_matrix_sync(ah[i], &sAh[wm * 32 + i * 16][kt * 16], BK + 8);
                wmma::load_matrix_sync(al[i], &sAl[wm * 32 + i * 16][kt * 16], BK + 8);
            }
#pragma unroll
            for (int j = 0; j < 4; j++) {
                wmma::load_matrix_sync(bh[j], &sBh[kt * 16][wn * 64 + j * 16], BN + 8);
                wmma::load_matrix_sync(bl[j], &sBl[kt * 16][wn * 64 + j * 16], BN + 8);
            }
#pragma unroll
            for (int i = 0; i < 2; i++)
#pragma unroll
                for (int j = 0; j < 4; j++) {
                    wmma::mma_sync(acc[i][j], ah[i], bh[j], acc[i][j]);
                    wmma::mma_sync(acc[i][j], ah[i], bl[j], acc[i][j]);
                    wmma::mma_sync(acc[i][j], al[i], bh[j], acc[i][j]);
                }
        }
        __syncthreads();
    }

#pragma unroll
    for (int i = 0; i < 2; i++)
#pragma unroll
        for (int j = 0; j < 4; j++)
            wmma::store_matrix_sync(
                &C[(arow0 + wm * 32 + i * 16) * N + bcol0 + wn * 64 + j * 16],
                acc[i][j], N, wmma::mem_row_major);
}

// ---------------------------------------------------------------------------
// YaRN RoPE (unchanged).
// ---------------------------------------------------------------------------
__global__ __launch_bounds__(64) void rope_kernel(float* __restrict__ x, int nheads) {
    const int s = blockIdx.x;
    const int h = blockIdx.y;
    const int j = threadIdx.x;

    const float expo = (float)(2 * j) / 128.0f;
    float invf = 1.0f / powf(10000.0f, expo);
    const float wl = 6.283185307179586f / invf;
    const float r = 163840.0f / wl;
    float gamma = (r - 1.0f) / 31.0f;
    gamma = fminf(fmaxf(gamma, 0.0f), 1.0f);
    invf = invf * ((1.0f - gamma) / 80.0f + gamma);
    const float ang = ((float)s * invf) / 1.19925088f;
    const float c = cosf(ang);
    const float sn = sinf(ang);

    float* base = x + ((size_t)s * nheads + h) * HD;
    const float x1 = base[j];
    const float x2 = base[j + 64];
    base[j]      = x1 * c - x2 * sn;
    base[j + 64] = x2 * c + x1 * sn;
}

// ---------------------------------------------------------------------------
// Tiled causal GQA flash attention on tensor cores (mma.m16n8k16, split bf16).
// Block: 256 threads = 8 warps; Q tile 128 rows (one head), K tiles of 64.
// Warp w owns query rows w*16..w*16+15. All softmax state in registers.
// ---------------------------------------------------------------------------
#define QTI 128
#define KTI 64
#define QP  136   // bf16 row stride for Q/K tiles (pad: conflict-free frags)
#define VP  72    // bf16 key stride for transposed V tile

__device__ __forceinline__ void mma16816(float* c, const uint32_t* a,
                                         uint32_t b0, uint32_t b1) {
    asm volatile(
        "mma.sync.aligned.m16n8k16.row.col.f32.bf16.bf16.f32 "
        "{%0,%1,%2,%3}, {%4,%5,%6,%7}, {%8,%9}, {%0,%1,%2,%3};\n"
        : "+f"(c[0]), "+f"(c[1]), "+f"(c[2]), "+f"(c[3])
        : "r"(a[0]), "r"(a[1]), "r"(a[2]), "r"(a[3]), "r"(b0), "r"(b1));
}

__device__ __forceinline__ void split2pack(float x, float y,
                                           uint32_t& hi, uint32_t& lo) {
    union { __nv_bfloat162 b2; uint32_t u; } H, L;
    __nv_bfloat16 hx = __float2bfloat16(x);
    __nv_bfloat16 hy = __float2bfloat16(y);
    H.b2.x = hx; H.b2.y = hy;
    L.b2.x = __float2bfloat16(x - __bfloat162float(hx));
    L.b2.y = __float2bfloat16(y - __bfloat162float(hy));
    hi = H.u; lo = L.u;
}

__device__ __forceinline__ void split_store4(__nv_bfloat16* ph, __nv_bfloat16* pl,
                                             float4 v) {
    union { __nv_bfloat16 b[4]; uint2 u; } H, L;
    H.b[0] = __float2bfloat16(v.x);
    H.b[1] = __float2bfloat16(v.y);
    H.b[2] = __float2bfloat16(v.z);
    H.b[3] = __float2bfloat16(v.w);
    L.b[0] = __float2bfloat16(v.x - __bfloat162float(H.b[0]));
    L.b[1] = __float2bfloat16(v.y - __bfloat162float(H.b[1]));
    L.b[2] = __float2bfloat16(v.z - __bfloat162float(H.b[2]));
    L.b[3] = __float2bfloat16(v.w - __bfloat162float(H.b[3]));
    *(uint2*)ph = H.u;
    *(uint2*)pl = L.u;
}

__global__ __launch_bounds__(256) void attn_mma(const float* __restrict__ Qg,
                                                const float* __restrict__ Kg,
                                                const float* __restrict__ Vg,
                                                float* __restrict__ Og) {
    extern __shared__ __nv_bfloat16 sm[];
    __nv_bfloat16* Qh  = sm;                      // [QTI][QP]
    __nv_bfloat16* Ql  = Qh  + QTI * QP;
    __nv_bfloat16* Kh  = Ql  + QTI * QP;          // [KTI][QP]
    __nv_bfloat16* Kl  = Kh  + KTI * QP;
    __nv_bfloat16* Vth = Kl  + KTI * QP;          // [HD][VP] (transposed)
    __nv_bfloat16* Vtl = Vth + HD  * VP;

    const int qt   = gridDim.x - 1 - blockIdx.x;   // big tiles first
    const int h    = blockIdx.y;
    const int kvh  = h >> 3;
    const int tid  = threadIdx.x;
    const int warp = tid >> 5;
    const int lane = tid & 31;
    const int lg   = lane >> 2;    // row in group (0..7)
    const int lc   = lane & 3;     // col group (0..3)
    const int q0   = qt * QTI;
    const int rloc = warp * 16 + lg;               // local query row (and +8)

    // ---- load + split Q tile (128 x 128 fp32) ----
    for (int i = tid; i < QTI * 32; i += 256) {
        int r = i >> 5, dc = (i & 31) << 2;
        float4 v = *(const float4*)(Qg + ((size_t)(q0 + r) * NH + h) * HD + dc);
        split_store4(Qh + r * QP + dc, Ql + r * QP + dc, v);
    }

    float oacc[16][4];
#pragma unroll
    for (int n = 0; n < 16; n++)
#pragma unroll
        for (int i = 0; i < 4; i++) oacc[n][i] = 0.0f;
    float m0 = -1e30f, m1 = -1e30f, l0 = 0.0f, l1 = 0.0f;
    const float scale = 0.08838834764831845f;

    const int nkt = 2 * qt + 2;
    for (int kt = 0; kt < nkt; kt++) {
        __syncthreads();   // prior tile's smem reads done (and Q stores on iter 0)
        const int k0 = kt * KTI;

        // ---- load + split K tile (row-major) and V tile (transposed) ----
        for (int i = tid; i < KTI * 32; i += 256) {
            int r = i >> 5, dc = (i & 31) << 2;
            const size_t goff = ((size_t)(k0 + r) * NKV + kvh) * HD + dc;
            float4 kv = *(const float4*)(Kg + goff);
            split_store4(Kh + r * QP + dc, Kl + r * QP + dc, kv);
            float4 vv = *(const float4*)(Vg + goff);
#pragma unroll
            for (int jj = 0; jj < 4; jj++) {
                float x = (&vv.x)[jj];
                __nv_bfloat16 hx = __float2bfloat16(x);
                Vth[(dc + jj) * VP + r] = hx;
                Vtl[(dc + jj) * VP + r] = __float2bfloat16(x - __bfloat162float(hx));
            }
        }
        __syncthreads();

        // ---- S = Q K^T (split bf16, fp32 accum) ----
        float sc[8][4];
#pragma unroll
        for (int j = 0; j < 8; j++)
#pragma unroll
            for (int i = 0; i < 4; i++) sc[j][i] = 0.0f;

#pragma unroll
        for (int dk = 0; dk < 8; dk++) {
            const int cb = dk * 16 + lc * 2;
            uint32_t ah[4], al[4];
            ah[0] = *(const uint32_t*)&Qh[(rloc)     * QP + cb];
            ah[1] = *(const uint32_t*)&Qh[(rloc + 8) * QP + cb];
            ah[2] = *(const uint32_t*)&Qh[(rloc)     * QP + cb + 8];
            ah[3] = *(const uint32_t*)&Qh[(rloc + 8) * QP + cb + 8];
            al[0] = *(const uint32_t*)&Ql[(rloc)     * QP + cb];
            al[1] = *(const uint32_t*)&Ql[(rloc + 8) * QP + cb];
            al[2] = *(const uint32_t*)&Ql[(rloc)     * QP + cb + 8];
            al[3] = *(const uint32_t*)&Ql[(rloc + 8) * QP + cb + 8];
#pragma unroll
            for (int j = 0; j < 8; j++) {
                const int krow = j * 8 + lg;
                uint32_t bh0 = *(const uint32_t*)&Kh[krow * QP + cb];
                uint32_t bh1 = *(const uint32_t*)&Kh[krow * QP + cb + 8];
                uint32_t bl0 = *(const uint32_t*)&Kl[krow * QP + cb];
                uint32_t bl1 = *(const uint32_t*)&Kl[krow * QP + cb + 8];
                mma16816(sc[j], ah, bh0, bh1);
                mma16816(sc[j], ah, bl0, bl1);
                mma16816(sc[j], al, bh0, bh1);
            }
        }

        // ---- scale + causal mask ----
        const bool dm = (kt >= 2 * qt);   // only top two diagonal tiles mask
#pragma unroll
        for (int j = 0; j < 8; j++) {
            const int keyb = k0 + j * 8 + lc * 2;
#pragma unroll
            for (int i = 0; i < 4; i++) {
                const int key = keyb + (i & 1);
                const int qr  = q0 + rloc + ((i >> 1) << 3);
                float s = sc[j][i] * scale;
                sc[j][i] = (dm && key > qr) ? -1e30f : s;
            }
        }

        // ---- online softmax (registers) ----
        float mx0 = -1e30f, mx1 = -1e30f;
#pragma unroll
        for (int j = 0; j < 8; j++) {
            mx0 = fmaxf(mx0, fmaxf(sc[j][0], sc[j][1]));
            mx1 = fmaxf(mx1, fmaxf(sc[j][2], sc[j][3]));
        }
        mx0 = fmaxf(mx0, __shfl_xor_sync(0xffffffffu, mx0, 1));
        mx0 = fmaxf(mx0, __shfl_xor_sync(0xffffffffu, mx0, 2));
        mx1 = fmaxf(mx1, __shfl_xor_sync(0xffffffffu, mx1, 1));
        mx1 = fmaxf(mx1, __shfl_xor_sync(0xffffffffu, mx1, 2));

        const float mn0 = fmaxf(m0, mx0), mn1 = fmaxf(m1, mx1);
        const float a0 = __expf(m0 - mn0), a1 = __expf(m1 - mn1);
        m0 = mn0; m1 = mn1;
        l0 *= a0; l1 *= a1;
#pragma unroll
        for (int n = 0; n < 16; n++) {
            oacc[n][0] *= a0; oacc[n][1] *= a0;
            oacc[n][2] *= a1; oacc[n][3] *= a1;
        }

        float rs0 = 0.0f, rs1 = 0.0f;
#pragma unroll
        for (int j = 0; j < 8; j++) {
            sc[j][0] = __expf(sc[j][0] - mn0); rs0 += sc[j][0];
            sc[j][1] = __expf(sc[j][1] - mn0); rs0 += sc[j][1];
            sc[j][2] = __expf(sc[j][2] - mn1); rs1 += sc[j][2];
            sc[j][3] = __expf(sc[j][3] - mn1); rs1 += sc[j][3];
        }
        rs0 += __shfl_xor_sync(0xffffffffu, rs0, 1);
        rs0 += __shfl_xor_sync(0xffffffffu, rs0, 2);
        rs1 += __shfl_xor_sync(0xffffffffu, rs1, 1);
        rs1 += __shfl_xor_sync(0xffffffffu, rs1, 2);
        l0 += rs0; l1 += rs1;

        // ---- P fragments (C layout of S == A layout for PV) ----
        uint32_t pah[4][4], pal[4][4];
#pragma unroll
        for (int k4 = 0; k4 < 4; k4++) {
            const int j0 = 2 * k4, j1 = 2 * k4 + 1;
            split2pack(sc[j0][0], sc[j0][1], pah[k4][0], pal[k4][0]);
            split2pack(sc[j0][2], sc[j0][3], pah[k4][1], pal[k4][1]);
            split2pack(sc[j1][0], sc[j1][1], pah[k4][2], pal[k4][2]);
            split2pack(sc[j1][2], sc[j1][3], pah[k4][3], pal[k4][3]);
        }

        // ---- O += P V ----
#pragma unroll
        for (int k4 = 0; k4 < 4; k4++) {
            const int kb = k4 * 16 + lc * 2;
#pragma unroll
            for (int n = 0; n < 16; n++) {
                const int drow = n * 8 + lg;
                uint32_t bh0 = *(const uint32_t*)&Vth[drow * VP + kb];
                uint32_t bh1 = *(const uint32_t*)&Vth[drow * VP + kb + 8];
                uint32_t bl0 = *(const uint32_t*)&Vtl[drow * VP + kb];
                uint32_t bl1 = *(const uint32_t*)&Vtl[drow * VP + kb + 8];
                mma16816(oacc[n], pah[k4], bh0, bh1);
                mma16816(oacc[n], pah[k4], bl0, bl1);
                mma16816(oacc[n], pal[k4], bh0, bh1);
            }
        }
    }

    // ---- epilogue: normalize and store ----
    const float i0 = 1.0f / l0, i1 = 1.0f / l1;
#pragma unroll
    for (int n = 0; n < 16; n++) {
        const int d = n * 8 + lc * 2;
        float2 r0 = make_float2(oacc[n][0] * i0, oacc[n][1] * i0);
        float2 r1 = make_float2(oacc[n][2] * i1, oacc[n][3] * i1);
        *(float2*)(Og + ((size_t)(q0 + rloc)     * NH + h) * HD + d) = r0;
        *(float2*)(Og + ((size_t)(q0 + rloc + 8) * NH + h) * HD + d) = r1;
    }
}

// ---------------------------------------------------------------------------
// Launch
// ---------------------------------------------------------------------------
extern "C" void kernel_launch(void* const* d_in, const int* in_sizes, int n_in,
                              void* d_out, int out_size) {
    const float* x  = (const float*)d_in[0];
    const float* wq = (const float*)d_in[1];
    const float* wk = (const float*)d_in[2];
    const float* wv = (const float*)d_in[3];
    const float* wo = (const float*)d_in[4];
    float* out = (float*)d_out;

    const int S = in_sizes[0] / DMODEL;   // 2048

    float *q, *k, *v, *o;
    cudaGetSymbolAddress((void**)&q, g_q);
    cudaGetSymbolAddress((void**)&k, g_k);
    cudaGetSymbolAddress((void**)&v, g_v);
    cudaGetSymbolAddress((void**)&o, g_o);

    __nv_bfloat16 *xh, *xl, *wqh, *wql, *wkh, *wkl, *wvh, *wvl, *woh, *wol, *oh, *ol;
    cudaGetSymbolAddress((void**)&xh, g_xh);   cudaGetSymbolAddress((void**)&xl, g_xl);
    cudaGetSymbolAddress((void**)&wqh, g_wqh); cudaGetSymbolAddress((void**)&wql, g_wql);
    cudaGetSymbolAddress((void**)&wkh, g_wkh); cudaGetSymbolAddress((void**)&wkl, g_wkl);
    cudaGetSymbolAddress((void**)&wvh, g_wvh); cudaGetSymbolAddress((void**)&wvl, g_wvl);
    cudaGetSymbolAddress((void**)&woh, g_woh); cudaGetSymbolAddress((void**)&wol, g_wol);
    cudaGetSymbolAddress((void**)&oh, g_oh);   cudaGetSymbolAddress((void**)&ol, g_ol);

    auto split = [](const float* p, __nv_bfloat16* h, __nv_bfloat16* l, int count) {
        int n4 = count / 4;
        split_kernel<<<(n4 + 255) / 256, 256>>>((const float4*)p, (uint2*)h, (uint2*)l, n4);
    };

    split(x,  xh,  xl,  S * DMODEL);
    split(wq, wqh, wql, DMODEL * NH * HD);
    split(wk, wkh, wkl, DMODEL * NKV * HD);
    split(wv, wvh, wvl, DMODEL * NKV * HD);
    split(wo, woh, wol, NH * HD * DMODEL);

    gemm_bf16split<<<dim3((NH * HD) / BN, S / BM), 256>>>(xh, xl, wqh, wql, q, S, NH * HD, DMODEL);
    gemm_bf16split<<<dim3((NKV * HD) / BN, S / BM), 256>>>(xh, xl, wkh, wkl, k, S, NKV * HD, DMODEL);
    gemm_bf16split<<<dim3((NKV * HD) / BN, S / BM), 256>>>(xh, xl, wvh, wvl, v, S, NKV * HD, DMODEL);

    rope_kernel<<<dim3(S, NH), 64>>>(q, NH);
    rope_kernel<<<dim3(S, NKV), 64>>>(k, NKV);

    // Tensor-core flash attention (dynamic smem: 138 KB)
    const int smem_bytes = (2 * QTI * QP + 2 * KTI * QP + 2 * HD * VP) * (int)sizeof(__nv_bfloat16);
    cudaFuncSetAttribute(attn_mma, cudaFuncAttributeMaxDynamicSharedMemorySize, smem_bytes);
    attn_mma<<<dim3(S / QTI, NH), 256, smem_bytes>>>(q, k, v, o);

    split(o, oh, ol, S * NH * HD);
    gemm_bf16split<<<dim3(DMODEL / BN, S / BM), 256>>>(oh, ol, woh, wol, out, S, DMODEL, DMODEL);
}

// round 6
// speedup vs baseline: 4.1597x; 1.1968x over previous
#include <cuda_runtime.h>
#include <cuda_bf16.h>
#include <mma.h>
#include <math.h>
#include <stdint.h>

using namespace nvcuda;

#define DMODEL 4096
#define NH 32
#define NKV 4
#define HD 128
#define S_MAX 2048

// fp32 activations
__device__ float g_q[S_MAX * NH * HD];
__device__ float g_k[S_MAX * NKV * HD];
__device__ float g_v[S_MAX * NKV * HD];

// split-bf16 operands (hi + lo representation of fp32)
__device__ __nv_bfloat16 g_xh[S_MAX * DMODEL],  g_xl[S_MAX * DMODEL];
__device__ __nv_bfloat16 g_wqh[DMODEL * NH * HD],  g_wql[DMODEL * NH * HD];
__device__ __nv_bfloat16 g_wkh[DMODEL * NKV * HD], g_wkl[DMODEL * NKV * HD];
__device__ __nv_bfloat16 g_wvh[DMODEL * NKV * HD], g_wvl[DMODEL * NKV * HD];
__device__ __nv_bfloat16 g_woh[NH * HD * DMODEL],  g_wol[NH * HD * DMODEL];
__device__ __nv_bfloat16 g_oh[S_MAX * NH * HD],    g_ol[S_MAX * NH * HD];

// ---------------------------------------------------------------------------
// fp32 -> (hi, lo) bf16 split.
// ---------------------------------------------------------------------------
__global__ __launch_bounds__(256) void split_kernel(const float4* __restrict__ x,
                                                    uint2* __restrict__ hi,
                                                    uint2* __restrict__ lo,
                                                    int n4) {
    int i = blockIdx.x * 256 + threadIdx.x;
    if (i >= n4) return;
    float4 v = x[i];
    union { __nv_bfloat16 b[4]; uint2 u; } H, L;
    H.b[0] = __float2bfloat16(v.x);
    H.b[1] = __float2bfloat16(v.y);
    H.b[2] = __float2bfloat16(v.z);
    H.b[3] = __float2bfloat16(v.w);
    L.b[0] = __float2bfloat16(v.x - __bfloat162float(H.b[0]));
    L.b[1] = __float2bfloat16(v.y - __bfloat162float(H.b[1]));
    L.b[2] = __float2bfloat16(v.z - __bfloat162float(H.b[2]));
    L.b[3] = __float2bfloat16(v.w - __bfloat162float(H.b[3]));
    hi[i] = H.u;
    lo[i] = L.u;
}

// ---------------------------------------------------------------------------
// Double-buffered split-bf16 tensor-core GEMM (cp.async pipeline).
// C = Ahi*Bhi + Ahi*Blo + Alo*Bhi, fp32 accum.
// 128x128 block tile, BK=32, 256 threads, warp tile 32x64.
// ---------------------------------------------------------------------------
#define BM 128
#define BN 128
#define BK 32
#define PAD 8
#define AP (BK + PAD)              // 40
#define BP (BN + PAD)              // 136
#define ASZ (BM * AP)              // 5120 elems
#define BSZ (BK * BP)              // 4352 elems
#define STG (2 * ASZ + 2 * BSZ)    // elems per stage
#define GEMM_SMEM (2 * STG * 2)    // bytes (75776)

__device__ __forceinline__ void cpa16(uint32_t d, const void* s) {
    asm volatile("cp.async.cg.shared.global [%0], [%1], 16;\n" :: "r"(d), "l"(s));
}
__device__ __forceinline__ void cp_commit() {
    asm volatile("cp.async.commit_group;\n");
}
template <int N> __device__ __forceinline__ void cp_wait() {
    asm volatile("cp.async.wait_group %0;\n" :: "n"(N));
}

__device__ __forceinline__ void gemm_core(
    const __nv_bfloat16* __restrict__ Ah, const __nv_bfloat16* __restrict__ Al,
    const __nv_bfloat16* __restrict__ Bh, const __nv_bfloat16* __restrict__ Bl,
    float* __restrict__ C, int M, int N, int K, int bx, int by,
    __nv_bfloat16* sm) {
    const int tid  = threadIdx.x;
    const int warp = tid >> 5;
    const int wm   = warp >> 1;
    const int wn   = warp & 1;
    const size_t arow0 = (size_t)by * BM;
    const size_t bcol0 = (size_t)bx * BN;
    const uint32_t sb = (uint32_t)__cvta_generic_to_shared(sm);

    auto load_stage = [&](int st, int k0) {
        const uint32_t base = sb + (uint32_t)(st * STG * 2);
#pragma unroll
        for (int it = 0; it < 2; it++) {
            const int c = tid + it * 256;
            const int r = c >> 2, col = (c & 3) << 3;
            const uint32_t da = base + (uint32_t)((r * AP + col) << 1);
            cpa16(da,           Ah + (arow0 + r) * K + k0 + col);
            cpa16(da + ASZ * 2, Al + (arow0 + r) * K + k0 + col);
            const int br = c >> 4, bc = (c & 15) << 3;
            const uint32_t db = base + (uint32_t)((2 * ASZ + br * BP + bc) << 1);
            cpa16(db,           Bh + (size_t)(k0 + br) * N + bcol0 + bc);
            cpa16(db + BSZ * 2, Bl + (size_t)(k0 + br) * N + bcol0 + bc);
        }
    };

    wmma::fragment<wmma::accumulator, 16, 16, 16, float> acc[2][4];
#pragma unroll
    for (int i = 0; i < 2; i++)
#pragma unroll
        for (int j = 0; j < 4; j++) wmma::fill_fragment(acc[i][j], 0.0f);

    const int nst = K / BK;
    load_stage(0, 0);
    cp_commit();

    for (int t = 0; t < nst; t++) {
        if (t + 1 < nst) {
            load_stage((t + 1) & 1, (t + 1) * BK);
            cp_commit();
            cp_wait<1>();
        } else {
            cp_wait<0>();
        }
        __syncthreads();

        __nv_bfloat16* p   = sm + (t & 1) * STG;
        __nv_bfloat16* pAh = p;
        __nv_bfloat16* pAl = p + ASZ;
        __nv_bfloat16* pBh = p + 2 * ASZ;
        __nv_bfloat16* pBl = p + 2 * ASZ + BSZ;

#pragma unroll
        for (int kt = 0; kt < 2; kt++) {
            wmma::fragment<wmma::matrix_a, 16, 16, 16, __nv_bfloat16, wmma::row_major> ah[2], al[2];
            wmma::fragment<wmma::matrix_b, 16, 16, 16, __nv_bfloat16, wmma::row_major> bh[4], bl[4];
#pragma unroll
            for (int i = 0; i < 2; i++) {
                wmma::load_matrix_sync(ah[i], pAh + (wm * 32 + i * 16) * AP + kt * 16, AP);
                wmma::load_matrix_sync(al[i], pAl + (wm * 32 + i * 16) * AP + kt * 16, AP);
            }
#pragma unroll
            for (int j = 0; j < 4; j++) {
                wmma::load_matrix_sync(bh[j], pBh + kt * 16 * BP + wn * 64 + j * 16, BP);
                wmma::load_matrix_sync(bl[j], pBl + kt * 16 * BP + wn * 64 + j * 16, BP);
            }
#pragma unroll
            for (int i = 0; i < 2; i++)
#pragma unroll
                for (int j = 0; j < 4; j++) {
                    wmma::mma_sync(acc[i][j], ah[i], bh[j], acc[i][j]);
                    wmma::mma_sync(acc[i][j], ah[i], bl[j], acc[i][j]);
                    wmma::mma_sync(acc[i][j], al[i], bh[j], acc[i][j]);
                }
        }
        __syncthreads();
    }

#pragma unroll
    for (int i = 0; i < 2; i++)
#pragma unroll
        for (int j = 0; j < 4; j++)
            wmma::store_matrix_sync(
                &C[(arow0 + wm * 32 + i * 16) * N + bcol0 + wn * 64 + j * 16],
                acc[i][j], N, wmma::mem_row_major);
}

// Merged Q/K/V projection: grid (32 + 4 + 4, 16)
__global__ __launch_bounds__(256, 2) void gemm_qkv_kernel(
    const __nv_bfloat16* __restrict__ xh, const __nv_bfloat16* __restrict__ xl,
    const __nv_bfloat16* __restrict__ wqh, const __nv_bfloat16* __restrict__ wql,
    const __nv_bfloat16* __restrict__ wkh, const __nv_bfloat16* __restrict__ wkl,
    const __nv_bfloat16* __restrict__ wvh, const __nv_bfloat16* __restrict__ wvl,
    float* __restrict__ q, float* __restrict__ k, float* __restrict__ v, int M) {
    extern __shared__ __nv_bfloat16 sm[];
    const int bx = blockIdx.x;
    if (bx < 32)
        gemm_core(xh, xl, wqh, wql, q, M, NH * HD, DMODEL, bx, blockIdx.y, sm);
    else if (bx < 36)
        gemm_core(xh, xl, wkh, wkl, k, M, NKV * HD, DMODEL, bx - 32, blockIdx.y, sm);
    else
        gemm_core(xh, xl, wvh, wvl, v, M, NKV * HD, DMODEL, bx - 36, blockIdx.y, sm);
}

__global__ __launch_bounds__(256, 2) void gemm_wo_kernel(
    const __nv_bfloat16* __restrict__ Ah, const __nv_bfloat16* __restrict__ Al,
    const __nv_bfloat16* __restrict__ Bh, const __nv_bfloat16* __restrict__ Bl,
    float* __restrict__ C, int M) {
    extern __shared__ __nv_bfloat16 sm[];
    gemm_core(Ah, Al, Bh, Bl, C, M, DMODEL, DMODEL, blockIdx.x, blockIdx.y, sm);
}

// ---------------------------------------------------------------------------
// YaRN RoPE (unchanged).
// ---------------------------------------------------------------------------
__global__ __launch_bounds__(64) void rope_kernel(float* __restrict__ x, int nheads) {
    const int s = blockIdx.x;
    const int h = blockIdx.y;
    const int j = threadIdx.x;

    const float expo = (float)(2 * j) / 128.0f;
    float invf = 1.0f / powf(10000.0f, expo);
    const float wl = 6.283185307179586f / invf;
    const float r = 163840.0f / wl;
    float gamma = (r - 1.0f) / 31.0f;
    gamma = fminf(fmaxf(gamma, 0.0f), 1.0f);
    invf = invf * ((1.0f - gamma) / 80.0f + gamma);
    const float ang = ((float)s * invf) / 1.19925088f;
    const float c = cosf(ang);
    const float sn = sinf(ang);

    float* base = x + ((size_t)s * nheads + h) * HD;
    const float x1 = base[j];
    const float x2 = base[j + 64];
    base[j]      = x1 * c - x2 * sn;
    base[j + 64] = x2 * c + x1 * sn;
}

// ---------------------------------------------------------------------------
// Tiled causal GQA flash attention on tensor cores (mma.m16n8k16, split bf16).
// Writes split-bf16 output directly (feeds the wo GEMM).
// ---------------------------------------------------------------------------
#define QTI 128
#define KTI 64
#define QP  136
#define VP  72

__device__ __forceinline__ void mma16816(float* c, const uint32_t* a,
                                         uint32_t b0, uint32_t b1) {
    asm volatile(
        "mma.sync.aligned.m16n8k16.row.col.f32.bf16.bf16.f32 "
        "{%0,%1,%2,%3}, {%4,%5,%6,%7}, {%8,%9}, {%0,%1,%2,%3};\n"
        : "+f"(c[0]), "+f"(c[1]), "+f"(c[2]), "+f"(c[3])
        : "r"(a[0]), "r"(a[1]), "r"(a[2]), "r"(a[3]), "r"(b0), "r"(b1));
}

__device__ __forceinline__ void split2pack(float x, float y,
                                           uint32_t& hi, uint32_t& lo) {
    union { __nv_bfloat162 b2; uint32_t u; } H, L;
    __nv_bfloat16 hx = __float2bfloat16(x);
    __nv_bfloat16 hy = __float2bfloat16(y);
    H.b2.x = hx; H.b2.y = hy;
    L.b2.x = __float2bfloat16(x - __bfloat162float(hx));
    L.b2.y = __float2bfloat16(y - __bfloat162float(hy));
    hi = H.u; lo = L.u;
}

__device__ __forceinline__ void split_store4(__nv_bfloat16* ph, __nv_bfloat16* pl,
                                             float4 v) {
    union { __nv_bfloat16 b[4]; uint2 u; } H, L;
    H.b[0] = __float2bfloat16(v.x);
    H.b[1] = __float2bfloat16(v.y);
    H.b[2] = __float2bfloat16(v.z);
    H.b[3] = __float2bfloat16(v.w);
    L.b[0] = __float2bfloat16(v.x - __bfloat162float(H.b[0]));
    L.b[1] = __float2bfloat16(v.y - __bfloat162float(H.b[1]));
    L.b[2] = __float2bfloat16(v.z - __bfloat162float(H.b[2]));
    L.b[3] = __float2bfloat16(v.w - __bfloat162float(H.b[3]));
    *(uint2*)ph = H.u;
    *(uint2*)pl = L.u;
}

__global__ __launch_bounds__(256) void attn_mma(const float* __restrict__ Qg,
                                                const float* __restrict__ Kg,
                                                const float* __restrict__ Vg,
                                                __nv_bfloat16* __restrict__ Ohg,
                                                __nv_bfloat16* __restrict__ Olg) {
    extern __shared__ __nv_bfloat16 smA[];
    __nv_bfloat16* Qh  = smA;
    __nv_bfloat16* Ql  = Qh  + QTI * QP;
    __nv_bfloat16* Kh  = Ql  + QTI * QP;
    __nv_bfloat16* Kl  = Kh  + KTI * QP;
    __nv_bfloat16* Vth = Kl  + KTI * QP;
    __nv_bfloat16* Vtl = Vth + HD  * VP;

    const int qt   = gridDim.x - 1 - blockIdx.x;
    const int h    = blockIdx.y;
    const int kvh  = h >> 3;
    const int tid  = threadIdx.x;
    const int warp = tid >> 5;
    const int lane = tid & 31;
    const int lg   = lane >> 2;
    const int lc   = lane & 3;
    const int q0   = qt * QTI;
    const int rloc = warp * 16 + lg;

    for (int i = tid; i < QTI * 32; i += 256) {
        int r = i >> 5, dc = (i & 31) << 2;
        float4 v = *(const float4*)(Qg + ((size_t)(q0 + r) * NH + h) * HD + dc);
        split_store4(Qh + r * QP + dc, Ql + r * QP + dc, v);
    }

    float oacc[16][4];
#pragma unroll
    for (int n = 0; n < 16; n++)
#pragma unroll
        for (int i = 0; i < 4; i++) oacc[n][i] = 0.0f;
    float m0 = -1e30f, m1 = -1e30f, l0 = 0.0f, l1 = 0.0f;
    const float scale = 0.08838834764831845f;

    const int nkt = 2 * qt + 2;
    for (int kt = 0; kt < nkt; kt++) {
        __syncthreads();
        const int k0 = kt * KTI;

        for (int i = tid; i < KTI * 32; i += 256) {
            int r = i >> 5, dc = (i & 31) << 2;
            const size_t goff = ((size_t)(k0 + r) * NKV + kvh) * HD + dc;
            float4 kv = *(const float4*)(Kg + goff);
            split_store4(Kh + r * QP + dc, Kl + r * QP + dc, kv);
            float4 vv = *(const float4*)(Vg + goff);
#pragma unroll
            for (int jj = 0; jj < 4; jj++) {
                float x = (&vv.x)[jj];
                __nv_bfloat16 hx = __float2bfloat16(x);
                Vth[(dc + jj) * VP + r] = hx;
                Vtl[(dc + jj) * VP + r] = __float2bfloat16(x - __bfloat162float(hx));
            }
        }
        __syncthreads();

        float sc[8][4];
#pragma unroll
        for (int j = 0; j < 8; j++)
#pragma unroll
            for (int i = 0; i < 4; i++) sc[j][i] = 0.0f;

#pragma unroll
        for (int dk = 0; dk < 8; dk++) {
            const int cb = dk * 16 + lc * 2;
            uint32_t ah[4], al[4];
            ah[0] = *(const uint32_t*)&Qh[(rloc)     * QP + cb];
            ah[1] = *(const uint32_t*)&Qh[(rloc + 8) * QP + cb];
            ah[2] = *(const uint32_t*)&Qh[(rloc)     * QP + cb + 8];
            ah[3] = *(const uint32_t*)&Qh[(rloc + 8) * QP + cb + 8];
            al[0] = *(const uint32_t*)&Ql[(rloc)     * QP + cb];
            al[1] = *(const uint32_t*)&Ql[(rloc + 8) * QP + cb];
            al[2] = *(const uint32_t*)&Ql[(rloc)     * QP + cb + 8];
            al[3] = *(const uint32_t*)&Ql[(rloc + 8) * QP + cb + 8];
#pragma unroll
            for (int j = 0; j < 8; j++) {
                const int krow = j * 8 + lg;
                uint32_t bh0 = *(const uint32_t*)&Kh[krow * QP + cb];
                uint32_t bh1 = *(const uint32_t*)&Kh[krow * QP + cb + 8];
                uint32_t bl0 = *(const uint32_t*)&Kl[krow * QP + cb];
                uint32_t bl1 = *(const uint32_t*)&Kl[krow * QP + cb + 8];
                mma16816(sc[j], ah, bh0, bh1);
                mma16816(sc[j], ah, bl0, bl1);
                mma16816(sc[j], al, bh0, bh1);
            }
        }

        const bool dm = (kt >= 2 * qt);
#pragma unroll
        for (int j = 0; j < 8; j++) {
            const int keyb = k0 + j * 8 + lc * 2;
#pragma unroll
            for (int i = 0; i < 4; i++) {
                const int key = keyb + (i & 1);
                const int qr  = q0 + rloc + ((i >> 1) << 3);
                float s = sc[j][i] * scale;
                sc[j][i] = (dm && key > qr) ? -1e30f : s;
            }
        }

        float mx0 = -1e30f, mx1 = -1e30f;
#pragma unroll
        for (int j = 0; j < 8; j++) {
            mx0 = fmaxf(mx0, fmaxf(sc[j][0], sc[j][1]));
            mx1 = fmaxf(mx1, fmaxf(sc[j][2], sc[j][3]));
        }
        mx0 = fmaxf(mx0, __shfl_xor_sync(0xffffffffu, mx0, 1));
        mx0 = fmaxf(mx0, __shfl_xor_sync(0xffffffffu, mx0, 2));
        mx1 = fmaxf(mx1, __shfl_xor_sync(0xffffffffu, mx1, 1));
        mx1 = fmaxf(mx1, __shfl_xor_sync(0xffffffffu, mx1, 2));

        const float mn0 = fmaxf(m0, mx0), mn1 = fmaxf(m1, mx1);
        const float a0 = __expf(m0 - mn0), a1 = __expf(m1 - mn1);
        m0 = mn0; m1 = mn1;
        l0 *= a0; l1 *= a1;
#pragma unroll
        for (int n = 0; n < 16; n++) {
            oacc[n][0] *= a0; oacc[n][1] *= a0;
            oacc[n][2] *= a1; oacc[n][3] *= a1;
        }

        float rs0 = 0.0f, rs1 = 0.0f;
#pragma unroll
        for (int j = 0; j < 8; j++) {
            sc[j][0] = __expf(sc[j][0] - mn0); rs0 += sc[j][0];
            sc[j][1] = __expf(sc[j][1] - mn0); rs0 += sc[j][1];
            sc[j][2] = __expf(sc[j][2] - mn1); rs1 += sc[j][2];
            sc[j][3] = __expf(sc[j][3] - mn1); rs1 += sc[j][3];
        }
        rs0 += __shfl_xor_sync(0xffffffffu, rs0, 1);
        rs0 += __shfl_xor_sync(0xffffffffu, rs0, 2);
        rs1 += __shfl_xor_sync(0xffffffffu, rs1, 1);
        rs1 += __shfl_xor_sync(0xffffffffu, rs1, 2);
        l0 += rs0; l1 += rs1;

        uint32_t pah[4][4], pal[4][4];
#pragma unroll
        for (int k4 = 0; k4 < 4; k4++) {
            const int j0 = 2 * k4, j1 = 2 * k4 + 1;
            split2pack(sc[j0][0], sc[j0][1], pah[k4][0], pal[k4][0]);
            split2pack(sc[j0][2], sc[j0][3], pah[k4][1], pal[k4][1]);
            split2pack(sc[j1][0], sc[j1][1], pah[k4][2], pal[k4][2]);
            split2pack(sc[j1][2], sc[j1][3], pah[k4][3], pal[k4][3]);
        }

#pragma unroll
        for (int k4 = 0; k4 < 4; k4++) {
            const int kb = k4 * 16 + lc * 2;
#pragma unroll
            for (int n = 0; n < 16; n++) {
                const int drow = n * 8 + lg;
                uint32_t bh0 = *(const uint32_t*)&Vth[drow * VP + kb];
                uint32_t bh1 = *(const uint32_t*)&Vth[drow * VP + kb + 8];
                uint32_t bl0 = *(const uint32_t*)&Vtl[drow * VP + kb];
                uint32_t bl1 = *(const uint32_t*)&Vtl[drow * VP + kb + 8];
                mma16816(oacc[n], pah[k4], bh0, bh1);
                mma16816(oacc[n], pah[k4], bl0, bl1);
                mma16816(oacc[n], pal[k4], bh0, bh1);
            }
        }
    }

    // epilogue: normalize, split to (hi, lo) bf16, store
    const float i0 = 1.0f / l0, i1 = 1.0f / l1;
#pragma unroll
    for (int n = 0; n < 16; n++) {
        const int d = n * 8 + lc * 2;
        uint32_t h0, lo0, h1, lo1;
        split2pack(oacc[n][0] * i0, oacc[n][1] * i0, h0, lo0);
        split2pack(oacc[n][2] * i1, oacc[n][3] * i1, h1, lo1);
        const size_t off0 = ((size_t)(q0 + rloc)     * NH + h) * HD + d;
        const size_t off1 = ((size_t)(q0 + rloc + 8) * NH + h) * HD + d;
        *(uint32_t*)(Ohg + off0) = h0;
        *(uint32_t*)(Olg + off0) = lo0;
        *(uint32_t*)(Ohg + off1) = h1;
        *(uint32_t*)(Olg + off1) = lo1;
    }
}

// ---------------------------------------------------------------------------
// Launch
// ---------------------------------------------------------------------------
extern "C" void kernel_launch(void* const* d_in, const int* in_sizes, int n_in,
                              void* d_out, int out_size) {
    const float* x  = (const float*)d_in[0];
    const float* wq = (const float*)d_in[1];
    const float* wk = (const float*)d_in[2];
    const float* wv = (const float*)d_in[3];
    const float* wo = (const float*)d_in[4];
    float* out = (float*)d_out;

    const int S = in_sizes[0] / DMODEL;   // 2048

    float *q, *k, *v;
    cudaGetSymbolAddress((void**)&q, g_q);
    cudaGetSymbolAddress((void**)&k, g_k);
    cudaGetSymbolAddress((void**)&v, g_v);

    __nv_bfloat16 *xh, *xl, *wqh, *wql, *wkh, *wkl, *wvh, *wvl, *woh, *wol, *oh, *ol;
    cudaGetSymbolAddress((void**)&xh, g_xh);   cudaGetSymbolAddress((void**)&xl, g_xl);
    cudaGetSymbolAddress((void**)&wqh, g_wqh); cudaGetSymbolAddress((void**)&wql, g_wql);
    cudaGetSymbolAddress((void**)&wkh, g_wkh); cudaGetSymbolAddress((void**)&wkl, g_wkl);
    cudaGetSymbolAddress((void**)&wvh, g_wvh); cudaGetSymbolAddress((void**)&wvl, g_wvl);
    cudaGetSymbolAddress((void**)&woh, g_woh); cudaGetSymbolAddress((void**)&wol, g_wol);
    cudaGetSymbolAddress((void**)&oh, g_oh);   cudaGetSymbolAddress((void**)&ol, g_ol);

    auto split = [](const float* p, __nv_bfloat16* h, __nv_bfloat16* l, int count) {
        int n4 = count / 4;
        split_kernel<<<(n4 + 255) / 256, 256>>>((const float4*)p, (uint2*)h, (uint2*)l, n4);
    };

    split(x,  xh,  xl,  S * DMODEL);
    split(wq, wqh, wql, DMODEL * NH * HD);
    split(wk, wkh, wkl, DMODEL * NKV * HD);
    split(wv, wvh, wvl, DMODEL * NKV * HD);
    split(wo, woh, wol, NH * HD * DMODEL);

    cudaFuncSetAttribute(gemm_qkv_kernel, cudaFuncAttributeMaxDynamicSharedMemorySize, GEMM_SMEM);
    cudaFuncSetAttribute(gemm_wo_kernel,  cudaFuncAttributeMaxDynamicSharedMemorySize, GEMM_SMEM);

    // Merged Q/K/V projections
    gemm_qkv_kernel<<<dim3(40, S / BM), 256, GEMM_SMEM>>>(
        xh, xl, wqh, wql, wkh, wkl, wvh, wvl, q, k, v, S);

    rope_kernel<<<dim3(S, NH), 64>>>(q, NH);
    rope_kernel<<<dim3(S, NKV), 64>>>(k, NKV);

    // Tensor-core flash attention -> split bf16 output
    const int smem_bytes = (2 * QTI * QP + 2 * KTI * QP + 2 * HD * VP) * (int)sizeof(__nv_bfloat16);
    cudaFuncSetAttribute(attn_mma, cudaFuncAttributeMaxDynamicSharedMemorySize, smem_bytes);
    attn_mma<<<dim3(S / QTI, NH), 256, smem_bytes>>>(q, k, v, oh, ol);

    // Output projection
    gemm_wo_kernel<<<dim3(DMODEL / BN, S / BM), 256, GEMM_SMEM>>>(oh, ol, woh, wol, out, S);
}

// round 9
// speedup vs baseline: 4.2899x; 1.0313x over previous
#include <cuda_runtime.h>
#include <cuda_bf16.h>
#include <mma.h>
#include <math.h>
#include <stdint.h>

using namespace nvcuda;

#define DMODEL 4096
#define NH 32
#define NKV 4
#define HD 128
#define S_MAX 2048

// fp32 activations
__device__ float g_q[S_MAX * NH * HD];
__device__ float g_k[S_MAX * NKV * HD];
__device__ float g_v[S_MAX * NKV * HD];

// split-bf16 operands (hi + lo representation of fp32)
__device__ __nv_bfloat16 g_xh[S_MAX * DMODEL],  g_xl[S_MAX * DMODEL];
__device__ __nv_bfloat16 g_wqh[DMODEL * NH * HD],  g_wql[DMODEL * NH * HD];
__device__ __nv_bfloat16 g_wkh[DMODEL * NKV * HD], g_wkl[DMODEL * NKV * HD];
__device__ __nv_bfloat16 g_wvh[DMODEL * NKV * HD], g_wvl[DMODEL * NKV * HD];
__device__ __nv_bfloat16 g_woh[NH * HD * DMODEL],  g_wol[NH * HD * DMODEL];
__device__ __nv_bfloat16 g_oh[S_MAX * NH * HD],    g_ol[S_MAX * NH * HD];

// ---------------------------------------------------------------------------
// fp32 -> (hi, lo) bf16 split.
// ---------------------------------------------------------------------------
__global__ __launch_bounds__(256) void split_kernel(const float4* __restrict__ x,
                                                    uint2* __restrict__ hi,
                                                    uint2* __restrict__ lo,
                                                    int n4) {
    int i = blockIdx.x * 256 + threadIdx.x;
    if (i >= n4) return;
    float4 v = x[i];
    union { __nv_bfloat16 b[4]; uint2 u; } H, L;
    H.b[0] = __float2bfloat16(v.x);
    H.b[1] = __float2bfloat16(v.y);
    H.b[2] = __float2bfloat16(v.z);
    H.b[3] = __float2bfloat16(v.w);
    L.b[0] = __float2bfloat16(v.x - __bfloat162float(H.b[0]));
    L.b[1] = __float2bfloat16(v.y - __bfloat162float(H.b[1]));
    L.b[2] = __float2bfloat16(v.z - __bfloat162float(H.b[2]));
    L.b[3] = __float2bfloat16(v.w - __bfloat162float(H.b[3]));
    hi[i] = H.u;
    lo[i] = L.u;
}

// ---------------------------------------------------------------------------
// Double-buffered split-bf16 tensor-core GEMM (cp.async pipeline).
// C = Ahi*Bhi + Ahi*Blo + Alo*Bhi, fp32 accum.
// ---------------------------------------------------------------------------
#define BM 128
#define BN 128
#define BK 32
#define PAD 8
#define AP (BK + PAD)
#define BP (BN + PAD)
#define ASZ (BM * AP)
#define BSZ (BK * BP)
#define STG (2 * ASZ + 2 * BSZ)
#define GEMM_SMEM (2 * STG * 2)

__device__ __forceinline__ void cpa16(uint32_t d, const void* s) {
    asm volatile("cp.async.cg.shared.global [%0], [%1], 16;\n" :: "r"(d), "l"(s));
}
__device__ __forceinline__ void cp_commit() {
    asm volatile("cp.async.commit_group;\n");
}
template <int N> __device__ __forceinline__ void cp_wait() {
    asm volatile("cp.async.wait_group %0;\n" :: "n"(N));
}

__device__ __forceinline__ void gemm_core(
    const __nv_bfloat16* __restrict__ Ah, const __nv_bfloat16* __restrict__ Al,
    const __nv_bfloat16* __restrict__ Bh, const __nv_bfloat16* __restrict__ Bl,
    float* __restrict__ C, int M, int N, int K, int bx, int by,
    __nv_bfloat16* sm) {
    const int tid  = threadIdx.x;
    const int warp = tid >> 5;
    const int wm   = warp >> 1;
    const int wn   = warp & 1;
    const size_t arow0 = (size_t)by * BM;
    const size_t bcol0 = (size_t)bx * BN;
    const uint32_t sb = (uint32_t)__cvta_generic_to_shared(sm);

    auto load_stage = [&](int st, int k0) {
        const uint32_t base = sb + (uint32_t)(st * STG * 2);
#pragma unroll
        for (int it = 0; it < 2; it++) {
            const int c = tid + it * 256;
            const int r = c >> 2, col = (c & 3) << 3;
            const uint32_t da = base + (uint32_t)((r * AP + col) << 1);
            cpa16(da,           Ah + (arow0 + r) * K + k0 + col);
            cpa16(da + ASZ * 2, Al + (arow0 + r) * K + k0 + col);
            const int br = c >> 4, bc = (c & 15) << 3;
            const uint32_t db = base + (uint32_t)((2 * ASZ + br * BP + bc) << 1);
            cpa16(db,           Bh + (size_t)(k0 + br) * N + bcol0 + bc);
            cpa16(db + BSZ * 2, Bl + (size_t)(k0 + br) * N + bcol0 + bc);
        }
    };

    wmma::fragment<wmma::accumulator, 16, 16, 16, float> acc[2][4];
#pragma unroll
    for (int i = 0; i < 2; i++)
#pragma unroll
        for (int j = 0; j < 4; j++) wmma::fill_fragment(acc[i][j], 0.0f);

    const int nst = K / BK;
    load_stage(0, 0);
    cp_commit();

    for (int t = 0; t < nst; t++) {
        if (t + 1 < nst) {
            load_stage((t + 1) & 1, (t + 1) * BK);
            cp_commit();
            cp_wait<1>();
        } else {
            cp_wait<0>();
        }
        __syncthreads();

        __nv_bfloat16* p   = sm + (t & 1) * STG;
        __nv_bfloat16* pAh = p;
        __nv_bfloat16* pAl = p + ASZ;
        __nv_bfloat16* pBh = p + 2 * ASZ;
        __nv_bfloat16* pBl = p + 2 * ASZ + BSZ;

#pragma unroll
        for (int kt = 0; kt < 2; kt++) {
            wmma::fragment<wmma::matrix_a, 16, 16, 16, __nv_bfloat16, wmma::row_major> ah[2], al[2];
            wmma::fragment<wmma::matrix_b, 16, 16, 16, __nv_bfloat16, wmma::row_major> bh[4], bl[4];
#pragma unroll
            for (int i = 0; i < 2; i++) {
                wmma::load_matrix_sync(ah[i], pAh + (wm * 32 + i * 16) * AP + kt * 16, AP);
                wmma::load_matrix_sync(al[i], pAl + (wm * 32 + i * 16) * AP + kt * 16, AP);
            }
#pragma unroll
            for (int j = 0; j < 4; j++) {
                wmma::load_matrix_sync(bh[j], pBh + kt * 16 * BP + wn * 64 + j * 16, BP);
                wmma::load_matrix_sync(bl[j], pBl + kt * 16 * BP + wn * 64 + j * 16, BP);
            }
#pragma unroll
            for (int i = 0; i < 2; i++)
#pragma unroll
                for (int j = 0; j < 4; j++) {
                    wmma::mma_sync(acc[i][j], ah[i], bh[j], acc[i][j]);
                    wmma::mma_sync(acc[i][j], ah[i], bl[j], acc[i][j]);
                    wmma::mma_sync(acc[i][j], al[i], bh[j], acc[i][j]);
                }
        }
        __syncthreads();
    }

#pragma unroll
    for (int i = 0; i < 2; i++)
#pragma unroll
        for (int j = 0; j < 4; j++)
            wmma::store_matrix_sync(
                &C[(arow0 + wm * 32 + i * 16) * N + bcol0 + wn * 64 + j * 16],
                acc[i][j], N, wmma::mem_row_major);
}

// Merged Q/K/V projection: grid (32 + 4 + 4, 16)
__global__ __launch_bounds__(256, 2) void gemm_qkv_kernel(
    const __nv_bfloat16* __restrict__ xh, const __nv_bfloat16* __restrict__ xl,
    const __nv_bfloat16* __restrict__ wqh, const __nv_bfloat16* __restrict__ wql,
    const __nv_bfloat16* __restrict__ wkh, const __nv_bfloat16* __restrict__ wkl,
    const __nv_bfloat16* __restrict__ wvh, const __nv_bfloat16* __restrict__ wvl,
    float* __restrict__ q, float* __restrict__ k, float* __restrict__ v, int M) {
    extern __shared__ __nv_bfloat16 sm[];
    const int bx = blockIdx.x;
    if (bx < 32)
        gemm_core(xh, xl, wqh, wql, q, M, NH * HD, DMODEL, bx, blockIdx.y, sm);
    else if (bx < 36)
        gemm_core(xh, xl, wkh, wkl, k, M, NKV * HD, DMODEL, bx - 32, blockIdx.y, sm);
    else
        gemm_core(xh, xl, wvh, wvl, v, M, NKV * HD, DMODEL, bx - 36, blockIdx.y, sm);
}

__global__ __launch_bounds__(256, 2) void gemm_wo_kernel(
    const __nv_bfloat16* __restrict__ Ah, const __nv_bfloat16* __restrict__ Al,
    const __nv_bfloat16* __restrict__ Bh, const __nv_bfloat16* __restrict__ Bl,
    float* __restrict__ C, int M) {
    extern __shared__ __nv_bfloat16 sm[];
    gemm_core(Ah, Al, Bh, Bl, C, M, DMODEL, DMODEL, blockIdx.x, blockIdx.y, sm);
}

// ---------------------------------------------------------------------------
// YaRN RoPE (unchanged).
// ---------------------------------------------------------------------------
__global__ __launch_bounds__(64) void rope_kernel(float* __restrict__ x, int nheads) {
    const int s = blockIdx.x;
    const int h = blockIdx.y;
    const int j = threadIdx.x;

    const float expo = (float)(2 * j) / 128.0f;
    float invf = 1.0f / powf(10000.0f, expo);
    const float wl = 6.283185307179586f / invf;
    const float r = 163840.0f / wl;
    float gamma = (r - 1.0f) / 31.0f;
    gamma = fminf(fmaxf(gamma, 0.0f), 1.0f);
    invf = invf * ((1.0f - gamma) / 80.0f + gamma);
    const float ang = ((float)s * invf) / 1.19925088f;
    const float c = cosf(ang);
    const float sn = sinf(ang);

    float* base = x + ((size_t)s * nheads + h) * HD;
    const float x1 = base[j];
    const float x2 = base[j + 64];
    base[j]      = x1 * c - x2 * sn;
    base[j + 64] = x2 * c + x1 * sn;
}

// ---------------------------------------------------------------------------
// Tiled causal GQA flash attention on tensor cores (mma.m16n8k16, split bf16).
// R9: Q fragments hoisted to registers; K/V double-buffered, 1 sync per tile;
// softmax scale folded into Q.
// ---------------------------------------------------------------------------
#define QTI 128
#define KTI 64
#define QP  136
#define VP  72
// per-stage K/V buffer (elems): Kh + Kl + Vth + Vtl
#define KV_STAGE (2 * KTI * QP + 2 * HD * VP)   // 35840 elems = 71680 B
#define ATTN_SMEM (2 * KV_STAGE * 2)            // 143360 B

__device__ __forceinline__ void mma16816(float* c, const uint32_t* a,
                                         uint32_t b0, uint32_t b1) {
    asm volatile(
        "mma.sync.aligned.m16n8k16.row.col.f32.bf16.bf16.f32 "
        "{%0,%1,%2,%3}, {%4,%5,%6,%7}, {%8,%9}, {%0,%1,%2,%3};\n"
        : "+f"(c[0]), "+f"(c[1]), "+f"(c[2]), "+f"(c[3])
        : "r"(a[0]), "r"(a[1]), "r"(a[2]), "r"(a[3]), "r"(b0), "r"(b1));
}

__device__ __forceinline__ void split2pack(float x, float y,
                                           uint32_t& hi, uint32_t& lo) {
    union { __nv_bfloat162 b2; uint32_t u; } H, L;
    __nv_bfloat16 hx = __float2bfloat16(x);
    __nv_bfloat16 hy = __float2bfloat16(y);
    H.b2.x = hx; H.b2.y = hy;
    L.b2.x = __float2bfloat16(x - __bfloat162float(hx));
    L.b2.y = __float2bfloat16(y - __bfloat162float(hy));
    hi = H.u; lo = L.u;
}

__device__ __forceinline__ void split_store4(__nv_bfloat16* ph, __nv_bfloat16* pl,
                                             float4 v) {
    union { __nv_bfloat16 b[4]; uint2 u; } H, L;
    H.b[0] = __float2bfloat16(v.x);
    H.b[1] = __float2bfloat16(v.y);
    H.b[2] = __float2bfloat16(v.z);
    H.b[3] = __float2bfloat16(v.w);
    L.b[0] = __float2bfloat16(v.x - __bfloat162float(H.b[0]));
    L.b[1] = __float2bfloat16(v.y - __bfloat162float(H.b[1]));
    L.b[2] = __float2bfloat16(v.z - __bfloat162float(H.b[2]));
    L.b[3] = __float2bfloat16(v.w - __bfloat162float(H.b[3]));
    *(uint2*)ph = H.u;
    *(uint2*)pl = L.u;
}

__global__ __launch_bounds__(256) void attn_mma(const float* __restrict__ Qg,
                                                const float* __restrict__ Kg,
                                                const float* __restrict__ Vg,
                                                __nv_bfloat16* __restrict__ Ohg,
                                                __nv_bfloat16* __restrict__ Olg) {
    extern __shared__ __nv_bfloat16 smA[];

    const int qt   = gridDim.x - 1 - blockIdx.x;   // big tiles first
    const int h    = blockIdx.y;
    const int kvh  = h >> 3;
    const int tid  = threadIdx.x;
    const int warp = tid >> 5;
    const int lane = tid & 31;
    const int lg   = lane >> 2;
    const int lc   = lane & 3;
    const int q0   = qt * QTI;
    const int rloc = warp * 16 + lg;
    const float scale = 0.08838834764831845f;

    // K/V tile load+split into stage s.
    auto load_tile = [&](int kt, int s) {
        __nv_bfloat16* Kh  = smA + s * KV_STAGE;
        __nv_bfloat16* Kl  = Kh + KTI * QP;
        __nv_bfloat16* Vth = Kl + KTI * QP;
        __nv_bfloat16* Vtl = Vth + HD * VP;
        const int k0 = kt * KTI;
        for (int i = tid; i < KTI * 32; i += 256) {
            int r = i >> 5, dc = (i & 31) << 2;
            const size_t goff = ((size_t)(k0 + r) * NKV + kvh) * HD + dc;
            float4 kv = *(const float4*)(Kg + goff);
            split_store4(Kh + r * QP + dc, Kl + r * QP + dc, kv);
            float4 vv = *(const float4*)(Vg + goff);
#pragma unroll
            for (int jj = 0; jj < 4; jj++) {
                float x = (&vv.x)[jj];
                __nv_bfloat16 hx = __float2bfloat16(x);
                Vth[(dc + jj) * VP + r] = hx;
                Vtl[(dc + jj) * VP + r] = __float2bfloat16(x - __bfloat162float(hx));
            }
        }
    };

    // ---- Q tile staged in stage-1 space (freed before tile 1 loads) ----
    {
        __nv_bfloat16* Qh = smA + KV_STAGE;
        __nv_bfloat16* Ql = Qh + QTI * QP;
        for (int i = tid; i < QTI * 32; i += 256) {
            int r = i >> 5, dc = (i & 31) << 2;
            float4 v = *(const float4*)(Qg + ((size_t)(q0 + r) * NH + h) * HD + dc);
            v.x *= scale; v.y *= scale; v.z *= scale; v.w *= scale;
            split_store4(Qh + r * QP + dc, Ql + r * QP + dc, v);
        }
    }
    load_tile(0, 0);
    __syncthreads();

    // ---- hoist Q fragments into registers (loop-invariant) ----
    uint32_t qah[8][4], qal[8][4];
    {
        const __nv_bfloat16* Qh = smA + KV_STAGE;
        const __nv_bfloat16* Ql = Qh + QTI * QP;
#pragma unroll
        for (int dk = 0; dk < 8; dk++) {
            const int cb = dk * 16 + lc * 2;
            qah[dk][0] = *(const uint32_t*)&Qh[(rloc)     * QP + cb];
            qah[dk][1] = *(const uint32_t*)&Qh[(rloc + 8) * QP + cb];
            qah[dk][2] = *(const uint32_t*)&Qh[(rloc)     * QP + cb + 8];
            qah[dk][3] = *(const uint32_t*)&Qh[(rloc + 8) * QP + cb + 8];
            qal[dk][0] = *(const uint32_t*)&Ql[(rloc)     * QP + cb];
            qal[dk][1] = *(const uint32_t*)&Ql[(rloc + 8) * QP + cb];
            qal[dk][2] = *(const uint32_t*)&Ql[(rloc)     * QP + cb + 8];
            qal[dk][3] = *(const uint32_t*)&Ql[(rloc + 8) * QP + cb + 8];
        }
    }
    __syncthreads();   // Q frag reads done: stage 1 is free for tile loads

    float oacc[16][4];
#pragma unroll
    for (int n = 0; n < 16; n++)
#pragma unroll
        for (int i = 0; i < 4; i++) oacc[n][i] = 0.0f;
    float m0 = -1e30f, m1 = -1e30f, l0 = 0.0f, l1 = 0.0f;

    const int nkt = 2 * qt + 2;
    for (int kt = 0; kt < nkt; kt++) {
        const int s = kt & 1;
        const __nv_bfloat16* Kh  = smA + s * KV_STAGE;
        const __nv_bfloat16* Kl  = Kh + KTI * QP;
        const __nv_bfloat16* Vth = Kl + KTI * QP;
        const __nv_bfloat16* Vtl = Vth + HD * VP;
        const int k0 = kt * KTI;

        // ---- S = Q K^T (Q frags in registers) ----
        float sc[8][4];
#pragma unroll
        for (int j = 0; j < 8; j++)
#pragma unroll
            for (int i = 0; i < 4; i++) sc[j][i] = 0.0f;

#pragma unroll
        for (int dk = 0; dk < 8; dk++) {
            const int cb = dk * 16 + lc * 2;
#pragma unroll
            for (int j = 0; j < 8; j++) {
                const int krow = j * 8 + lg;
                uint32_t bh0 = *(const uint32_t*)&Kh[krow * QP + cb];
                uint32_t bh1 = *(const uint32_t*)&Kh[krow * QP + cb + 8];
                uint32_t bl0 = *(const uint32_t*)&Kl[krow * QP + cb];
                uint32_t bl1 = *(const uint32_t*)&Kl[krow * QP + cb + 8];
                mma16816(sc[j], qah[dk], bh0, bh1);
                mma16816(sc[j], qah[dk], bl0, bl1);
                mma16816(sc[j], qal[dk], bh0, bh1);
            }
        }

        // ---- causal mask (scale already folded into Q) ----
        const bool dm = (kt >= 2 * qt);
        if (dm) {
#pragma unroll
            for (int j = 0; j < 8; j++) {
                const int keyb = k0 + j * 8 + lc * 2;
#pragma unroll
                for (int i = 0; i < 4; i++) {
                    const int key = keyb + (i & 1);
                    const int qr  = q0 + rloc + ((i >> 1) << 3);
                    if (key > qr) sc[j][i] = -1e30f;
                }
            }
        }

        // ---- online softmax (registers) ----
        float mx0 = -1e30f, mx1 = -1e30f;
#pragma unroll
        for (int j = 0; j < 8; j++) {
            mx0 = fmaxf(mx0, fmaxf(sc[j][0], sc[j][1]));
            mx1 = fmaxf(mx1, fmaxf(sc[j][2], sc[j][3]));
        }
        mx0 = fmaxf(mx0, __shfl_xor_sync(0xffffffffu, mx0, 1));
        mx0 = fmaxf(mx0, __shfl_xor_sync(0xffffffffu, mx0, 2));
        mx1 = fmaxf(mx1, __shfl_xor_sync(0xffffffffu, mx1, 1));
        mx1 = fmaxf(mx1, __shfl_xor_sync(0xffffffffu, mx1, 2));

        const float mn0 = fmaxf(m0, mx0), mn1 = fmaxf(m1, mx1);
        const float a0 = __expf(m0 - mn0), a1 = __expf(m1 - mn1);
        m0 = mn0; m1 = mn1;
        l0 *= a0; l1 *= a1;
#pragma unroll
        for (int n = 0; n < 16; n++) {
            oacc[n][0] *= a0; oacc[n][1] *= a0;
            oacc[n][2] *= a1; oacc[n][3] *= a1;
        }

        float rs0 = 0.0f, rs1 = 0.0f;
#pragma unroll
        for (int j = 0; j < 8; j++) {
            sc[j][0] = __expf(sc[j][0] - mn0); rs0 += sc[j][0];
            sc[j][1] = __expf(sc[j][1] - mn0); rs0 += sc[j][1];
            sc[j][2] = __expf(sc[j][2] - mn1); rs1 += sc[j][2];
            sc[j][3] = __expf(sc[j][3] - mn1); rs1 += sc[j][3];
        }
        rs0 += __shfl_xor_sync(0xffffffffu, rs0, 1);
        rs0 += __shfl_xor_sync(0xffffffffu, rs0, 2);
        rs1 += __shfl_xor_sync(0xffffffffu, rs1, 1);
        rs1 += __shfl_xor_sync(0xffffffffu, rs1, 2);
        l0 += rs0; l1 += rs1;

        // ---- P fragments ----
        uint32_t pah[4][4], pal[4][4];
#pragma unroll
        for (int k4 = 0; k4 < 4; k4++) {
            const int j0 = 2 * k4, j1 = 2 * k4 + 1;
            split2pack(sc[j0][0], sc[j0][1], pah[k4][0], pal[k4][0]);
            split2pack(sc[j0][2], sc[j0][3], pah[k4][1], pal[k4][1]);
            split2pack(sc[j1][0], sc[j1][1], pah[k4][2], pal[k4][2]);
            split2pack(sc[j1][2], sc[j1][3], pah[k4][3], pal[k4][3]);
        }

        // ---- O += P V ----
#pragma unroll
        for (int k4 = 0; k4 < 4; k4++) {
            const int kb = k4 * 16 + lc * 2;
#pragma unroll
            for (int n = 0; n < 16; n++) {
                const int drow = n * 8 + lg;
                uint32_t bh0 = *(const uint32_t*)&Vth[drow * VP + kb];
                uint32_t bh1 = *(const uint32_t*)&Vth[drow * VP + kb + 8];
                uint32_t bl0 = *(const uint32_t*)&Vtl[drow * VP + kb];
                uint32_t bl1 = *(const uint32_t*)&Vtl[drow * VP + kb + 8];
                mma16816(oacc[n], pah[k4], bh0, bh1);
                mma16816(oacc[n], pah[k4], bl0, bl1);
                mma16816(oacc[n], pal[k4], bh0, bh1);
            }
        }

        // ---- prefetch next tile into the other stage, single barrier ----
        if (kt + 1 < nkt) load_tile(kt + 1, s ^ 1);
        __syncthreads();
    }

    // ---- epilogue: normalize, split, store ----
    const float i0 = 1.0f / l0, i1 = 1.0f / l1;
#pragma unroll
    for (int n = 0; n < 16; n++) {
        const int d = n * 8 + lc * 2;
        uint32_t h0, lo0, h1, lo1;
        split2pack(oacc[n][0] * i0, oacc[n][1] * i0, h0, lo0);
        split2pack(oacc[n][2] * i1, oacc[n][3] * i1, h1, lo1);
        const size_t off0 = ((size_t)(q0 + rloc)     * NH + h) * HD + d;
        const size_t off1 = ((size_t)(q0 + rloc + 8) * NH + h) * HD + d;
        *(uint32_t*)(Ohg + off0) = h0;
        *(uint32_t*)(Olg + off0) = lo0;
        *(uint32_t*)(Ohg + off1) = h1;
        *(uint32_t*)(Olg + off1) = lo1;
    }
}

// ---------------------------------------------------------------------------
// Launch
// ---------------------------------------------------------------------------
extern "C" void kernel_launch(void* const* d_in, const int* in_sizes, int n_in,
                              void* d_out, int out_size) {
    const float* x  = (const float*)d_in[0];
    const float* wq = (const float*)d_in[1];
    const float* wk = (const float*)d_in[2];
    const float* wv = (const float*)d_in[3];
    const float* wo = (const float*)d_in[4];
    float* out = (float*)d_out;

    const int S = in_sizes[0] / DMODEL;   // 2048

    float *q, *k, *v;
    cudaGetSymbolAddress((void**)&q, g_q);
    cudaGetSymbolAddress((void**)&k, g_k);
    cudaGetSymbolAddress((void**)&v, g_v);

    __nv_bfloat16 *xh, *xl, *wqh, *wql, *wkh, *wkl, *wvh, *wvl, *woh, *wol, *oh, *ol;
    cudaGetSymbolAddress((void**)&xh, g_xh);   cudaGetSymbolAddress((void**)&xl, g_xl);
    cudaGetSymbolAddress((void**)&wqh, g_wqh); cudaGetSymbolAddress((void**)&wql, g_wql);
    cudaGetSymbolAddress((void**)&wkh, g_wkh); cudaGetSymbolAddress((void**)&wkl, g_wkl);
    cudaGetSymbolAddress((void**)&wvh, g_wvh); cudaGetSymbolAddress((void**)&wvl, g_wvl);
    cudaGetSymbolAddress((void**)&woh, g_woh); cudaGetSymbolAddress((void**)&wol, g_wol);
    cudaGetSymbolAddress((void**)&oh, g_oh);   cudaGetSymbolAddress((void**)&ol, g_ol);

    auto split = [](const float* p, __nv_bfloat16* h, __nv_bfloat16* l, int count) {
        int n4 = count / 4;
        split_kernel<<<(n4 + 255) / 256, 256>>>((const float4*)p, (uint2*)h, (uint2*)l, n4);
    };

    split(x,  xh,  xl,  S * DMODEL);
    split(wq, wqh, wql, DMODEL * NH * HD);
    split(wk, wkh, wkl, DMODEL * NKV * HD);
    split(wv, wvh, wvl, DMODEL * NKV * HD);
    split(wo, woh, wol, NH * HD * DMODEL);

    cudaFuncSetAttribute(gemm_qkv_kernel, cudaFuncAttributeMaxDynamicSharedMemorySize, GEMM_SMEM);
    cudaFuncSetAttribute(gemm_wo_kernel,  cudaFuncAttributeMaxDynamicSharedMemorySize, GEMM_SMEM);

    // Merged Q/K/V projections
    gemm_qkv_kernel<<<dim3(40, S / BM), 256, GEMM_SMEM>>>(
        xh, xl, wqh, wql, wkh, wkl, wvh, wvl, q, k, v, S);

    rope_kernel<<<dim3(S, NH), 64>>>(q, NH);
    rope_kernel<<<dim3(S, NKV), 64>>>(k, NKV);

    // Tensor-core flash attention -> split bf16 output
    cudaFuncSetAttribute(attn_mma, cudaFuncAttributeMaxDynamicSharedMemorySize, ATTN_SMEM);
    attn_mma<<<dim3(S / QTI, NH), 256, ATTN_SMEM>>>(q, k, v, oh, ol);

    // Output projection
    gemm_wo_kernel<<<dim3(DMODEL / BN, S / BM), 256, GEMM_SMEM>>>(oh, ol, woh, wol, out, S);
}

// round 10
// speedup vs baseline: 5.9427x; 1.3853x over previous
#include <cuda_runtime.h>
#include <cuda_bf16.h>
#include <mma.h>
#include <math.h>
#include <stdint.h>

using namespace nvcuda;

#define DMODEL 4096
#define NH 32
#define NKV 4
#define HD 128
#define S_MAX 2048

// fp32 activations (GEMM outputs)
__device__ float g_q[S_MAX * NH * HD];
__device__ float g_k[S_MAX * NKV * HD];
__device__ float g_v[S_MAX * NKV * HD];

// ---- packed smem-image layouts ----
// GEMM A-image per (by, kc): 128 rows x 40 cols bf16 (32 data + 8 pad)
// GEMM B-image per (bx, kc): 32 rows x 136 cols bf16 (128 data + 8 pad)
#define A_IMG 5120              // elems (128*40)
#define B_IMG 4352              // elems (32*136)
#define KC_N 128                // K chunks (4096/32)

__device__ __nv_bfloat16 g_xh[16 * KC_N * A_IMG], g_xl[16 * KC_N * A_IMG];
__device__ __nv_bfloat16 g_oh[16 * KC_N * A_IMG], g_ol[16 * KC_N * A_IMG];
__device__ __nv_bfloat16 g_wqh[32 * KC_N * B_IMG], g_wql[32 * KC_N * B_IMG];
__device__ __nv_bfloat16 g_wkh[4 * KC_N * B_IMG],  g_wkl[4 * KC_N * B_IMG];
__device__ __nv_bfloat16 g_wvh[4 * KC_N * B_IMG],  g_wvl[4 * KC_N * B_IMG];
__device__ __nv_bfloat16 g_woh[32 * KC_N * B_IMG], g_wol[32 * KC_N * B_IMG];
// attention K images per (kvh, kt): 64 x 136 bf16 ; V-transposed: 128 x 72 bf16
__device__ __nv_bfloat16 g_kph[4 * 32 * 64 * 136], g_kpl[4 * 32 * 64 * 136];
__device__ __nv_bfloat16 g_vph[4 * 32 * 128 * 72], g_vpl[4 * 32 * 128 * 72];

// ===========================================================================
// helpers
// ===========================================================================
__device__ __forceinline__ uint32_t smem_u32(const void* p) {
    return (uint32_t)__cvta_generic_to_shared(p);
}
#define MBAR_INIT(addr, cnt) \
    asm volatile("mbarrier.init.shared.b64 [%0], %1;" :: "r"(addr), "r"(cnt) : "memory")
#define MBAR_EXPECT_TX(addr, tx) \
    asm volatile("mbarrier.arrive.expect_tx.shared.b64 _, [%0], %1;" :: "r"(addr), "r"(tx) : "memory")
#define MBAR_WAIT(addr, par) do {                                              \
    uint32_t _m = (uint32_t)(addr), _p = (uint32_t)(par), _d;                  \
    asm volatile("{\n\t.reg .pred p;\n\t"                                      \
        "mbarrier.try_wait.parity.acquire.cta.shared::cta.b64 p, [%1], %2;\n\t"\
        "selp.b32 %0, 1, 0, p;\n\t}" : "=r"(_d) : "r"(_m), "r"(_p) : "memory");\
    if (!_d) {                                                                 \
        asm volatile("{\n\t.reg .pred P1;\n\t"                                 \
            "WL_%=:\n\t"                                                       \
            "mbarrier.try_wait.parity.acquire.cta.shared::cta.b64 P1, [%0], %1, 0x989680;\n\t" \
            "@P1 bra.uni WD_%=;\n\t"                                           \
            "bra.uni WL_%=;\n\t"                                               \
            "WD_%=:\n\t}" :: "r"(_m), "r"(_p) : "memory");                     \
    }                                                                          \
} while (0)

__device__ __forceinline__ void bulk_g2s(uint32_t dst, const void* src,
                                         uint32_t bytes, uint32_t mbar) {
    asm volatile(
        "cp.async.bulk.shared::cta.global.mbarrier::complete_tx::bytes [%0], [%1], %2, [%3];"
        :: "r"(dst), "l"(src), "r"(bytes), "r"(mbar) : "memory");
}

__device__ __forceinline__ void split2pack(float x, float y,
                                           uint32_t& hi, uint32_t& lo) {
    union { __nv_bfloat162 b2; uint32_t u; } H, L;
    __nv_bfloat16 hx = __float2bfloat16(x);
    __nv_bfloat16 hy = __float2bfloat16(y);
    H.b2.x = hx; H.b2.y = hy;
    L.b2.x = __float2bfloat16(x - __bfloat162float(hx));
    L.b2.y = __float2bfloat16(y - __bfloat162float(hy));
    hi = H.u; lo = L.u;
}

__device__ __forceinline__ void split_store4(__nv_bfloat16* ph, __nv_bfloat16* pl,
                                             float4 v) {
    union { __nv_bfloat16 b[4]; uint2 u; } H, L;
    H.b[0] = __float2bfloat16(v.x);
    H.b[1] = __float2bfloat16(v.y);
    H.b[2] = __float2bfloat16(v.z);
    H.b[3] = __float2bfloat16(v.w);
    L.b[0] = __float2bfloat16(v.x - __bfloat162float(H.b[0]));
    L.b[1] = __float2bfloat16(v.y - __bfloat162float(H.b[1]));
    L.b[2] = __float2bfloat16(v.z - __bfloat162float(H.b[2]));
    L.b[3] = __float2bfloat16(v.w - __bfloat162float(H.b[3]));
    *(uint2*)ph = H.u;
    *(uint2*)pl = L.u;
}

// ===========================================================================
// Prep kernels: pack + split into smem-image layouts
// ===========================================================================
// x[2048][4096] fp32 -> padded A-images
__global__ __launch_bounds__(256) void pack_a_split(const float4* __restrict__ x,
                                                    __nv_bfloat16* __restrict__ hi,
                                                    __nv_bfloat16* __restrict__ lo,
                                                    int n4) {
    int i = blockIdx.x * 256 + threadIdx.x;
    if (i >= n4) return;
    float4 v = x[i];
    int e = i * 4;
    int m = e >> 12, k = e & 4095;
    size_t out = ((size_t)((m >> 7) * KC_N + (k >> 5)) * 128 + (m & 127)) * 40 + (k & 31);
    split_store4(hi + out, lo + out, v);
}

// w[K=4096][N] fp32 -> padded B-images  (nb = log2 N)
__global__ __launch_bounds__(256) void pack_b_split(const float4* __restrict__ w,
                                                    __nv_bfloat16* __restrict__ hi,
                                                    __nv_bfloat16* __restrict__ lo,
                                                    int nb, int n4) {
    int i = blockIdx.x * 256 + threadIdx.x;
    if (i >= n4) return;
    float4 v = w[i];
    int e = i * 4;
    int k = e >> nb, n = e & ((1 << nb) - 1);
    size_t out = ((size_t)((n >> 7) * KC_N + (k >> 5)) * 32 + (k & 31)) * 136 + (n & 127);
    split_store4(hi + out, lo + out, v);
}

// ===========================================================================
// Bulk-fed split-bf16 wmma GEMM. 128x128 tile, BK=32, 256 threads, 2 stages.
// ===========================================================================
#define STAGE_B 37888   // bytes: Ah 10240 | Al 10240 | Bh 8704 | Bl 8704
#define GEMM_SMEM (2 * STAGE_B)

__device__ void gemm_core_bulk(const __nv_bfloat16* __restrict__ Ahp,
                               const __nv_bfloat16* __restrict__ Alp,
                               const __nv_bfloat16* __restrict__ Bhp,
                               const __nv_bfloat16* __restrict__ Blp,
                               float* __restrict__ C, int Ntot, int bx, int by,
                               char* sm) {
    __shared__ uint64_t mbv[2];
    const int tid = threadIdx.x;
    const int warp = tid >> 5, wm = warp >> 1, wn = warp & 1;
    const uint32_t sb = smem_u32(sm);
    const uint32_t mb = smem_u32(mbv);

    if (tid == 0) { MBAR_INIT(mb, 1); MBAR_INIT(mb + 8, 1); }
    __syncthreads();

    auto issue = [&](int t) {
        const int s = t & 1;
        const uint32_t bar = mb + 8 * s;
        const uint32_t d = sb + s * STAGE_B;
        MBAR_EXPECT_TX(bar, STAGE_B);
        const size_t aoff = (size_t)(by * KC_N + t) * A_IMG;
        const size_t boff = (size_t)(bx * KC_N + t) * B_IMG;
        bulk_g2s(d,         Ahp + aoff, 10240, bar);
        bulk_g2s(d + 10240, Alp + aoff, 10240, bar);
        bulk_g2s(d + 20480, Bhp + boff, 8704,  bar);
        bulk_g2s(d + 29184, Blp + boff, 8704,  bar);
    };

    wmma::fragment<wmma::accumulator, 16, 16, 16, float> acc[2][4];
#pragma unroll
    for (int i = 0; i < 2; i++)
#pragma unroll
        for (int j = 0; j < 4; j++) wmma::fill_fragment(acc[i][j], 0.0f);

    if (tid == 0) { issue(0); issue(1); }

    for (int t = 0; t < KC_N; t++) {
        const int s = t & 1;
        MBAR_WAIT(mb + 8 * s, (t >> 1) & 1);

        __nv_bfloat16* p   = (__nv_bfloat16*)(sm + s * STAGE_B);
        __nv_bfloat16* pAh = p;
        __nv_bfloat16* pAl = p + 5120;
        __nv_bfloat16* pBh = p + 10240;
        __nv_bfloat16* pBl = p + 14592;

#pragma unroll
        for (int kt = 0; kt < 2; kt++) {
            wmma::fragment<wmma::matrix_a, 16, 16, 16, __nv_bfloat16, wmma::row_major> ah[2], al[2];
            wmma::fragment<wmma::matrix_b, 16, 16, 16, __nv_bfloat16, wmma::row_major> bh[4], bl[4];
#pragma unroll
            for (int i = 0; i < 2; i++) {
                wmma::load_matrix_sync(ah[i], pAh + (wm * 32 + i * 16) * 40 + kt * 16, 40);
                wmma::load_matrix_sync(al[i], pAl + (wm * 32 + i * 16) * 40 + kt * 16, 40);
            }
#pragma unroll
            for (int j = 0; j < 4; j++) {
                wmma::load_matrix_sync(bh[j], pBh + kt * 16 * 136 + wn * 64 + j * 16, 136);
                wmma::load_matrix_sync(bl[j], pBl + kt * 16 * 136 + wn * 64 + j * 16, 136);
            }
#pragma unroll
            for (int i = 0; i < 2; i++)
#pragma unroll
                for (int j = 0; j < 4; j++) {
                    wmma::mma_sync(acc[i][j], ah[i], bh[j], acc[i][j]);
                    wmma::mma_sync(acc[i][j], ah[i], bl[j], acc[i][j]);
                    wmma::mma_sync(acc[i][j], al[i], bh[j], acc[i][j]);
                }
        }
        __syncthreads();
        if (tid == 0 && t + 2 < KC_N) issue(t + 2);
    }

    const size_t arow0 = (size_t)by * 128;
    const size_t bcol0 = (size_t)bx * 128;
#pragma unroll
    for (int i = 0; i < 2; i++)
#pragma unroll
        for (int j = 0; j < 4; j++)
            wmma::store_matrix_sync(
                &C[(arow0 + wm * 32 + i * 16) * Ntot + bcol0 + wn * 64 + j * 16],
                acc[i][j], Ntot, wmma::mem_row_major);
}

__global__ __launch_bounds__(256, 2) void gemm_qkv_kernel(
    const __nv_bfloat16* __restrict__ xh, const __nv_bfloat16* __restrict__ xl,
    const __nv_bfloat16* __restrict__ wqh, const __nv_bfloat16* __restrict__ wql,
    const __nv_bfloat16* __restrict__ wkh, const __nv_bfloat16* __restrict__ wkl,
    const __nv_bfloat16* __restrict__ wvh, const __nv_bfloat16* __restrict__ wvl,
    float* __restrict__ q, float* __restrict__ k, float* __restrict__ v) {
    extern __shared__ char sm[];
    const int bx = blockIdx.x;
    if (bx < 32)
        gemm_core_bulk(xh, xl, wqh, wql, q, NH * HD, bx, blockIdx.y, sm);
    else if (bx < 36)
        gemm_core_bulk(xh, xl, wkh, wkl, k, NKV * HD, bx - 32, blockIdx.y, sm);
    else
        gemm_core_bulk(xh, xl, wvh, wvl, v, NKV * HD, bx - 36, blockIdx.y, sm);
}

__global__ __launch_bounds__(256, 2) void gemm_wo_kernel(
    const __nv_bfloat16* __restrict__ Ah, const __nv_bfloat16* __restrict__ Al,
    const __nv_bfloat16* __restrict__ Bh, const __nv_bfloat16* __restrict__ Bl,
    float* __restrict__ C) {
    extern __shared__ char sm[];
    gemm_core_bulk(Ah, Al, Bh, Bl, C, DMODEL, blockIdx.x, blockIdx.y, sm);
}

// ===========================================================================
// YaRN RoPE helpers
// ===========================================================================
__device__ __forceinline__ void yarn_cs(int s, int j, float& c, float& sn) {
    const float expo = (float)(2 * j) / 128.0f;
    float invf = 1.0f / powf(10000.0f, expo);
    const float wl = 6.283185307179586f / invf;
    const float r = 163840.0f / wl;
    float gamma = (r - 1.0f) / 31.0f;
    gamma = fminf(fmaxf(gamma, 0.0f), 1.0f);
    invf = invf * ((1.0f - gamma) / 80.0f + gamma);
    const float ang = ((float)s * invf) / 1.19925088f;
    c = cosf(ang);
    sn = sinf(ang);
}

// RoPE in place on q (fp32, [S][NH*HD])
__global__ __launch_bounds__(64) void rope_kernel(float* __restrict__ x, int nheads) {
    const int s = blockIdx.x, h = blockIdx.y, j = threadIdx.x;
    float c, sn;
    yarn_cs(s, j, c, sn);
    float* base = x + ((size_t)s * nheads + h) * HD;
    const float x1 = base[j];
    const float x2 = base[j + 64];
    base[j]      = x1 * c - x2 * sn;
    base[j + 64] = x2 * c + x1 * sn;
}

// RoPE k fp32 -> split bf16 packed K-images [kvh][kt][64][136]
__global__ __launch_bounds__(64) void rope_k_pack(const float* __restrict__ kf,
                                                  __nv_bfloat16* __restrict__ kh,
                                                  __nv_bfloat16* __restrict__ kl) {
    const int s = blockIdx.x, kvh = blockIdx.y, j = threadIdx.x;
    float c, sn;
    yarn_cs(s, j, c, sn);
    const float* base = kf + ((size_t)s * NKV + kvh) * HD;
    const float x1 = base[j];
    const float x2 = base[j + 64];
    const float r1 = x1 * c - x2 * sn;
    const float r2 = x2 * c + x1 * sn;
    const size_t ob = ((size_t)(kvh * 32 + (s >> 6)) * 64 + (s & 63)) * 136;
    __nv_bfloat16 h1 = __float2bfloat16(r1);
    __nv_bfloat16 h2 = __float2bfloat16(r2);
    kh[ob + j]      = h1;
    kh[ob + j + 64] = h2;
    kl[ob + j]      = __float2bfloat16(r1 - __bfloat162float(h1));
    kl[ob + j + 64] = __float2bfloat16(r2 - __bfloat162float(h2));
}

// v fp32 [S][512] -> transposed split packed V-images [kvh][kt][128][72]
__global__ __launch_bounds__(256) void pack_v(const float* __restrict__ v,
                                              __nv_bfloat16* __restrict__ vh,
                                              __nv_bfloat16* __restrict__ vl) {
    __shared__ float tile[64][129];
    const int kt = blockIdx.x & 31, kvh = blockIdx.x >> 5;
    const int tid = threadIdx.x;
    const int s0 = kt * 64;
    for (int idx = tid; idx < 64 * 32; idx += 256) {
        int sl = idx >> 5, d4 = (idx & 31) << 2;
        float4 val = *(const float4*)(v + ((size_t)(s0 + sl) * NKV + kvh) * HD + d4);
        tile[sl][d4]     = val.x;
        tile[sl][d4 + 1] = val.y;
        tile[sl][d4 + 2] = val.z;
        tile[sl][d4 + 3] = val.w;
    }
    __syncthreads();
    const size_t ob = (size_t)(kvh * 32 + kt) * 128 * 72;
    for (int idx = tid; idx < 128 * 64; idx += 256) {
        int d = idx >> 6, c = idx & 63;
        float x = tile[c][d];
        __nv_bfloat16 h = __float2bfloat16(x);
        vh[ob + (size_t)d * 72 + c] = h;
        vl[ob + (size_t)d * 72 + c] = __float2bfloat16(x - __bfloat162float(h));
    }
}

// ===========================================================================
// Bulk-fed causal GQA flash attention (mma.m16n8k16, split bf16).
// ===========================================================================
#define QTI 128
#define KTI 64
#define QP  136
#define VP  72
#define KV_B 71680   // bytes: Kh 17408 | Kl 17408 | Vth 18432 | Vtl 18432
#define ATTN_SMEM (2 * KV_B)

__device__ __forceinline__ void mma16816(float* c, const uint32_t* a,
                                         uint32_t b0, uint32_t b1) {
    asm volatile(
        "mma.sync.aligned.m16n8k16.row.col.f32.bf16.bf16.f32 "
        "{%0,%1,%2,%3}, {%4,%5,%6,%7}, {%8,%9}, {%0,%1,%2,%3};\n"
        : "+f"(c[0]), "+f"(c[1]), "+f"(c[2]), "+f"(c[3])
        : "r"(a[0]), "r"(a[1]), "r"(a[2]), "r"(a[3]), "r"(b0), "r"(b1));
}

__global__ __launch_bounds__(256) void attn_mma(const float* __restrict__ Qg,
                                                const __nv_bfloat16* __restrict__ kph,
                                                const __nv_bfloat16* __restrict__ kpl,
                                                const __nv_bfloat16* __restrict__ vph,
                                                const __nv_bfloat16* __restrict__ vpl,
                                                __nv_bfloat16* __restrict__ Ohg,
                                                __nv_bfloat16* __restrict__ Olg) {
    extern __shared__ char smA[];
    __shared__ uint64_t mbv[2];

    const int qt   = gridDim.x - 1 - blockIdx.x;   // big tiles first
    const int h    = blockIdx.y;
    const int kvh  = h >> 3;
    const int tid  = threadIdx.x;
    const int warp = tid >> 5;
    const int lane = tid & 31;
    const int lg   = lane >> 2;
    const int lc   = lane & 3;
    const int q0   = qt * QTI;
    const int rloc = warp * 16 + lg;
    const float scale = 0.08838834764831845f;
    const uint32_t sb = smem_u32(smA);
    const uint32_t mb = smem_u32(mbv);
    const int nkt = 2 * qt + 2;

    if (tid == 0) { MBAR_INIT(mb, 1); MBAR_INIT(mb + 8, 1); }

    // ---- Q tile split into stage-1 area (freed before kt=1 fill) ----
    {
        __nv_bfloat16* Qh = (__nv_bfloat16*)(smA + KV_B);
        __nv_bfloat16* Ql = Qh + QTI * QP;
        for (int i = tid; i < QTI * 32; i += 256) {
            int r = i >> 5, dc = (i & 31) << 2;
            float4 v = *(const float4*)(Qg + ((size_t)(q0 + r) * NH + h) * HD + dc);
            v.x *= scale; v.y *= scale; v.z *= scale; v.w *= scale;
            split_store4(Qh + r * QP + dc, Ql + r * QP + dc, v);
        }
    }
    __syncthreads();

    uint32_t qah[8][4], qal[8][4];
    {
        const __nv_bfloat16* Qh = (const __nv_bfloat16*)(smA + KV_B);
        const __nv_bfloat16* Ql = Qh + QTI * QP;
#pragma unroll
        for (int dk = 0; dk < 8; dk++) {
            const int cb = dk * 16 + lc * 2;
            qah[dk][0] = *(const uint32_t*)&Qh[(rloc)     * QP + cb];
            qah[dk][1] = *(const uint32_t*)&Qh[(rloc + 8) * QP + cb];
            qah[dk][2] = *(const uint32_t*)&Qh[(rloc)     * QP + cb + 8];
            qah[dk][3] = *(const uint32_t*)&Qh[(rloc + 8) * QP + cb + 8];
            qal[dk][0] = *(const uint32_t*)&Ql[(rloc)     * QP + cb];
            qal[dk][1] = *(const uint32_t*)&Ql[(rloc + 8) * QP + cb];
            qal[dk][2] = *(const uint32_t*)&Ql[(rloc)     * QP + cb + 8];
            qal[dk][3] = *(const uint32_t*)&Ql[(rloc + 8) * QP + cb + 8];
        }
    }
    __syncthreads();   // Q reads done: stage-1 space free

    auto issue = [&](int kt) {
        const int s = kt & 1;
        const uint32_t bar = mb + 8 * s;
        const uint32_t d = sb + s * KV_B;
        MBAR_EXPECT_TX(bar, KV_B);
        const size_t koff = (size_t)(kvh * 32 + kt) * 64 * 136;
        const size_t voff = (size_t)(kvh * 32 + kt) * 128 * 72;
        bulk_g2s(d,         kph + koff, 17408, bar);
        bulk_g2s(d + 17408, kpl + koff, 17408, bar);
        bulk_g2s(d + 34816, vph + voff, 18432, bar);
        bulk_g2s(d + 53248, vpl + voff, 18432, bar);
    };
    if (tid == 0) { issue(0); issue(1); }

    float oacc[16][4];
#pragma unroll
    for (int n = 0; n < 16; n++)
#pragma unroll
        for (int i = 0; i < 4; i++) oacc[n][i] = 0.0f;
    float m0 = -1e30f, m1 = -1e30f, l0 = 0.0f, l1 = 0.0f;

    for (int kt = 0; kt < nkt; kt++) {
        const int s = kt & 1;
        MBAR_WAIT(mb + 8 * s, (kt >> 1) & 1);
        const __nv_bfloat16* Kh  = (const __nv_bfloat16*)(smA + s * KV_B);
        const __nv_bfloat16* Kl  = Kh + 8704;
        const __nv_bfloat16* Vth = (const __nv_bfloat16*)(smA + s * KV_B + 34816);
        const __nv_bfloat16* Vtl = Vth + 9216;
        const int k0 = kt * KTI;

        float sc[8][4];
#pragma unroll
        for (int j = 0; j < 8; j++)
#pragma unroll
            for (int i = 0; i < 4; i++) sc[j][i] = 0.0f;

#pragma unroll
        for (int dk = 0; dk < 8; dk++) {
            const int cb = dk * 16 + lc * 2;
#pragma unroll
            for (int j = 0; j < 8; j++) {
                const int krow = j * 8 + lg;
                uint32_t bh0 = *(const uint32_t*)&Kh[krow * QP + cb];
                uint32_t bh1 = *(const uint32_t*)&Kh[krow * QP + cb + 8];
                uint32_t bl0 = *(const uint32_t*)&Kl[krow * QP + cb];
                uint32_t bl1 = *(const uint32_t*)&Kl[krow * QP + cb + 8];
                mma16816(sc[j], qah[dk], bh0, bh1);
                mma16816(sc[j], qah[dk], bl0, bl1);
                mma16816(sc[j], qal[dk], bh0, bh1);
            }
        }

        const bool dm = (kt >= 2 * qt);
        if (dm) {
#pragma unroll
            for (int j = 0; j < 8; j++) {
                const int keyb = k0 + j * 8 + lc * 2;
#pragma unroll
                for (int i = 0; i < 4; i++) {
                    const int key = keyb + (i & 1);
                    const int qr  = q0 + rloc + ((i >> 1) << 3);
                    if (key > qr) sc[j][i] = -1e30f;
                }
            }
        }

        float mx0 = -1e30f, mx1 = -1e30f;
#pragma unroll
        for (int j = 0; j < 8; j++) {
            mx0 = fmaxf(mx0, fmaxf(sc[j][0], sc[j][1]));
            mx1 = fmaxf(mx1, fmaxf(sc[j][2], sc[j][3]));
        }
        mx0 = fmaxf(mx0, __shfl_xor_sync(0xffffffffu, mx0, 1));
        mx0 = fmaxf(mx0, __shfl_xor_sync(0xffffffffu, mx0, 2));
        mx1 = fmaxf(mx1, __shfl_xor_sync(0xffffffffu, mx1, 1));
        mx1 = fmaxf(mx1, __shfl_xor_sync(0xffffffffu, mx1, 2));

        const float mn0 = fmaxf(m0, mx0), mn1 = fmaxf(m1, mx1);
        const float a0 = __expf(m0 - mn0), a1 = __expf(m1 - mn1);
        m0 = mn0; m1 = mn1;
        l0 *= a0; l1 *= a1;
#pragma unroll
        for (int n = 0; n < 16; n++) {
            oacc[n][0] *= a0; oacc[n][1] *= a0;
            oacc[n][2] *= a1; oacc[n][3] *= a1;
        }

        float rs0 = 0.0f, rs1 = 0.0f;
#pragma unroll
        for (int j = 0; j < 8; j++) {
            sc[j][0] = __expf(sc[j][0] - mn0); rs0 += sc[j][0];
            sc[j][1] = __expf(sc[j][1] - mn0); rs0 += sc[j][1];
            sc[j][2] = __expf(sc[j][2] - mn1); rs1 += sc[j][2];
            sc[j][3] = __expf(sc[j][3] - mn1); rs1 += sc[j][3];
        }
        rs0 += __shfl_xor_sync(0xffffffffu, rs0, 1);
        rs0 += __shfl_xor_sync(0xffffffffu, rs0, 2);
        rs1 += __shfl_xor_sync(0xffffffffu, rs1, 1);
        rs1 += __shfl_xor_sync(0xffffffffu, rs1, 2);
        l0 += rs0; l1 += rs1;

        uint32_t pah[4][4], pal[4][4];
#pragma unroll
        for (int k4 = 0; k4 < 4; k4++) {
            const int j0 = 2 * k4, j1 = 2 * k4 + 1;
            split2pack(sc[j0][0], sc[j0][1], pah[k4][0], pal[k4][0]);
            split2pack(sc[j0][2], sc[j0][3], pah[k4][1], pal[k4][1]);
            split2pack(sc[j1][0], sc[j1][1], pah[k4][2], pal[k4][2]);
            split2pack(sc[j1][2], sc[j1][3], pah[k4][3], pal[k4][3]);
        }

#pragma unroll
        for (int k4 = 0; k4 < 4; k4++) {
            const int kb = k4 * 16 + lc * 2;
#pragma unroll
            for (int n = 0; n < 16; n++) {
                const int drow = n * 8 + lg;
                uint32_t bh0 = *(const uint32_t*)&Vth[drow * VP + kb];
                uint32_t bh1 = *(const uint32_t*)&Vth[drow * VP + kb + 8];
                uint32_t bl0 = *(const uint32_t*)&Vtl[drow * VP + kb];
                uint32_t bl1 = *(const uint32_t*)&Vtl[drow * VP + kb + 8];
                mma16816(oacc[n], pah[k4], bh0, bh1);
                mma16816(oacc[n], pah[k4], bl0, bl1);
                mma16816(oacc[n], pal[k4], bh0, bh1);
            }
        }

        __syncthreads();
        if (tid == 0 && kt + 2 < nkt) issue(kt + 2);
    }

    // ---- epilogue: normalize, split, store into packed wo A-images ----
    const float i0 = 1.0f / l0, i1 = 1.0f / l1;
#pragma unroll
    for (int n = 0; n < 16; n++) {
        const int d = n * 8 + lc * 2;
        const int kc = h * 4 + (d >> 5);
        const int col = d & 31;
        uint32_t h0, lo0, h1, lo1;
        split2pack(oacc[n][0] * i0, oacc[n][1] * i0, h0, lo0);
        split2pack(oacc[n][2] * i1, oacc[n][3] * i1, h1, lo1);
        const size_t off0 = ((size_t)(qt * KC_N + kc) * 128 + rloc)     * 40 + col;
        const size_t off1 = ((size_t)(qt * KC_N + kc) * 128 + rloc + 8) * 40 + col;
        *(uint32_t*)(Ohg + off0) = h0;
        *(uint32_t*)(Olg + off0) = lo0;
        *(uint32_t*)(Ohg + off1) = h1;
        *(uint32_t*)(Olg + off1) = lo1;
    }
}

// ===========================================================================
// Launch
// ===========================================================================
extern "C" void kernel_launch(void* const* d_in, const int* in_sizes, int n_in,
                              void* d_out, int out_size) {
    const float* x  = (const float*)d_in[0];
    const float* wq = (const float*)d_in[1];
    const float* wk = (const float*)d_in[2];
    const float* wv = (const float*)d_in[3];
    const float* wo = (const float*)d_in[4];
    float* out = (float*)d_out;

    const int S = in_sizes[0] / DMODEL;   // 2048

    float *q, *k, *v;
    cudaGetSymbolAddress((void**)&q, g_q);
    cudaGetSymbolAddress((void**)&k, g_k);
    cudaGetSymbolAddress((void**)&v, g_v);

    __nv_bfloat16 *xh, *xl, *wqh, *wql, *wkh, *wkl, *wvh, *wvl, *woh, *wol, *oh, *ol;
    __nv_bfloat16 *kph, *kpl, *vph, *vpl;
    cudaGetSymbolAddress((void**)&xh, g_xh);   cudaGetSymbolAddress((void**)&xl, g_xl);
    cudaGetSymbolAddress((void**)&wqh, g_wqh); cudaGetSymbolAddress((void**)&wql, g_wql);
    cudaGetSymbolAddress((void**)&wkh, g_wkh); cudaGetSymbolAddress((void**)&wkl, g_wkl);
    cudaGetSymbolAddress((void**)&wvh, g_wvh); cudaGetSymbolAddress((void**)&wvl, g_wvl);
    cudaGetSymbolAddress((void**)&woh, g_woh); cudaGetSymbolAddress((void**)&wol, g_wol);
    cudaGetSymbolAddress((void**)&oh, g_oh);   cudaGetSymbolAddress((void**)&ol, g_ol);
    cudaGetSymbolAddress((void**)&kph, g_kph); cudaGetSymbolAddress((void**)&kpl, g_kpl);
    cudaGetSymbolAddress((void**)&vph, g_vph); cudaGetSymbolAddress((void**)&vpl, g_vpl);

    // ---- pack + split ----
    {
        int n4 = (S * DMODEL) / 4;
        pack_a_split<<<(n4 + 255) / 256, 256>>>((const float4*)x, xh, xl, n4);
    }
    {
        int n4 = (DMODEL * NH * HD) / 4;
        pack_b_split<<<(n4 + 255) / 256, 256>>>((const float4*)wq, wqh, wql, 12, n4);
        pack_b_split<<<(n4 + 255) / 256, 256>>>((const float4*)wo, woh, wol, 12, n4);
    }
    {
        int n4 = (DMODEL * NKV * HD) / 4;
        pack_b_split<<<(n4 + 255) / 256, 256>>>((const float4*)wk, wkh, wkl, 9, n4);
        pack_b_split<<<(n4 + 255) / 256, 256>>>((const float4*)wv, wvh, wvl, 9, n4);
    }

    cudaFuncSetAttribute(gemm_qkv_kernel, cudaFuncAttributeMaxDynamicSharedMemorySize, GEMM_SMEM);
    cudaFuncSetAttribute(gemm_wo_kernel,  cudaFuncAttributeMaxDynamicSharedMemorySize, GEMM_SMEM);

    // ---- QKV projections ----
    gemm_qkv_kernel<<<dim3(40, S / 128), 256, GEMM_SMEM>>>(
        xh, xl, wqh, wql, wkh, wkl, wvh, wvl, q, k, v);

    // ---- RoPE + attention-operand packing ----
    rope_kernel<<<dim3(S, NH), 64>>>(q, NH);
    rope_k_pack<<<dim3(S, NKV), 64>>>(k, kph, kpl);
    pack_v<<<128, 256>>>(v, vph, vpl);

    // ---- flash attention -> packed wo A-images ----
    cudaFuncSetAttribute(attn_mma, cudaFuncAttributeMaxDynamicSharedMemorySize, ATTN_SMEM);
    attn_mma<<<dim3(S / QTI, NH), 256, ATTN_SMEM>>>(q, kph, kpl, vph, vpl, oh, ol);

    // ---- output projection ----
    gemm_wo_kernel<<<dim3(DMODEL / 128, S / 128), 256, GEMM_SMEM>>>(oh, ol, woh, wol, out);
}

// round 12
// speedup vs baseline: 7.0465x; 1.1857x over previous
#include <cuda_runtime.h>
#include <cuda_bf16.h>
#include <cuda_fp16.h>
#include <mma.h>
#include <math.h>
#include <stdint.h>

using namespace nvcuda;

#define DMODEL 4096
#define NH 32
#define NKV 4
#define HD 128
#define S_MAX 2048

// fp32 activations (GEMM outputs)
__device__ float g_q[S_MAX * NH * HD];
__device__ float g_k[S_MAX * NKV * HD];
__device__ float g_v[S_MAX * NKV * HD];

// ---- packed smem-image layouts ----
// GEMM A-image per (by, kc): 128 rows x 40 cols (32 data + 8 pad), 2B elems
// GEMM B-image per (bx, kc): 32 rows x 136 cols (128 data + 8 pad), 2B elems
#define A_IMG 5120              // elems (128*40)
#define B_IMG 4352              // elems (32*136)
#define KC_N 128                // K chunks (4096/32)

// bf16 split operands (QKV path, unchanged from R10)
__device__ __nv_bfloat16 g_xh[16 * KC_N * A_IMG], g_xl[16 * KC_N * A_IMG];
__device__ __nv_bfloat16 g_wqh[32 * KC_N * B_IMG], g_wql[32 * KC_N * B_IMG];
__device__ __nv_bfloat16 g_wkh[4 * KC_N * B_IMG],  g_wkl[4 * KC_N * B_IMG];
__device__ __nv_bfloat16 g_wvh[4 * KC_N * B_IMG],  g_wvl[4 * KC_N * B_IMG];
// fp16 wo path: attention output split fp16, wo single fp16
__device__ __half g_oh[16 * KC_N * A_IMG], g_ol[16 * KC_N * A_IMG];
__device__ __half g_wo1[32 * KC_N * B_IMG];
// attention K images per (kvh, kt): 64 x 136 bf16 ; V-transposed: 128 x 72 bf16
__device__ __nv_bfloat16 g_kph[4 * 32 * 64 * 136], g_kpl[4 * 32 * 64 * 136];
__device__ __nv_bfloat16 g_vph[4 * 32 * 128 * 72], g_vpl[4 * 32 * 128 * 72];

// ===========================================================================
// helpers
// ===========================================================================
__device__ __forceinline__ uint32_t smem_u32(const void* p) {
    return (uint32_t)__cvta_generic_to_shared(p);
}
#define MBAR_INIT(addr, cnt) \
    asm volatile("mbarrier.init.shared.b64 [%0], %1;" :: "r"(addr), "r"(cnt) : "memory")
#define MBAR_EXPECT_TX(addr, tx) \
    asm volatile("mbarrier.arrive.expect_tx.shared.b64 _, [%0], %1;" :: "r"(addr), "r"(tx) : "memory")
#define MBAR_WAIT(addr, par) do {                                              \
    uint32_t _m = (uint32_t)(addr), _p = (uint32_t)(par), _d;                  \
    asm volatile("{\n\t.reg .pred p;\n\t"                                      \
        "mbarrier.try_wait.parity.acquire.cta.shared::cta.b64 p, [%1], %2;\n\t"\
        "selp.b32 %0, 1, 0, p;\n\t}" : "=r"(_d) : "r"(_m), "r"(_p) : "memory");\
    if (!_d) {                                                                 \
        asm volatile("{\n\t.reg .pred P1;\n\t"                                 \
            "WL_%=:\n\t"                                                       \
            "mbarrier.try_wait.parity.acquire.cta.shared::cta.b64 P1, [%0], %1, 0x989680;\n\t" \
            "@P1 bra.uni WD_%=;\n\t"                                           \
            "bra.uni WL_%=;\n\t"                                               \
            "WD_%=:\n\t}" :: "r"(_m), "r"(_p) : "memory");                     \
    }                                                                          \
} while (0)

__device__ __forceinline__ void bulk_g2s(uint32_t dst, const void* src,
                                         uint32_t bytes, uint32_t mbar) {
    asm volatile(
        "cp.async.bulk.shared::cta.global.mbarrier::complete_tx::bytes [%0], [%1], %2, [%3];"
        :: "r"(dst), "l"(src), "r"(bytes), "r"(mbar) : "memory");
}

__device__ __forceinline__ void split2pack(float x, float y,
                                           uint32_t& hi, uint32_t& lo) {
    union { __nv_bfloat162 b2; uint32_t u; } H, L;
    __nv_bfloat16 hx = __float2bfloat16(x);
    __nv_bfloat16 hy = __float2bfloat16(y);
    H.b2.x = hx; H.b2.y = hy;
    L.b2.x = __float2bfloat16(x - __bfloat162float(hx));
    L.b2.y = __float2bfloat16(y - __bfloat162float(hy));
    hi = H.u; lo = L.u;
}

// fp16 split-pack (wo path)
__device__ __forceinline__ void split2pack_h(float x, float y,
                                             uint32_t& hi, uint32_t& lo) {
    union { __half2 h2; uint32_t u; } H, L;
    __half hx = __float2half_rn(x);
    __half hy = __float2half_rn(y);
    H.h2 = __halves2half2(hx, hy);
    L.h2 = __halves2half2(__float2half_rn(x - __half2float(hx)),
                          __float2half_rn(y - __half2float(hy)));
    hi = H.u; lo = L.u;
}

__device__ __forceinline__ void split_store4(__nv_bfloat16* ph, __nv_bfloat16* pl,
                                             float4 v) {
    union { __nv_bfloat16 b[4]; uint2 u; } H, L;
    H.b[0] = __float2bfloat16(v.x);
    H.b[1] = __float2bfloat16(v.y);
    H.b[2] = __float2bfloat16(v.z);
    H.b[3] = __float2bfloat16(v.w);
    L.b[0] = __float2bfloat16(v.x - __bfloat162float(H.b[0]));
    L.b[1] = __float2bfloat16(v.y - __bfloat162float(H.b[1]));
    L.b[2] = __float2bfloat16(v.z - __bfloat162float(H.b[2]));
    L.b[3] = __float2bfloat16(v.w - __bfloat162float(H.b[3]));
    *(uint2*)ph = H.u;
    *(uint2*)pl = L.u;
}

// ===========================================================================
// Prep kernels
// ===========================================================================
// x[2048][4096] fp32 -> padded bf16 A-images
__global__ __launch_bounds__(256) void pack_a_split(const float4* __restrict__ x,
                                                    __nv_bfloat16* __restrict__ hi,
                                                    __nv_bfloat16* __restrict__ lo,
                                                    int n4) {
    int i = blockIdx.x * 256 + threadIdx.x;
    if (i >= n4) return;
    float4 v = x[i];
    int e = i * 4;
    int m = e >> 12, k = e & 4095;
    size_t out = ((size_t)((m >> 7) * KC_N + (k >> 5)) * 128 + (m & 127)) * 40 + (k & 31);
    split_store4(hi + out, lo + out, v);
}

// w[K=4096][N] fp32 -> padded bf16 split B-images  (nb = log2 N)
__global__ __launch_bounds__(256) void pack_b_split(const float4* __restrict__ w,
                                                    __nv_bfloat16* __restrict__ hi,
                                                    __nv_bfloat16* __restrict__ lo,
                                                    int nb, int n4) {
    int i = blockIdx.x * 256 + threadIdx.x;
    if (i >= n4) return;
    float4 v = w[i];
    int e = i * 4;
    int k = e >> nb, n = e & ((1 << nb) - 1);
    size_t out = ((size_t)((n >> 7) * KC_N + (k >> 5)) * 32 + (k & 31)) * 136 + (n & 127);
    split_store4(hi + out, lo + out, v);
}

// wo[4096][4096] fp32 -> padded fp16 SINGLE B-images
__global__ __launch_bounds__(256) void pack_b_f16(const float4* __restrict__ w,
                                                  __half* __restrict__ o,
                                                  int n4) {
    int i = blockIdx.x * 256 + threadIdx.x;
    if (i >= n4) return;
    float4 v = w[i];
    int e = i * 4;
    int k = e >> 12, n = e & 4095;
    size_t out = ((size_t)((n >> 7) * KC_N + (k >> 5)) * 32 + (k & 31)) * 136 + (n & 127);
    union { __half h[4]; uint2 u; } O;
    O.h[0] = __float2half_rn(v.x);
    O.h[1] = __float2half_rn(v.y);
    O.h[2] = __float2half_rn(v.z);
    O.h[3] = __float2half_rn(v.w);
    *(uint2*)(o + out) = O.u;
}

// ===========================================================================
// Bulk-fed split-bf16 wmma GEMM (3-term, QKV path — unchanged from R10).
// ===========================================================================
#define STAGE_B 37888
#define GEMM_SMEM (2 * STAGE_B)

__device__ void gemm_core_bulk(const __nv_bfloat16* __restrict__ Ahp,
                               const __nv_bfloat16* __restrict__ Alp,
                               const __nv_bfloat16* __restrict__ Bhp,
                               const __nv_bfloat16* __restrict__ Blp,
                               float* __restrict__ C, int Ntot, int bx, int by,
                               char* sm) {
    __shared__ uint64_t mbv[2];
    const int tid = threadIdx.x;
    const int warp = tid >> 5, wm = warp >> 1, wn = warp & 1;
    const uint32_t sb = smem_u32(sm);
    const uint32_t mb = smem_u32(mbv);

    if (tid == 0) { MBAR_INIT(mb, 1); MBAR_INIT(mb + 8, 1); }
    __syncthreads();

    auto issue = [&](int t) {
        const int s = t & 1;
        const uint32_t bar = mb + 8 * s;
        const uint32_t d = sb + s * STAGE_B;
        MBAR_EXPECT_TX(bar, STAGE_B);
        const size_t aoff = (size_t)(by * KC_N + t) * A_IMG;
        const size_t boff = (size_t)(bx * KC_N + t) * B_IMG;
        bulk_g2s(d,         Ahp + aoff, 10240, bar);
        bulk_g2s(d + 10240, Alp + aoff, 10240, bar);
        bulk_g2s(d + 20480, Bhp + boff, 8704,  bar);
        bulk_g2s(d + 29184, Blp + boff, 8704,  bar);
    };

    wmma::fragment<wmma::accumulator, 16, 16, 16, float> acc[2][4];
#pragma unroll
    for (int i = 0; i < 2; i++)
#pragma unroll
        for (int j = 0; j < 4; j++) wmma::fill_fragment(acc[i][j], 0.0f);

    if (tid == 0) { issue(0); issue(1); }

    for (int t = 0; t < KC_N; t++) {
        const int s = t & 1;
        MBAR_WAIT(mb + 8 * s, (t >> 1) & 1);

        __nv_bfloat16* p   = (__nv_bfloat16*)(sm + s * STAGE_B);
        __nv_bfloat16* pAh = p;
        __nv_bfloat16* pAl = p + 5120;
        __nv_bfloat16* pBh = p + 10240;
        __nv_bfloat16* pBl = p + 14592;

#pragma unroll
        for (int kt = 0; kt < 2; kt++) {
            wmma::fragment<wmma::matrix_a, 16, 16, 16, __nv_bfloat16, wmma::row_major> ah[2], al[2];
            wmma::fragment<wmma::matrix_b, 16, 16, 16, __nv_bfloat16, wmma::row_major> bh[4], bl[4];
#pragma unroll
            for (int i = 0; i < 2; i++) {
                wmma::load_matrix_sync(ah[i], pAh + (wm * 32 + i * 16) * 40 + kt * 16, 40);
                wmma::load_matrix_sync(al[i], pAl + (wm * 32 + i * 16) * 40 + kt * 16, 40);
            }
#pragma unroll
            for (int j = 0; j < 4; j++) {
                wmma::load_matrix_sync(bh[j], pBh + kt * 16 * 136 + wn * 64 + j * 16, 136);
                wmma::load_matrix_sync(bl[j], pBl + kt * 16 * 136 + wn * 64 + j * 16, 136);
            }
#pragma unroll
            for (int i = 0; i < 2; i++)
#pragma unroll
                for (int j = 0; j < 4; j++) {
                    wmma::mma_sync(acc[i][j], ah[i], bh[j], acc[i][j]);
                    wmma::mma_sync(acc[i][j], ah[i], bl[j], acc[i][j]);
                    wmma::mma_sync(acc[i][j], al[i], bh[j], acc[i][j]);
                }
        }
        __syncthreads();
        if (tid == 0 && t + 2 < KC_N) issue(t + 2);
    }

    const size_t arow0 = (size_t)by * 128;
    const size_t bcol0 = (size_t)bx * 128;
#pragma unroll
    for (int i = 0; i < 2; i++)
#pragma unroll
        for (int j = 0; j < 4; j++)
            wmma::store_matrix_sync(
                &C[(arow0 + wm * 32 + i * 16) * Ntot + bcol0 + wn * 64 + j * 16],
                acc[i][j], Ntot, wmma::mem_row_major);
}

__global__ __launch_bounds__(256, 2) void gemm_qkv_kernel(
    const __nv_bfloat16* __restrict__ xh, const __nv_bfloat16* __restrict__ xl,
    const __nv_bfloat16* __restrict__ wqh, const __nv_bfloat16* __restrict__ wql,
    const __nv_bfloat16* __restrict__ wkh, const __nv_bfloat16* __restrict__ wkl,
    const __nv_bfloat16* __restrict__ wvh, const __nv_bfloat16* __restrict__ wvl,
    float* __restrict__ q, float* __restrict__ k, float* __restrict__ v) {
    extern __shared__ char sm[];
    const int bx = blockIdx.x;
    if (bx < 32)
        gemm_core_bulk(xh, xl, wqh, wql, q, NH * HD, bx, blockIdx.y, sm);
    else if (bx < 36)
        gemm_core_bulk(xh, xl, wkh, wkl, k, NKV * HD, bx - 32, blockIdx.y, sm);
    else
        gemm_core_bulk(xh, xl, wvh, wvl, v, NKV * HD, bx - 36, blockIdx.y, sm);
}

// ===========================================================================
// wo GEMM: fp16 2-term (A split fp16, B single fp16).
// stage: Ah 10240 | Al 10240 | B 8704 = 29184 B
// ===========================================================================
#define STAGE2_B 29184
#define GEMM2_SMEM (2 * STAGE2_B)

__global__ __launch_bounds__(256, 2) void gemm_wo_kernel(
    const __half* __restrict__ Ahp, const __half* __restrict__ Alp,
    const __half* __restrict__ Bp, float* __restrict__ C) {
    extern __shared__ char sm[];
    __shared__ uint64_t mbv[2];
    const int tid = threadIdx.x;
    const int warp = tid >> 5, wm = warp >> 1, wn = warp & 1;
    const int bx = blockIdx.x, by = blockIdx.y;
    const uint32_t sb = smem_u32(sm);
    const uint32_t mb = smem_u32(mbv);

    if (tid == 0) { MBAR_INIT(mb, 1); MBAR_INIT(mb + 8, 1); }
    __syncthreads();

    auto issue = [&](int t) {
        const int s = t & 1;
        const uint32_t bar = mb + 8 * s;
        const uint32_t d = sb + s * STAGE2_B;
        MBAR_EXPECT_TX(bar, STAGE2_B);
        const size_t aoff = (size_t)(by * KC_N + t) * A_IMG;
        const size_t boff = (size_t)(bx * KC_N + t) * B_IMG;
        bulk_g2s(d,         Ahp + aoff, 10240, bar);
        bulk_g2s(d + 10240, Alp + aoff, 10240, bar);
        bulk_g2s(d + 20480, Bp + boff,  8704,  bar);
    };

    wmma::fragment<wmma::accumulator, 16, 16, 16, float> acc[2][4];
#pragma unroll
    for (int i = 0; i < 2; i++)
#pragma unroll
        for (int j = 0; j < 4; j++) wmma::fill_fragment(acc[i][j], 0.0f);

    if (tid == 0) { issue(0); issue(1); }

    for (int t = 0; t < KC_N; t++) {
        const int s = t & 1;
        MBAR_WAIT(mb + 8 * s, (t >> 1) & 1);

        __half* p   = (__half*)(sm + s * STAGE2_B);
        __half* pAh = p;
        __half* pAl = p + 5120;
        __half* pB  = p + 10240;

#pragma unroll
        for (int kt = 0; kt < 2; kt++) {
            wmma::fragment<wmma::matrix_a, 16, 16, 16, __half, wmma::row_major> ah[2], al[2];
            wmma::fragment<wmma::matrix_b, 16, 16, 16, __half, wmma::row_major> b[4];
#pragma unroll
            for (int i = 0; i < 2; i++) {
                wmma::load_matrix_sync(ah[i], pAh + (wm * 32 + i * 16) * 40 + kt * 16, 40);
                wmma::load_matrix_sync(al[i], pAl + (wm * 32 + i * 16) * 40 + kt * 16, 40);
            }
#pragma unroll
            for (int j = 0; j < 4; j++)
                wmma::load_matrix_sync(b[j], pB + kt * 16 * 136 + wn * 64 + j * 16, 136);
#pragma unroll
            for (int i = 0; i < 2; i++)
#pragma unroll
                for (int j = 0; j < 4; j++) {
                    wmma::mma_sync(acc[i][j], ah[i], b[j], acc[i][j]);
                    wmma::mma_sync(acc[i][j], al[i], b[j], acc[i][j]);
                }
        }
        __syncthreads();
        if (tid == 0 && t + 2 < KC_N) issue(t + 2);
    }

    const size_t arow0 = (size_t)by * 128;
    const size_t bcol0 = (size_t)bx * 128;
#pragma unroll
    for (int i = 0; i < 2; i++)
#pragma unroll
        for (int j = 0; j < 4; j++)
            wmma::store_matrix_sync(
                &C[(arow0 + wm * 32 + i * 16) * DMODEL + bcol0 + wn * 64 + j * 16],
                acc[i][j], DMODEL, wmma::mem_row_major);
}

// ===========================================================================
// YaRN RoPE helpers
// ===========================================================================
__device__ __forceinline__ void yarn_cs(int s, int j, float& c, float& sn) {
    const float expo = (float)(2 * j) / 128.0f;
    float invf = 1.0f / powf(10000.0f, expo);
    const float wl = 6.283185307179586f / invf;
    const float r = 163840.0f / wl;
    float gamma = (r - 1.0f) / 31.0f;
    gamma = fminf(fmaxf(gamma, 0.0f), 1.0f);
    invf = invf * ((1.0f - gamma) / 80.0f + gamma);
    const float ang = ((float)s * invf) / 1.19925088f;
    c = cosf(ang);
    sn = sinf(ang);
}

__global__ __launch_bounds__(64) void rope_kernel(float* __restrict__ x, int nheads) {
    const int s = blockIdx.x, h = blockIdx.y, j = threadIdx.x;
    float c, sn;
    yarn_cs(s, j, c, sn);
    float* base = x + ((size_t)s * nheads + h) * HD;
    const float x1 = base[j];
    const float x2 = base[j + 64];
    base[j]      = x1 * c - x2 * sn;
    base[j + 64] = x2 * c + x1 * sn;
}

__global__ __launch_bounds__(64) void rope_k_pack(const float* __restrict__ kf,
                                                  __nv_bfloat16* __restrict__ kh,
                                                  __nv_bfloat16* __restrict__ kl) {
    const int s = blockIdx.x, kvh = blockIdx.y, j = threadIdx.x;
    float c, sn;
    yarn_cs(s, j, c, sn);
    const float* base = kf + ((size_t)s * NKV + kvh) * HD;
    const float x1 = base[j];
    const float x2 = base[j + 64];
    const float r1 = x1 * c - x2 * sn;
    const float r2 = x2 * c + x1 * sn;
    const size_t ob = ((size_t)(kvh * 32 + (s >> 6)) * 64 + (s & 63)) * 136;
    __nv_bfloat16 h1 = __float2bfloat16(r1);
    __nv_bfloat16 h2 = __float2bfloat16(r2);
    kh[ob + j]      = h1;
    kh[ob + j + 64] = h2;
    kl[ob + j]      = __float2bfloat16(r1 - __bfloat162float(h1));
    kl[ob + j + 64] = __float2bfloat16(r2 - __bfloat162float(h2));
}

__global__ __launch_bounds__(256) void pack_v(const float* __restrict__ v,
                                              __nv_bfloat16* __restrict__ vh,
                                              __nv_bfloat16* __restrict__ vl) {
    __shared__ float tile[64][129];
    const int kt = blockIdx.x & 31, kvh = blockIdx.x >> 5;
    const int tid = threadIdx.x;
    const int s0 = kt * 64;
    for (int idx = tid; idx < 64 * 32; idx += 256) {
        int sl = idx >> 5, d4 = (idx & 31) << 2;
        float4 val = *(const float4*)(v + ((size_t)(s0 + sl) * NKV + kvh) * HD + d4);
        tile[sl][d4]     = val.x;
        tile[sl][d4 + 1] = val.y;
        tile[sl][d4 + 2] = val.z;
        tile[sl][d4 + 3] = val.w;
    }
    __syncthreads();
    const size_t ob = (size_t)(kvh * 32 + kt) * 128 * 72;
    for (int idx = tid; idx < 128 * 64; idx += 256) {
        int d = idx >> 6, c = idx & 63;
        float x = tile[c][d];
        __nv_bfloat16 h = __float2bfloat16(x);
        vh[ob + (size_t)d * 72 + c] = h;
        vl[ob + (size_t)d * 72 + c] = __float2bfloat16(x - __bfloat162float(h));
    }
}

// ===========================================================================
// Bulk-fed causal GQA flash attention (mma.m16n8k16, split bf16).
// Epilogue now writes fp16-split wo A-images.
// ===========================================================================
#define QTI 128
#define KTI 64
#define QP  136
#define VP  72
#define KV_B 71680
#define ATTN_SMEM (2 * KV_B)

__device__ __forceinline__ void mma16816(float* c, const uint32_t* a,
                                         uint32_t b0, uint32_t b1) {
    asm volatile(
        "mma.sync.aligned.m16n8k16.row.col.f32.bf16.bf16.f32 "
        "{%0,%1,%2,%3}, {%4,%5,%6,%7}, {%8,%9}, {%0,%1,%2,%3};\n"
        : "+f"(c[0]), "+f"(c[1]), "+f"(c[2]), "+f"(c[3])
        : "r"(a[0]), "r"(a[1]), "r"(a[2]), "r"(a[3]), "r"(b0), "r"(b1));
}

__global__ __launch_bounds__(256) void attn_mma(const float* __restrict__ Qg,
                                                const __nv_bfloat16* __restrict__ kph,
                                                const __nv_bfloat16* __restrict__ kpl,
                                                const __nv_bfloat16* __restrict__ vph,
                                                const __nv_bfloat16* __restrict__ vpl,
                                                __half* __restrict__ Ohg,
                                                __half* __restrict__ Olg) {
    extern __shared__ char smA[];
    __shared__ uint64_t mbv[2];

    const int qt   = gridDim.x - 1 - blockIdx.x;
    const int h    = blockIdx.y;
    const int kvh  = h >> 3;
    const int tid  = threadIdx.x;
    const int warp = tid >> 5;
    const int lane = tid & 31;
    const int lg   = lane >> 2;
    const int lc   = lane & 3;
    const int q0   = qt * QTI;
    const int rloc = warp * 16 + lg;
    const float scale = 0.08838834764831845f;
    const uint32_t sb = smem_u32(smA);
    const uint32_t mb = smem_u32(mbv);
    const int nkt = 2 * qt + 2;

    if (tid == 0) { MBAR_INIT(mb, 1); MBAR_INIT(mb + 8, 1); }

    {
        __nv_bfloat16* Qh = (__nv_bfloat16*)(smA + KV_B);
        __nv_bfloat16* Ql = Qh + QTI * QP;
        for (int i = tid; i < QTI * 32; i += 256) {
            int r = i >> 5, dc = (i & 31) << 2;
            float4 v = *(const float4*)(Qg + ((size_t)(q0 + r) * NH + h) * HD + dc);
            v.x *= scale; v.y *= scale; v.z *= scale; v.w *= scale;
            split_store4(Qh + r * QP + dc, Ql + r * QP + dc, v);
        }
    }
    __syncthreads();

    uint32_t qah[8][4], qal[8][4];
    {
        const __nv_bfloat16* Qh = (const __nv_bfloat16*)(smA + KV_B);
        const __nv_bfloat16* Ql = Qh + QTI * QP;
#pragma unroll
        for (int dk = 0; dk < 8; dk++) {
            const int cb = dk * 16 + lc * 2;
            qah[dk][0] = *(const uint32_t*)&Qh[(rloc)     * QP + cb];
            qah[dk][1] = *(const uint32_t*)&Qh[(rloc + 8) * QP + cb];
            qah[dk][2] = *(const uint32_t*)&Qh[(rloc)     * QP + cb + 8];
            qah[dk][3] = *(const uint32_t*)&Qh[(rloc + 8) * QP + cb + 8];
            qal[dk][0] = *(const uint32_t*)&Ql[(rloc)     * QP + cb];
            qal[dk][1] = *(const uint32_t*)&Ql[(rloc + 8) * QP + cb];
            qal[dk][2] = *(const uint32_t*)&Ql[(rloc)     * QP + cb + 8];
            qal[dk][3] = *(const uint32_t*)&Ql[(rloc + 8) * QP + cb + 8];
        }
    }
    __syncthreads();

    auto issue = [&](int kt) {
        const int s = kt & 1;
        const uint32_t bar = mb + 8 * s;
        const uint32_t d = sb + s * KV_B;
        MBAR_EXPECT_TX(bar, KV_B);
        const size_t koff = (size_t)(kvh * 32 + kt) * 64 * 136;
        const size_t voff = (size_t)(kvh * 32 + kt) * 128 * 72;
        bulk_g2s(d,         kph + koff, 17408, bar);
        bulk_g2s(d + 17408, kpl + koff, 17408, bar);
        bulk_g2s(d + 34816, vph + voff, 18432, bar);
        bulk_g2s(d + 53248, vpl + voff, 18432, bar);
    };
    if (tid == 0) { issue(0); issue(1); }

    float oacc[16][4];
#pragma unroll
    for (int n = 0; n < 16; n++)
#pragma unroll
        for (int i = 0; i < 4; i++) oacc[n][i] = 0.0f;
    float m0 = -1e30f, m1 = -1e30f, l0 = 0.0f, l1 = 0.0f;

    for (int kt = 0; kt < nkt; kt++) {
        const int s = kt & 1;
        MBAR_WAIT(mb + 8 * s, (kt >> 1) & 1);
        const __nv_bfloat16* Kh  = (const __nv_bfloat16*)(smA + s * KV_B);
        const __nv_bfloat16* Kl  = Kh + 8704;
        const __nv_bfloat16* Vth = (const __nv_bfloat16*)(smA + s * KV_B + 34816);
        const __nv_bfloat16* Vtl = Vth + 9216;
        const int k0 = kt * KTI;

        float sc[8][4];
#pragma unroll
        for (int j = 0; j < 8; j++)
#pragma unroll
            for (int i = 0; i < 4; i++) sc[j][i] = 0.0f;

#pragma unroll
        for (int dk = 0; dk < 8; dk++) {
            const int cb = dk * 16 + lc * 2;
#pragma unroll
            for (int j = 0; j < 8; j++) {
                const int krow = j * 8 + lg;
                uint32_t bh0 = *(const uint32_t*)&Kh[krow * QP + cb];
                uint32_t bh1 = *(const uint32_t*)&Kh[krow * QP + cb + 8];
                uint32_t bl0 = *(const uint32_t*)&Kl[krow * QP + cb];
                uint32_t bl1 = *(const uint32_t*)&Kl[krow * QP + cb + 8];
                mma16816(sc[j], qah[dk], bh0, bh1);
                mma16816(sc[j], qah[dk], bl0, bl1);
                mma16816(sc[j], qal[dk], bh0, bh1);
            }
        }

        const bool dm = (kt >= 2 * qt);
        if (dm) {
#pragma unroll
            for (int j = 0; j < 8; j++) {
                const int keyb = k0 + j * 8 + lc * 2;
#pragma unroll
                for (int i = 0; i < 4; i++) {
                    const int key = keyb + (i & 1);
                    const int qr  = q0 + rloc + ((i >> 1) << 3);
                    if (key > qr) sc[j][i] = -1e30f;
                }
            }
        }

        float mx0 = -1e30f, mx1 = -1e30f;
#pragma unroll
        for (int j = 0; j < 8; j++) {
            mx0 = fmaxf(mx0, fmaxf(sc[j][0], sc[j][1]));
            mx1 = fmaxf(mx1, fmaxf(sc[j][2], sc[j][3]));
        }
        mx0 = fmaxf(mx0, __shfl_xor_sync(0xffffffffu, mx0, 1));
        mx0 = fmaxf(mx0, __shfl_xor_sync(0xffffffffu, mx0, 2));
        mx1 = fmaxf(mx1, __shfl_xor_sync(0xffffffffu, mx1, 1));
        mx1 = fmaxf(mx1, __shfl_xor_sync(0xffffffffu, mx1, 2));

        const float mn0 = fmaxf(m0, mx0), mn1 = fmaxf(m1, mx1);
        const float a0 = __expf(m0 - mn0), a1 = __expf(m1 - mn1);
        m0 = mn0; m1 = mn1;
        l0 *= a0; l1 *= a1;
#pragma unroll
        for (int n = 0; n < 16; n++) {
            oacc[n][0] *= a0; oacc[n][1] *= a0;
            oacc[n][2] *= a1; oacc[n][3] *= a1;
        }

        float rs0 = 0.0f, rs1 = 0.0f;
#pragma unroll
        for (int j = 0; j < 8; j++) {
            sc[j][0] = __expf(sc[j][0] - mn0); rs0 += sc[j][0];
            sc[j][1] = __expf(sc[j][1] - mn0); rs0 += sc[j][1];
            sc[j][2] = __expf(sc[j][2] - mn1); rs1 += sc[j][2];
            sc[j][3] = __expf(sc[j][3] - mn1); rs1 += sc[j][3];
        }
        rs0 += __shfl_xor_sync(0xffffffffu, rs0, 1);
        rs0 += __shfl_xor_sync(0xffffffffu, rs0, 2);
        rs1 += __shfl_xor_sync(0xffffffffu, rs1, 1);
        rs1 += __shfl_xor_sync(0xffffffffu, rs1, 2);
        l0 += rs0; l1 += rs1;

        uint32_t pah[4][4], pal[4][4];
#pragma unroll
        for (int k4 = 0; k4 < 4; k4++) {
            const int j0 = 2 * k4, j1 = 2 * k4 + 1;
            split2pack(sc[j0][0], sc[j0][1], pah[k4][0], pal[k4][0]);
            split2pack(sc[j0][2], sc[j0][3], pah[k4][1], pal[k4][1]);
            split2pack(sc[j1][0], sc[j1][1], pah[k4][2], pal[k4][2]);
            split2pack(sc[j1][2], sc[j1][3], pah[k4][3], pal[k4][3]);
        }

#pragma unroll
        for (int k4 = 0; k4 < 4; k4++) {
            const int kb = k4 * 16 + lc * 2;
#pragma unroll
            for (int n = 0; n < 16; n++) {
                const int drow = n * 8 + lg;
                uint32_t bh0 = *(const uint32_t*)&Vth[drow * VP + kb];
                uint32_t bh1 = *(const uint32_t*)&Vth[drow * VP + kb + 8];
                uint32_t bl0 = *(const uint32_t*)&Vtl[drow * VP + kb];
                uint32_t bl1 = *(const uint32_t*)&Vtl[drow * VP + kb + 8];
                mma16816(oacc[n], pah[k4], bh0, bh1);
                mma16816(oacc[n], pah[k4], bl0, bl1);
                mma16816(oacc[n], pal[k4], bh0, bh1);
            }
        }

        __syncthreads();
        if (tid == 0 && kt + 2 < nkt) issue(kt + 2);
    }

    // ---- epilogue: normalize, fp16-split, store into packed wo A-images ----
    const float i0 = 1.0f / l0, i1 = 1.0f / l1;
#pragma unroll
    for (int n = 0; n < 16; n++) {
        const int d = n * 8 + lc * 2;
        const int kc = h * 4 + (d >> 5);
        const int col = d & 31;
        uint32_t h0, lo0, h1, lo1;
        split2pack_h(oacc[n][0] * i0, oacc[n][1] * i0, h0, lo0);
        split2pack_h(oacc[n][2] * i1, oacc[n][3] * i1, h1, lo1);
        const size_t off0 = ((size_t)(qt * KC_N + kc) * 128 + rloc)     * 40 + col;
        const size_t off1 = ((size_t)(qt * KC_N + kc) * 128 + rloc + 8) * 40 + col;
        *(uint32_t*)(Ohg + off0) = h0;
        *(uint32_t*)(Olg + off0) = lo0;
        *(uint32_t*)(Ohg + off1) = h1;
        *(uint32_t*)(Olg + off1) = lo1;
    }
}

// ===========================================================================
// Launch
// ===========================================================================
extern "C" void kernel_launch(void* const* d_in, const int* in_sizes, int n_in,
                              void* d_out, int out_size) {
    const float* x  = (const float*)d_in[0];
    const float* wq = (const float*)d_in[1];
    const float* wk = (const float*)d_in[2];
    const float* wv = (const float*)d_in[3];
    const float* wo = (const float*)d_in[4];
    float* out = (float*)d_out;

    const int S = in_sizes[0] / DMODEL;   // 2048

    float *q, *k, *v;
    cudaGetSymbolAddress((void**)&q, g_q);
    cudaGetSymbolAddress((void**)&k, g_k);
    cudaGetSymbolAddress((void**)&v, g_v);

    __nv_bfloat16 *xh, *xl, *wqh, *wql, *wkh, *wkl, *wvh, *wvl;
    __nv_bfloat16 *kph, *kpl, *vph, *vpl;
    __half *oh, *ol, *wo1;
    cudaGetSymbolAddress((void**)&xh, g_xh);   cudaGetSymbolAddress((void**)&xl, g_xl);
    cudaGetSymbolAddress((void**)&wqh, g_wqh); cudaGetSymbolAddress((void**)&wql, g_wql);
    cudaGetSymbolAddress((void**)&wkh, g_wkh); cudaGetSymbolAddress((void**)&wkl, g_wkl);
    cudaGetSymbolAddress((void**)&wvh, g_wvh); cudaGetSymbolAddress((void**)&wvl, g_wvl);
    cudaGetSymbolAddress((void**)&oh, g_oh);   cudaGetSymbolAddress((void**)&ol, g_ol);
    cudaGetSymbolAddress((void**)&wo1, g_wo1);
    cudaGetSymbolAddress((void**)&kph, g_kph); cudaGetSymbolAddress((void**)&kpl, g_kpl);
    cudaGetSymbolAddress((void**)&vph, g_vph); cudaGetSymbolAddress((void**)&vpl, g_vpl);

    // ---- pack + split ----
    {
        int n4 = (S * DMODEL) / 4;
        pack_a_split<<<(n4 + 255) / 256, 256>>>((const float4*)x, xh, xl, n4);
    }
    {
        int n4 = (DMODEL * NH * HD) / 4;
        pack_b_split<<<(n4 + 255) / 256, 256>>>((const float4*)wq, wqh, wql, 12, n4);
        pack_b_f16<<<(n4 + 255) / 256, 256>>>((const float4*)wo, wo1, n4);
    }
    {
        int n4 = (DMODEL * NKV * HD) / 4;
        pack_b_split<<<(n4 + 255) / 256, 256>>>((const float4*)wk, wkh, wkl, 9, n4);
        pack_b_split<<<(n4 + 255) / 256, 256>>>((const float4*)wv, wvh, wvl, 9, n4);
    }

    cudaFuncSetAttribute(gemm_qkv_kernel, cudaFuncAttributeMaxDynamicSharedMemorySize, GEMM_SMEM);
    cudaFuncSetAttribute(gemm_wo_kernel,  cudaFuncAttributeMaxDynamicSharedMemorySize, GEMM2_SMEM);

    // ---- QKV projections (bf16 3-term, unchanged) ----
    gemm_qkv_kernel<<<dim3(40, S / 128), 256, GEMM_SMEM>>>(
        xh, xl, wqh, wql, wkh, wkl, wvh, wvl, q, k, v);

    // ---- RoPE + attention-operand packing ----
    rope_kernel<<<dim3(S, NH), 64>>>(q, NH);
    rope_k_pack<<<dim3(S, NKV), 64>>>(k, kph, kpl);
    pack_v<<<128, 256>>>(v, vph, vpl);

    // ---- flash attention -> packed fp16 wo A-images ----
    cudaFuncSetAttribute(attn_mma, cudaFuncAttributeMaxDynamicSharedMemorySize, ATTN_SMEM);
    attn_mma<<<dim3(S / QTI, NH), 256, ATTN_SMEM>>>(q, kph, kpl, vph, vpl, oh, ol);

    // ---- output projection (fp16 2-term) ----
    gemm_wo_kernel<<<dim3(DMODEL / 128, S / 128), 256, GEMM2_SMEM>>>(oh, ol, wo1, out);
}

// round 14
// speedup vs baseline: 9.9665x; 1.4144x over previous
#include <cuda_runtime.h>
#include <cuda_bf16.h>
#include <cuda_fp16.h>
#include <mma.h>
#include <math.h>
#include <stdint.h>

using namespace nvcuda;

#define DMODEL 4096
#define NH 32
#define NKV 4
#define HD 128
#define S_MAX 2048

// fp32 activations (GEMM outputs)
__device__ float g_q[S_MAX * NH * HD];
__device__ float g_k[S_MAX * NKV * HD];
__device__ float g_v[S_MAX * NKV * HD];

// ---- packed smem-image layouts (all fp16 now) ----
// GEMM A-image per (by, kc): 128 rows x 40 cols (32 data + 8 pad)
// GEMM B-image per (bx, kc): 32 rows x 136 cols (128 data + 8 pad)
#define A_IMG 5120
#define B_IMG 4352
#define KC_N 128

__device__ __half g_xh[16 * KC_N * A_IMG],  g_xl[16 * KC_N * A_IMG];
__device__ __half g_oh[16 * KC_N * A_IMG],  g_ol[16 * KC_N * A_IMG];
__device__ __half g_wq1[32 * KC_N * B_IMG];
__device__ __half g_wk1[4 * KC_N * B_IMG];
__device__ __half g_wv1[4 * KC_N * B_IMG];
__device__ __half g_wo1[32 * KC_N * B_IMG];
// attention K images per (kvh, kt): 64 x 136 fp16 ; V-transposed: 128 x 72 fp16
__device__ __half g_kp1[4 * 32 * 64 * 136];
__device__ __half g_vp1[4 * 32 * 128 * 72];

// ===========================================================================
// helpers
// ===========================================================================
__device__ __forceinline__ uint32_t smem_u32(const void* p) {
    return (uint32_t)__cvta_generic_to_shared(p);
}
#define MBAR_INIT(addr, cnt) \
    asm volatile("mbarrier.init.shared.b64 [%0], %1;" :: "r"(addr), "r"(cnt) : "memory")
#define MBAR_EXPECT_TX(addr, tx) \
    asm volatile("mbarrier.arrive.expect_tx.shared.b64 _, [%0], %1;" :: "r"(addr), "r"(tx) : "memory")
#define MBAR_WAIT(addr, par) do {                                              \
    uint32_t _m = (uint32_t)(addr), _p = (uint32_t)(par), _d;                  \
    asm volatile("{\n\t.reg .pred p;\n\t"                                      \
        "mbarrier.try_wait.parity.acquire.cta.shared::cta.b64 p, [%1], %2;\n\t"\
        "selp.b32 %0, 1, 0, p;\n\t}" : "=r"(_d) : "r"(_m), "r"(_p) : "memory");\
    if (!_d) {                                                                 \
        asm volatile("{\n\t.reg .pred P1;\n\t"                                 \
            "WL_%=:\n\t"                                                       \
            "mbarrier.try_wait.parity.acquire.cta.shared::cta.b64 P1, [%0], %1, 0x989680;\n\t" \
            "@P1 bra.uni WD_%=;\n\t"                                           \
            "bra.uni WL_%=;\n\t"                                               \
            "WD_%=:\n\t}" :: "r"(_m), "r"(_p) : "memory");                     \
    }                                                                          \
} while (0)

__device__ __forceinline__ void bulk_g2s(uint32_t dst, const void* src,
                                         uint32_t bytes, uint32_t mbar) {
    asm volatile(
        "cp.async.bulk.shared::cta.global.mbarrier::complete_tx::bytes [%0], [%1], %2, [%3];"
        :: "r"(dst), "l"(src), "r"(bytes), "r"(mbar) : "memory");
}

// fp16 split-pack
__device__ __forceinline__ void split2pack_h(float x, float y,
                                             uint32_t& hi, uint32_t& lo) {
    union { __half2 h2; uint32_t u; } H, L;
    __half hx = __float2half_rn(x);
    __half hy = __float2half_rn(y);
    H.h2 = __halves2half2(hx, hy);
    L.h2 = __halves2half2(__float2half_rn(x - __half2float(hx)),
                          __float2half_rn(y - __half2float(hy)));
    hi = H.u; lo = L.u;
}

__device__ __forceinline__ void split_store4_h(__half* ph, __half* pl, float4 v) {
    union { __half h[4]; uint2 u; } H, L;
    H.h[0] = __float2half_rn(v.x);
    H.h[1] = __float2half_rn(v.y);
    H.h[2] = __float2half_rn(v.z);
    H.h[3] = __float2half_rn(v.w);
    L.h[0] = __float2half_rn(v.x - __half2float(H.h[0]));
    L.h[1] = __float2half_rn(v.y - __half2float(H.h[1]));
    L.h[2] = __float2half_rn(v.z - __half2float(H.h[2]));
    L.h[3] = __float2half_rn(v.w - __half2float(H.h[3]));
    *(uint2*)ph = H.u;
    *(uint2*)pl = L.u;
}

// ===========================================================================
// Prep kernels
// ===========================================================================
// x[2048][4096] fp32 -> padded fp16-split A-images
__global__ __launch_bounds__(256) void pack_a_split(const float4* __restrict__ x,
                                                    __half* __restrict__ hi,
                                                    __half* __restrict__ lo,
                                                    int n4) {
    int i = blockIdx.x * 256 + threadIdx.x;
    if (i >= n4) return;
    float4 v = x[i];
    int e = i * 4;
    int m = e >> 12, k = e & 4095;
    size_t out = ((size_t)((m >> 7) * KC_N + (k >> 5)) * 128 + (m & 127)) * 40 + (k & 31);
    split_store4_h(hi + out, lo + out, v);
}

// w[K=4096][N] fp32 -> padded fp16 SINGLE B-images (nb = log2 N)
__global__ __launch_bounds__(256) void pack_b_f16(const float4* __restrict__ w,
                                                  __half* __restrict__ o,
                                                  int nb, int n4) {
    int i = blockIdx.x * 256 + threadIdx.x;
    if (i >= n4) return;
    float4 v = w[i];
    int e = i * 4;
    int k = e >> nb, n = e & ((1 << nb) - 1);
    size_t out = ((size_t)((n >> 7) * KC_N + (k >> 5)) * 32 + (k & 31)) * 136 + (n & 127);
    union { __half h[4]; uint2 u; } O;
    O.h[0] = __float2half_rn(v.x);
    O.h[1] = __float2half_rn(v.y);
    O.h[2] = __float2half_rn(v.z);
    O.h[3] = __float2half_rn(v.w);
    *(uint2*)(o + out) = O.u;
}

// ===========================================================================
// Bulk-fed fp16 2-term wmma GEMM: C = Ahi*B + Alo*B (fp32 accum).
// stage: Ah 10240 | Al 10240 | B 8704 = 29184 B
// ===========================================================================
#define STAGE_B 29184
#define GEMM_SMEM (2 * STAGE_B)

__device__ void gemm2_core(const __half* __restrict__ Ahp,
                           const __half* __restrict__ Alp,
                           const __half* __restrict__ Bp,
                           float* __restrict__ C, int Ntot, int bx, int by,
                           char* sm) {
    __shared__ uint64_t mbv[2];
    const int tid = threadIdx.x;
    const int warp = tid >> 5, wm = warp >> 1, wn = warp & 1;
    const uint32_t sb = smem_u32(sm);
    const uint32_t mb = smem_u32(mbv);

    if (tid == 0) { MBAR_INIT(mb, 1); MBAR_INIT(mb + 8, 1); }
    __syncthreads();

    auto issue = [&](int t) {
        const int s = t & 1;
        const uint32_t bar = mb + 8 * s;
        const uint32_t d = sb + s * STAGE_B;
        MBAR_EXPECT_TX(bar, STAGE_B);
        const size_t aoff = (size_t)(by * KC_N + t) * A_IMG;
        const size_t boff = (size_t)(bx * KC_N + t) * B_IMG;
        bulk_g2s(d,         Ahp + aoff, 10240, bar);
        bulk_g2s(d + 10240, Alp + aoff, 10240, bar);
        bulk_g2s(d + 20480, Bp + boff,  8704,  bar);
    };

    wmma::fragment<wmma::accumulator, 16, 16, 16, float> acc[2][4];
#pragma unroll
    for (int i = 0; i < 2; i++)
#pragma unroll
        for (int j = 0; j < 4; j++) wmma::fill_fragment(acc[i][j], 0.0f);

    if (tid == 0) { issue(0); issue(1); }

    for (int t = 0; t < KC_N; t++) {
        const int s = t & 1;
        MBAR_WAIT(mb + 8 * s, (t >> 1) & 1);

        __half* p   = (__half*)(sm + s * STAGE_B);
        __half* pAh = p;
        __half* pAl = p + 5120;
        __half* pB  = p + 10240;

#pragma unroll
        for (int kt = 0; kt < 2; kt++) {
            wmma::fragment<wmma::matrix_a, 16, 16, 16, __half, wmma::row_major> ah[2], al[2];
            wmma::fragment<wmma::matrix_b, 16, 16, 16, __half, wmma::row_major> b[4];
#pragma unroll
            for (int i = 0; i < 2; i++) {
                wmma::load_matrix_sync(ah[i], pAh + (wm * 32 + i * 16) * 40 + kt * 16, 40);
                wmma::load_matrix_sync(al[i], pAl + (wm * 32 + i * 16) * 40 + kt * 16, 40);
            }
#pragma unroll
            for (int j = 0; j < 4; j++)
                wmma::load_matrix_sync(b[j], pB + kt * 16 * 136 + wn * 64 + j * 16, 136);
#pragma unroll
            for (int i = 0; i < 2; i++)
#pragma unroll
                for (int j = 0; j < 4; j++) {
                    wmma::mma_sync(acc[i][j], ah[i], b[j], acc[i][j]);
                    wmma::mma_sync(acc[i][j], al[i], b[j], acc[i][j]);
                }
        }
        __syncthreads();
        if (tid == 0 && t + 2 < KC_N) issue(t + 2);
    }

    const size_t arow0 = (size_t)by * 128;
    const size_t bcol0 = (size_t)bx * 128;
#pragma unroll
    for (int i = 0; i < 2; i++)
#pragma unroll
        for (int j = 0; j < 4; j++)
            wmma::store_matrix_sync(
                &C[(arow0 + wm * 32 + i * 16) * Ntot + bcol0 + wn * 64 + j * 16],
                acc[i][j], Ntot, wmma::mem_row_major);
}

// Merged Q/K/V projection: grid (32 + 4 + 4, 16)
__global__ __launch_bounds__(256, 2) void gemm_qkv_kernel(
    const __half* __restrict__ xh, const __half* __restrict__ xl,
    const __half* __restrict__ wq1, const __half* __restrict__ wk1,
    const __half* __restrict__ wv1,
    float* __restrict__ q, float* __restrict__ k, float* __restrict__ v) {
    extern __shared__ char sm[];
    const int bx = blockIdx.x;
    if (bx < 32)
        gemm2_core(xh, xl, wq1, q, NH * HD, bx, blockIdx.y, sm);
    else if (bx < 36)
        gemm2_core(xh, xl, wk1, k, NKV * HD, bx - 32, blockIdx.y, sm);
    else
        gemm2_core(xh, xl, wv1, v, NKV * HD, bx - 36, blockIdx.y, sm);
}

__global__ __launch_bounds__(256, 2) void gemm_wo_kernel(
    const __half* __restrict__ Ahp, const __half* __restrict__ Alp,
    const __half* __restrict__ Bp, float* __restrict__ C) {
    extern __shared__ char sm[];
    gemm2_core(Ahp, Alp, Bp, C, DMODEL, blockIdx.x, blockIdx.y, sm);
}

// ===========================================================================
// YaRN RoPE
// ===========================================================================
__device__ __forceinline__ void yarn_cs(int s, int j, float& c, float& sn) {
    const float expo = (float)(2 * j) / 128.0f;
    float invf = 1.0f / powf(10000.0f, expo);
    const float wl = 6.283185307179586f / invf;
    const float r = 163840.0f / wl;
    float gamma = (r - 1.0f) / 31.0f;
    gamma = fminf(fmaxf(gamma, 0.0f), 1.0f);
    invf = invf * ((1.0f - gamma) / 80.0f + gamma);
    const float ang = ((float)s * invf) / 1.19925088f;
    c = cosf(ang);
    sn = sinf(ang);
}

__global__ __launch_bounds__(64) void rope_kernel(float* __restrict__ x, int nheads) {
    const int s = blockIdx.x, h = blockIdx.y, j = threadIdx.x;
    float c, sn;
    yarn_cs(s, j, c, sn);
    float* base = x + ((size_t)s * nheads + h) * HD;
    const float x1 = base[j];
    const float x2 = base[j + 64];
    base[j]      = x1 * c - x2 * sn;
    base[j + 64] = x2 * c + x1 * sn;
}

// RoPE k fp32 -> single fp16 packed K-images [kvh][kt][64][136]
__global__ __launch_bounds__(64) void rope_k_pack(const float* __restrict__ kf,
                                                  __half* __restrict__ kp) {
    const int s = blockIdx.x, kvh = blockIdx.y, j = threadIdx.x;
    float c, sn;
    yarn_cs(s, j, c, sn);
    const float* base = kf + ((size_t)s * NKV + kvh) * HD;
    const float x1 = base[j];
    const float x2 = base[j + 64];
    const size_t ob = ((size_t)(kvh * 32 + (s >> 6)) * 64 + (s & 63)) * 136;
    kp[ob + j]      = __float2half_rn(x1 * c - x2 * sn);
    kp[ob + j + 64] = __float2half_rn(x2 * c + x1 * sn);
}

// v fp32 [S][512] -> transposed single-fp16 packed V-images [kvh][kt][128][72]
__global__ __launch_bounds__(256) void pack_v(const float* __restrict__ v,
                                              __half* __restrict__ vp) {
    __shared__ float tile[64][129];
    const int kt = blockIdx.x & 31, kvh = blockIdx.x >> 5;
    const int tid = threadIdx.x;
    const int s0 = kt * 64;
    for (int idx = tid; idx < 64 * 32; idx += 256) {
        int sl = idx >> 5, d4 = (idx & 31) << 2;
        float4 val = *(const float4*)(v + ((size_t)(s0 + sl) * NKV + kvh) * HD + d4);
        tile[sl][d4]     = val.x;
        tile[sl][d4 + 1] = val.y;
        tile[sl][d4 + 2] = val.z;
        tile[sl][d4 + 3] = val.w;
    }
    __syncthreads();
    const size_t ob = (size_t)(kvh * 32 + kt) * 128 * 72;
    for (int idx = tid; idx < 128 * 64; idx += 256) {
        int d = idx >> 6, c = idx & 63;
        vp[ob + (size_t)d * 72 + c] = __float2half_rn(tile[c][d]);
    }
}

// ===========================================================================
// Bulk-fed causal GQA flash attention (mma.m16n8k16 fp16 2-term).
// Q split fp16 in registers; K, V single fp16; P split fp16.
// ===========================================================================
#define QTI 128
#define KTI 64
#define QP  136
#define VP  72
#define KV_B 35840   // bytes: K 17408 | V 18432
#define ATTN_SMEM (2 * KV_B)

__device__ __forceinline__ void mma16816h(float* c, const uint32_t* a,
                                          uint32_t b0, uint32_t b1) {
    asm volatile(
        "mma.sync.aligned.m16n8k16.row.col.f32.f16.f16.f32 "
        "{%0,%1,%2,%3}, {%4,%5,%6,%7}, {%8,%9}, {%0,%1,%2,%3};\n"
        : "+f"(c[0]), "+f"(c[1]), "+f"(c[2]), "+f"(c[3])
        : "r"(a[0]), "r"(a[1]), "r"(a[2]), "r"(a[3]), "r"(b0), "r"(b1));
}

__global__ __launch_bounds__(256) void attn_mma(const float* __restrict__ Qg,
                                                const __half* __restrict__ kp,
                                                const __half* __restrict__ vp,
                                                __half* __restrict__ Ohg,
                                                __half* __restrict__ Olg) {
    extern __shared__ char smA[];
    __shared__ uint64_t mbv[2];

    const int qt   = gridDim.x - 1 - blockIdx.x;   // big tiles first
    const int h    = blockIdx.y;
    const int kvh  = h >> 3;
    const int tid  = threadIdx.x;
    const int warp = tid >> 5;
    const int lane = tid & 31;
    const int lg   = lane >> 2;
    const int lc   = lane & 3;
    const int q0   = qt * QTI;
    const int rloc = warp * 16 + lg;
    const float scale = 0.08838834764831845f;
    const uint32_t sb = smem_u32(smA);
    const uint32_t mb = smem_u32(mbv);
    const int nkt = 2 * qt + 2;

    if (tid == 0) { MBAR_INIT(mb, 1); MBAR_INIT(mb + 8, 1); }

    // ---- Q tile split fp16 into (temporarily free) stage space ----
    {
        __half* Qh = (__half*)smA;                    // 128*136*2 = 34816 B
        __half* Ql = (__half*)(smA + 34816);          // another 34816 B (fits 71680)
        for (int i = tid; i < QTI * 32; i += 256) {
            int r = i >> 5, dc = (i & 31) << 2;
            float4 v = *(const float4*)(Qg + ((size_t)(q0 + r) * NH + h) * HD + dc);
            v.x *= scale; v.y *= scale; v.z *= scale; v.w *= scale;
            split_store4_h(Qh + r * QP + dc, Ql + r * QP + dc, v);
        }
    }
    __syncthreads();

    // ---- hoist Q fragments into registers ----
    uint32_t qah[8][4], qal[8][4];
    {
        const __half* Qh = (const __half*)smA;
        const __half* Ql = (const __half*)(smA + 34816);
#pragma unroll
        for (int dk = 0; dk < 8; dk++) {
            const int cb = dk * 16 + lc * 2;
            qah[dk][0] = *(const uint32_t*)&Qh[(rloc)     * QP + cb];
            qah[dk][1] = *(const uint32_t*)&Qh[(rloc + 8) * QP + cb];
            qah[dk][2] = *(const uint32_t*)&Qh[(rloc)     * QP + cb + 8];
            qah[dk][3] = *(const uint32_t*)&Qh[(rloc + 8) * QP + cb + 8];
            qal[dk][0] = *(const uint32_t*)&Ql[(rloc)     * QP + cb];
            qal[dk][1] = *(const uint32_t*)&Ql[(rloc + 8) * QP + cb];
            qal[dk][2] = *(const uint32_t*)&Ql[(rloc)     * QP + cb + 8];
            qal[dk][3] = *(const uint32_t*)&Ql[(rloc + 8) * QP + cb + 8];
        }
    }
    __syncthreads();   // Q reads done: stages free for KV

    auto issue = [&](int kt) {
        const int s = kt & 1;
        const uint32_t bar = mb + 8 * s;
        const uint32_t d = sb + s * KV_B;
        MBAR_EXPECT_TX(bar, KV_B);
        const size_t koff = (size_t)(kvh * 32 + kt) * 64 * 136;
        const size_t voff = (size_t)(kvh * 32 + kt) * 128 * 72;
        bulk_g2s(d,         kp + koff, 17408, bar);
        bulk_g2s(d + 17408, vp + voff, 18432, bar);
    };
    if (tid == 0) { issue(0); issue(1); }

    float oacc[16][4];
#pragma unroll
    for (int n = 0; n < 16; n++)
#pragma unroll
        for (int i = 0; i < 4; i++) oacc[n][i] = 0.0f;
    float m0 = -1e30f, m1 = -1e30f, l0 = 0.0f, l1 = 0.0f;

    for (int kt = 0; kt < nkt; kt++) {
        const int s = kt & 1;
        MBAR_WAIT(mb + 8 * s, (kt >> 1) & 1);
        const __half* Kp  = (const __half*)(smA + s * KV_B);
        const __half* Vtp = (const __half*)(smA + s * KV_B + 17408);
        const int k0 = kt * KTI;

        // ---- S = Q K^T (2-term fp16) ----
        float sc[8][4];
#pragma unroll
        for (int j = 0; j < 8; j++)
#pragma unroll
            for (int i = 0; i < 4; i++) sc[j][i] = 0.0f;

#pragma unroll
        for (int dk = 0; dk < 8; dk++) {
            const int cb = dk * 16 + lc * 2;
#pragma unroll
            for (int j = 0; j < 8; j++) {
                const int krow = j * 8 + lg;
                uint32_t b0 = *(const uint32_t*)&Kp[krow * QP + cb];
                uint32_t b1 = *(const uint32_t*)&Kp[krow * QP + cb + 8];
                mma16816h(sc[j], qah[dk], b0, b1);
                mma16816h(sc[j], qal[dk], b0, b1);
            }
        }

        // ---- causal mask ----
        const bool dm = (kt >= 2 * qt);
        if (dm) {
#pragma unroll
            for (int j = 0; j < 8; j++) {
                const int keyb = k0 + j * 8 + lc * 2;
#pragma unroll
                for (int i = 0; i < 4; i++) {
                    const int key = keyb + (i & 1);
                    const int qr  = q0 + rloc + ((i >> 1) << 3);
                    if (key > qr) sc[j][i] = -1e30f;
                }
            }
        }

        // ---- online softmax ----
        float mx0 = -1e30f, mx1 = -1e30f;
#pragma unroll
        for (int j = 0; j < 8; j++) {
            mx0 = fmaxf(mx0, fmaxf(sc[j][0], sc[j][1]));
            mx1 = fmaxf(mx1, fmaxf(sc[j][2], sc[j][3]));
        }
        mx0 = fmaxf(mx0, __shfl_xor_sync(0xffffffffu, mx0, 1));
        mx0 = fmaxf(mx0, __shfl_xor_sync(0xffffffffu, mx0, 2));
        mx1 = fmaxf(mx1, __shfl_xor_sync(0xffffffffu, mx1, 1));
        mx1 = fmaxf(mx1, __shfl_xor_sync(0xffffffffu, mx1, 2));

        const float mn0 = fmaxf(m0, mx0), mn1 = fmaxf(m1, mx1);
        const float a0 = __expf(m0 - mn0), a1 = __expf(m1 - mn1);
        m0 = mn0; m1 = mn1;
        l0 *= a0; l1 *= a1;
#pragma unroll
        for (int n = 0; n < 16; n++) {
            oacc[n][0] *= a0; oacc[n][1] *= a0;
            oacc[n][2] *= a1; oacc[n][3] *= a1;
        }

        float rs0 = 0.0f, rs1 = 0.0f;
#pragma unroll
        for (int j = 0; j < 8; j++) {
            sc[j][0] = __expf(sc[j][0] - mn0); rs0 += sc[j][0];
            sc[j][1] = __expf(sc[j][1] - mn0); rs0 += sc[j][1];
            sc[j][2] = __expf(sc[j][2] - mn1); rs1 += sc[j][2];
            sc[j][3] = __expf(sc[j][3] - mn1); rs1 += sc[j][3];
        }
        rs0 += __shfl_xor_sync(0xffffffffu, rs0, 1);
        rs0 += __shfl_xor_sync(0xffffffffu, rs0, 2);
        rs1 += __shfl_xor_sync(0xffffffffu, rs1, 1);
        rs1 += __shfl_xor_sync(0xffffffffu, rs1, 2);
        l0 += rs0; l1 += rs1;

        // ---- P fragments (split fp16) ----
        uint32_t pah[4][4], pal[4][4];
#pragma unroll
        for (int k4 = 0; k4 < 4; k4++) {
            const int j0 = 2 * k4, j1 = 2 * k4 + 1;
            split2pack_h(sc[j0][0], sc[j0][1], pah[k4][0], pal[k4][0]);
            split2pack_h(sc[j0][2], sc[j0][3], pah[k4][1], pal[k4][1]);
            split2pack_h(sc[j1][0], sc[j1][1], pah[k4][2], pal[k4][2]);
            split2pack_h(sc[j1][2], sc[j1][3], pah[k4][3], pal[k4][3]);
        }

        // ---- O += P V (2-term fp16) ----
#pragma unroll
        for (int k4 = 0; k4 < 4; k4++) {
            const int kb = k4 * 16 + lc * 2;
#pragma unroll
            for (int n = 0; n < 16; n++) {
                const int drow = n * 8 + lg;
                uint32_t b0 = *(const uint32_t*)&Vtp[drow * VP + kb];
                uint32_t b1 = *(const uint32_t*)&Vtp[drow * VP + kb + 8];
                mma16816h(oacc[n], pah[k4], b0, b1);
                mma16816h(oacc[n], pal[k4], b0, b1);
            }
        }

        __syncthreads();
        if (tid == 0 && kt + 2 < nkt) issue(kt + 2);
    }

    // ---- epilogue: normalize, fp16-split, store into packed wo A-images ----
    const float i0 = 1.0f / l0, i1 = 1.0f / l1;
#pragma unroll
    for (int n = 0; n < 16; n++) {
        const int d = n * 8 + lc * 2;
        const int kc = h * 4 + (d >> 5);
        const int col = d & 31;
        uint32_t h0, lo0, h1, lo1;
        split2pack_h(oacc[n][0] * i0, oacc[n][1] * i0, h0, lo0);
        split2pack_h(oacc[n][2] * i1, oacc[n][3] * i1, h1, lo1);
        const size_t off0 = ((size_t)(qt * KC_N + kc) * 128 + rloc)     * 40 + col;
        const size_t off1 = ((size_t)(qt * KC_N + kc) * 128 + rloc + 8) * 40 + col;
        *(uint32_t*)(Ohg + off0) = h0;
        *(uint32_t*)(Olg + off0) = lo0;
        *(uint32_t*)(Ohg + off1) = h1;
        *(uint32_t*)(Olg + off1) = lo1;
    }
}

// ===========================================================================
// Launch
// ===========================================================================
extern "C" void kernel_launch(void* const* d_in, const int* in_sizes, int n_in,
                              void* d_out, int out_size) {
    const float* x  = (const float*)d_in[0];
    const float* wq = (const float*)d_in[1];
    const float* wk = (const float*)d_in[2];
    const float* wv = (const float*)d_in[3];
    const float* wo = (const float*)d_in[4];
    float* out = (float*)d_out;

    const int S = in_sizes[0] / DMODEL;   // 2048

    float *q, *k, *v;
    cudaGetSymbolAddress((void**)&q, g_q);
    cudaGetSymbolAddress((void**)&k, g_k);
    cudaGetSymbolAddress((void**)&v, g_v);

    __half *xh, *xl, *oh, *ol, *wq1, *wk1, *wv1, *wo1, *kp1, *vp1;
    cudaGetSymbolAddress((void**)&xh, g_xh);   cudaGetSymbolAddress((void**)&xl, g_xl);
    cudaGetSymbolAddress((void**)&oh, g_oh);   cudaGetSymbolAddress((void**)&ol, g_ol);
    cudaGetSymbolAddress((void**)&wq1, g_wq1); cudaGetSymbolAddress((void**)&wk1, g_wk1);
    cudaGetSymbolAddress((void**)&wv1, g_wv1); cudaGetSymbolAddress((void**)&wo1, g_wo1);
    cudaGetSymbolAddress((void**)&kp1, g_kp1); cudaGetSymbolAddress((void**)&vp1, g_vp1);

    // ---- pack ----
    {
        int n4 = (S * DMODEL) / 4;
        pack_a_split<<<(n4 + 255) / 256, 256>>>((const float4*)x, xh, xl, n4);
    }
    {
        int n4 = (DMODEL * NH * HD) / 4;
        pack_b_f16<<<(n4 + 255) / 256, 256>>>((const float4*)wq, wq1, 12, n4);
        pack_b_f16<<<(n4 + 255) / 256, 256>>>((const float4*)wo, wo1, 12, n4);
    }
    {
        int n4 = (DMODEL * NKV * HD) / 4;
        pack_b_f16<<<(n4 + 255) / 256, 256>>>((const float4*)wk, wk1, 9, n4);
        pack_b_f16<<<(n4 + 255) / 256, 256>>>((const float4*)wv, wv1, 9, n4);
    }

    cudaFuncSetAttribute(gemm_qkv_kernel, cudaFuncAttributeMaxDynamicSharedMemorySize, GEMM_SMEM);
    cudaFuncSetAttribute(gemm_wo_kernel,  cudaFuncAttributeMaxDynamicSharedMemorySize, GEMM_SMEM);

    // ---- QKV projections (fp16 2-term) ----
    gemm_qkv_kernel<<<dim3(40, S / 128), 256, GEMM_SMEM>>>(xh, xl, wq1, wk1, wv1, q, k, v);

    // ---- RoPE + attention-operand packing ----
    rope_kernel<<<dim3(S, NH), 64>>>(q, NH);
    rope_k_pack<<<dim3(S, NKV), 64>>>(k, kp1);
    pack_v<<<128, 256>>>(v, vp1);

    // ---- flash attention (fp16 2-term) -> packed fp16 wo A-images ----
    cudaFuncSetAttribute(attn_mma, cudaFuncAttributeMaxDynamicSharedMemorySize, ATTN_SMEM);
    attn_mma<<<dim3(S / QTI, NH), 256, ATTN_SMEM>>>(q, kp1, vp1, oh, ol);

    // ---- output projection (fp16 2-term) ----
    gemm_wo_kernel<<<dim3(DMODEL / 128, S / 128), 256, GEMM_SMEM>>>(oh, ol, wo1, out);
}

// round 16
// speedup vs baseline: 10.1402x; 1.0174x over previous
#include <cuda_runtime.h>
#include <cuda_bf16.h>
#include <cuda_fp16.h>
#include <mma.h>
#include <math.h>
#include <stdint.h>

using namespace nvcuda;

#define DMODEL 4096
#define NH 32
#define NKV 4
#define HD 128
#define S_MAX 2048

// fp32 activations (GEMM outputs)
__device__ float g_q[S_MAX * NH * HD];
__device__ float g_k[S_MAX * NKV * HD];
__device__ float g_v[S_MAX * NKV * HD];

// YaRN cos/sin table [S][64]
__device__ float2 g_cs[S_MAX * 64];

// ---- packed smem-image layouts (all fp16) ----
#define A_IMG 5120
#define B_IMG 4352
#define KC_N 128

__device__ __half g_xh[16 * KC_N * A_IMG],  g_xl[16 * KC_N * A_IMG];
__device__ __half g_oh[16 * KC_N * A_IMG],  g_ol[16 * KC_N * A_IMG];
__device__ __half g_wq1[32 * KC_N * B_IMG];
__device__ __half g_wk1[4 * KC_N * B_IMG];
__device__ __half g_wv1[4 * KC_N * B_IMG];
__device__ __half g_wo1[32 * KC_N * B_IMG];
__device__ __half g_kp1[4 * 32 * 64 * 136];
__device__ __half g_vp1[4 * 32 * 128 * 72];

// ===========================================================================
// helpers
// ===========================================================================
__device__ __forceinline__ uint32_t smem_u32(const void* p) {
    return (uint32_t)__cvta_generic_to_shared(p);
}
#define MBAR_INIT(addr, cnt) \
    asm volatile("mbarrier.init.shared.b64 [%0], %1;" :: "r"(addr), "r"(cnt) : "memory")
#define MBAR_EXPECT_TX(addr, tx) \
    asm volatile("mbarrier.arrive.expect_tx.shared.b64 _, [%0], %1;" :: "r"(addr), "r"(tx) : "memory")
#define MBAR_WAIT(addr, par) do {                                              \
    uint32_t _m = (uint32_t)(addr), _p = (uint32_t)(par), _d;                  \
    asm volatile("{\n\t.reg .pred p;\n\t"                                      \
        "mbarrier.try_wait.parity.acquire.cta.shared::cta.b64 p, [%1], %2;\n\t"\
        "selp.b32 %0, 1, 0, p;\n\t}" : "=r"(_d) : "r"(_m), "r"(_p) : "memory");\
    if (!_d) {                                                                 \
        asm volatile("{\n\t.reg .pred P1;\n\t"                                 \
            "WL_%=:\n\t"                                                       \
            "mbarrier.try_wait.parity.acquire.cta.shared::cta.b64 P1, [%0], %1, 0x989680;\n\t" \
            "@P1 bra.uni WD_%=;\n\t"                                           \
            "bra.uni WL_%=;\n\t"                                               \
            "WD_%=:\n\t}" :: "r"(_m), "r"(_p) : "memory");                     \
    }                                                                          \
} while (0)

__device__ __forceinline__ void bulk_g2s(uint32_t dst, const void* src,
                                         uint32_t bytes, uint32_t mbar) {
    asm volatile(
        "cp.async.bulk.shared::cta.global.mbarrier::complete_tx::bytes [%0], [%1], %2, [%3];"
        :: "r"(dst), "l"(src), "r"(bytes), "r"(mbar) : "memory");
}

__device__ __forceinline__ void split2pack_h(float x, float y,
                                             uint32_t& hi, uint32_t& lo) {
    union { __half2 h2; uint32_t u; } H, L;
    __half hx = __float2half_rn(x);
    __half hy = __float2half_rn(y);
    H.h2 = __halves2half2(hx, hy);
    L.h2 = __halves2half2(__float2half_rn(x - __half2float(hx)),
                          __float2half_rn(y - __half2float(hy)));
    hi = H.u; lo = L.u;
}

__device__ __forceinline__ void split_store4_h(__half* ph, __half* pl, float4 v) {
    union { __half h[4]; uint2 u; } H, L;
    H.h[0] = __float2half_rn(v.x);
    H.h[1] = __float2half_rn(v.y);
    H.h[2] = __float2half_rn(v.z);
    H.h[3] = __float2half_rn(v.w);
    L.h[0] = __float2half_rn(v.x - __half2float(H.h[0]));
    L.h[1] = __float2half_rn(v.y - __half2float(H.h[1]));
    L.h[2] = __float2half_rn(v.z - __half2float(H.h[2]));
    L.h[3] = __float2half_rn(v.w - __half2float(H.h[3]));
    *(uint2*)ph = H.u;
    *(uint2*)pl = L.u;
}

// 8 elems (2 float4) -> one uint4 hi + one uint4 lo
__device__ __forceinline__ void split_store8_h(__half* ph, __half* pl,
                                               float4 a, float4 b) {
    union { __half h[8]; uint4 u; } H, L;
    const float* f[2] = {&a.x, &b.x};
#pragma unroll
    for (int g = 0; g < 2; g++)
#pragma unroll
        for (int i = 0; i < 4; i++) {
            float x = f[g][i];
            __half hx = __float2half_rn(x);
            H.h[g * 4 + i] = hx;
            L.h[g * 4 + i] = __float2half_rn(x - __half2float(hx));
        }
    *(uint4*)ph = H.u;
    *(uint4*)pl = L.u;
}

// ===========================================================================
// Prep kernels (16 elems/thread)
// ===========================================================================
// x[2048][4096] fp32 -> padded fp16-split A-images
__global__ __launch_bounds__(256) void pack_a_split(const float4* __restrict__ x,
                                                    __half* __restrict__ hi,
                                                    __half* __restrict__ lo,
                                                    int n16) {
    int i = blockIdx.x * 256 + threadIdx.x;
    if (i >= n16) return;
    float4 v0 = x[i * 4], v1 = x[i * 4 + 1], v2 = x[i * 4 + 2], v3 = x[i * 4 + 3];
    int e = i * 16;
    int m = e >> 12, k = e & 4095;
    size_t out = ((size_t)((m >> 7) * KC_N + (k >> 5)) * 128 + (m & 127)) * 40 + (k & 31);
    split_store8_h(hi + out,     lo + out,     v0, v1);
    split_store8_h(hi + out + 8, lo + out + 8, v2, v3);
}

// w[K=4096][N] fp32 -> padded fp16 SINGLE B-images (nb = log2 N)
__global__ __launch_bounds__(256) void pack_b_f16(const float4* __restrict__ w,
                                                  __half* __restrict__ o,
                                                  int nb, int n16) {
    int i = blockIdx.x * 256 + threadIdx.x;
    if (i >= n16) return;
    float4 v0 = w[i * 4], v1 = w[i * 4 + 1], v2 = w[i * 4 + 2], v3 = w[i * 4 + 3];
    int e = i * 16;
    int k = e >> nb, n = e & ((1 << nb) - 1);
    size_t out = ((size_t)((n >> 7) * KC_N + (k >> 5)) * 32 + (k & 31)) * 136 + (n & 127);
    union { __half h[8]; uint4 u; } O;
    const float4 vv[4] = {v0, v1, v2, v3};
#pragma unroll
    for (int g = 0; g < 2; g++) {
#pragma unroll
        for (int q = 0; q < 2; q++) {
            const float* f = &vv[g * 2 + q].x;
#pragma unroll
            for (int j = 0; j < 4; j++) O.h[q * 4 + j] = __float2half_rn(f[j]);
        }
        *(uint4*)(o + out + g * 8) = O.u;
    }
}

// ===========================================================================
// YaRN cos/sin table
// ===========================================================================
__device__ __forceinline__ void yarn_cs(int s, int j, float& c, float& sn) {
    const float expo = (float)(2 * j) / 128.0f;
    float invf = 1.0f / powf(10000.0f, expo);
    const float wl = 6.283185307179586f / invf;
    const float r = 163840.0f / wl;
    float gamma = (r - 1.0f) / 31.0f;
    gamma = fminf(fmaxf(gamma, 0.0f), 1.0f);
    invf = invf * ((1.0f - gamma) / 80.0f + gamma);
    const float ang = ((float)s * invf) / 1.19925088f;
    c = cosf(ang);
    sn = sinf(ang);
}

__global__ __launch_bounds__(64) void build_cs(float2* __restrict__ tab) {
    const int s = blockIdx.x, j = threadIdx.x;
    float c, sn;
    yarn_cs(s, j, c, sn);
    tab[s * 64 + j] = make_float2(c, sn);
}

// RoPE k fp32 -> single fp16 packed K-images [kvh][kt][64][136]
__global__ __launch_bounds__(64) void rope_k_pack(const float* __restrict__ kf,
                                                  const float2* __restrict__ tab,
                                                  __half* __restrict__ kp) {
    const int s = blockIdx.x, kvh = blockIdx.y, j = threadIdx.x;
    const float2 cs = tab[s * 64 + j];
    const float* base = kf + ((size_t)s * NKV + kvh) * HD;
    const float x1 = base[j];
    const float x2 = base[j + 64];
    const size_t ob = ((size_t)(kvh * 32 + (s >> 6)) * 64 + (s & 63)) * 136;
    kp[ob + j]      = __float2half_rn(x1 * cs.x - x2 * cs.y);
    kp[ob + j + 64] = __float2half_rn(x2 * cs.x + x1 * cs.y);
}

// v fp32 [S][512] -> transposed single-fp16 packed V-images [kvh][kt][128][72]
__global__ __launch_bounds__(256) void pack_v(const float* __restrict__ v,
                                              __half* __restrict__ vp) {
    __shared__ float tile[64][129];
    const int kt = blockIdx.x & 31, kvh = blockIdx.x >> 5;
    const int tid = threadIdx.x;
    const int s0 = kt * 64;
    for (int idx = tid; idx < 64 * 32; idx += 256) {
        int sl = idx >> 5, d4 = (idx & 31) << 2;
        float4 val = *(const float4*)(v + ((size_t)(s0 + sl) * NKV + kvh) * HD + d4);
        tile[sl][d4]     = val.x;
        tile[sl][d4 + 1] = val.y;
        tile[sl][d4 + 2] = val.z;
        tile[sl][d4 + 3] = val.w;
    }
    __syncthreads();
    const size_t ob = (size_t)(kvh * 32 + kt) * 128 * 72;
    for (int idx = tid; idx < 128 * 64; idx += 256) {
        int d = idx >> 6, c = idx & 63;
        vp[ob + (size_t)d * 72 + c] = __float2half_rn(tile[c][d]);
    }
}

// ===========================================================================
// Bulk-fed fp16 2-term wmma GEMM: C = Ahi*B + Alo*B (fp32 accum).
// ===========================================================================
#define STAGE_B 29184
#define GEMM_SMEM (2 * STAGE_B)

__device__ void gemm2_core(const __half* __restrict__ Ahp,
                           const __half* __restrict__ Alp,
                           const __half* __restrict__ Bp,
                           float* __restrict__ C, int Ntot, int bx, int by,
                           char* sm) {
    __shared__ uint64_t mbv[2];
    const int tid = threadIdx.x;
    const int warp = tid >> 5, wm = warp >> 1, wn = warp & 1;
    const uint32_t sb = smem_u32(sm);
    const uint32_t mb = smem_u32(mbv);

    if (tid == 0) { MBAR_INIT(mb, 1); MBAR_INIT(mb + 8, 1); }
    __syncthreads();

    auto issue = [&](int t) {
        const int s = t & 1;
        const uint32_t bar = mb + 8 * s;
        const uint32_t d = sb + s * STAGE_B;
        MBAR_EXPECT_TX(bar, STAGE_B);
        const size_t aoff = (size_t)(by * KC_N + t) * A_IMG;
        const size_t boff = (size_t)(bx * KC_N + t) * B_IMG;
        bulk_g2s(d,         Ahp + aoff, 10240, bar);
        bulk_g2s(d + 10240, Alp + aoff, 10240, bar);
        bulk_g2s(d + 20480, Bp + boff,  8704,  bar);
    };

    wmma::fragment<wmma::accumulator, 16, 16, 16, float> acc[2][4];
#pragma unroll
    for (int i = 0; i < 2; i++)
#pragma unroll
        for (int j = 0; j < 4; j++) wmma::fill_fragment(acc[i][j], 0.0f);

    if (tid == 0) { issue(0); issue(1); }

    for (int t = 0; t < KC_N; t++) {
        const int s = t & 1;
        MBAR_WAIT(mb + 8 * s, (t >> 1) & 1);

        __half* p   = (__half*)(sm + s * STAGE_B);
        __half* pAh = p;
        __half* pAl = p + 5120;
        __half* pB  = p + 10240;

#pragma unroll
        for (int kt = 0; kt < 2; kt++) {
            wmma::fragment<wmma::matrix_a, 16, 16, 16, __half, wmma::row_major> ah[2], al[2];
            wmma::fragment<wmma::matrix_b, 16, 16, 16, __half, wmma::row_major> b[4];
#pragma unroll
            for (int i = 0; i < 2; i++) {
                wmma::load_matrix_sync(ah[i], pAh + (wm * 32 + i * 16) * 40 + kt * 16, 40);
                wmma::load_matrix_sync(al[i], pAl + (wm * 32 + i * 16) * 40 + kt * 16, 40);
            }
#pragma unroll
            for (int j = 0; j < 4; j++)
                wmma::load_matrix_sync(b[j], pB + kt * 16 * 136 + wn * 64 + j * 16, 136);
#pragma unroll
            for (int i = 0; i < 2; i++)
#pragma unroll
                for (int j = 0; j < 4; j++) {
                    wmma::mma_sync(acc[i][j], ah[i], b[j], acc[i][j]);
                    wmma::mma_sync(acc[i][j], al[i], b[j], acc[i][j]);
                }
        }
        __syncthreads();
        if (tid == 0 && t + 2 < KC_N) issue(t + 2);
    }

    const size_t arow0 = (size_t)by * 128;
    const size_t bcol0 = (size_t)bx * 128;
#pragma unroll
    for (int i = 0; i < 2; i++)
#pragma unroll
        for (int j = 0; j < 4; j++)
            wmma::store_matrix_sync(
                &C[(arow0 + wm * 32 + i * 16) * Ntot + bcol0 + wn * 64 + j * 16],
                acc[i][j], Ntot, wmma::mem_row_major);
}

__global__ __launch_bounds__(256, 2) void gemm_qkv_kernel(
    const __half* __restrict__ xh, const __half* __restrict__ xl,
    const __half* __restrict__ wq1, const __half* __restrict__ wk1,
    const __half* __restrict__ wv1,
    float* __restrict__ q, float* __restrict__ k, float* __restrict__ v) {
    extern __shared__ char sm[];
    const int bx = blockIdx.x;
    if (bx < 32)
        gemm2_core(xh, xl, wq1, q, NH * HD, bx, blockIdx.y, sm);
    else if (bx < 36)
        gemm2_core(xh, xl, wk1, k, NKV * HD, bx - 32, blockIdx.y, sm);
    else
        gemm2_core(xh, xl, wv1, v, NKV * HD, bx - 36, blockIdx.y, sm);
}

__global__ __launch_bounds__(256, 2) void gemm_wo_kernel(
    const __half* __restrict__ Ahp, const __half* __restrict__ Alp,
    const __half* __restrict__ Bp, float* __restrict__ C) {
    extern __shared__ char sm[];
    gemm2_core(Ahp, Alp, Bp, C, DMODEL, blockIdx.x, blockIdx.y, sm);
}

// ===========================================================================
// Bulk-fed causal GQA flash attention (fp16 2-term) with fused q-RoPE.
// ===========================================================================
#define QTI 128
#define KTI 64
#define QP  136
#define VP  72
#define KV_B 35840
#define ATTN_SMEM (2 * KV_B)

__device__ __forceinline__ void mma16816h(float* c, const uint32_t* a,
                                          uint32_t b0, uint32_t b1) {
    asm volatile(
        "mma.sync.aligned.m16n8k16.row.col.f32.f16.f16.f32 "
        "{%0,%1,%2,%3}, {%4,%5,%6,%7}, {%8,%9}, {%0,%1,%2,%3};\n"
        : "+f"(c[0]), "+f"(c[1]), "+f"(c[2]), "+f"(c[3])
        : "r"(a[0]), "r"(a[1]), "r"(a[2]), "r"(a[3]), "r"(b0), "r"(b1));
}

__global__ __launch_bounds__(256) void attn_mma(const float* __restrict__ Qg,
                                                const float2* __restrict__ tab,
                                                const __half* __restrict__ kp,
                                                const __half* __restrict__ vp,
                                                __half* __restrict__ Ohg,
                                                __half* __restrict__ Olg) {
    extern __shared__ char smA[];
    __shared__ uint64_t mbv[2];

    const int qt   = gridDim.x - 1 - blockIdx.x;   // big tiles first
    const int h    = blockIdx.y;
    const int kvh  = h >> 3;
    const int tid  = threadIdx.x;
    const int warp = tid >> 5;
    const int lane = tid & 31;
    const int lg   = lane >> 2;
    const int lc   = lane & 3;
    const int q0   = qt * QTI;
    const int rloc = warp * 16 + lg;
    const float scale = 0.08838834764831845f;
    const uint32_t sb = smem_u32(smA);
    const uint32_t mb = smem_u32(mbv);
    const int nkt = 2 * qt + 2;

    if (tid == 0) { MBAR_INIT(mb, 1); MBAR_INIT(mb + 8, 1); }

    // ---- Q tile: load un-roped q, apply RoPE (table) + scale, split fp16 ----
    {
        __half* Qh = (__half*)smA;
        __half* Ql = (__half*)(smA + 34816);
        for (int i = tid; i < QTI * 16; i += 256) {
            int r = i >> 4, j4 = (i & 15) << 2;   // j4 in 0..60
            const float* qrow = Qg + ((size_t)(q0 + r) * NH + h) * HD;
            float4 x1 = *(const float4*)(qrow + j4);
            float4 x2 = *(const float4*)(qrow + j4 + 64);
            const float2* cs = tab + (size_t)(q0 + r) * 64 + j4;
            float4 r1, r2;
#pragma unroll
            for (int jj = 0; jj < 4; jj++) {
                float2 c = cs[jj];
                float a = (&x1.x)[jj], b = (&x2.x)[jj];
                (&r1.x)[jj] = (a * c.x - b * c.y) * scale;
                (&r2.x)[jj] = (b * c.x + a * c.y) * scale;
            }
            split_store4_h(Qh + r * QP + j4,      Ql + r * QP + j4,      r1);
            split_store4_h(Qh + r * QP + j4 + 64, Ql + r * QP + j4 + 64, r2);
        }
    }
    __syncthreads();

    // ---- hoist Q fragments into registers ----
    uint32_t qah[8][4], qal[8][4];
    {
        const __half* Qh = (const __half*)smA;
        const __half* Ql = (const __half*)(smA + 34816);
#pragma unroll
        for (int dk = 0; dk < 8; dk++) {
            const int cb = dk * 16 + lc * 2;
            qah[dk][0] = *(const uint32_t*)&Qh[(rloc)     * QP + cb];
            qah[dk][1] = *(const uint32_t*)&Qh[(rloc + 8) * QP + cb];
            qah[dk][2] = *(const uint32_t*)&Qh[(rloc)     * QP + cb + 8];
            qah[dk][3] = *(const uint32_t*)&Qh[(rloc + 8) * QP + cb + 8];
            qal[dk][0] = *(const uint32_t*)&Ql[(rloc)     * QP + cb];
            qal[dk][1] = *(const uint32_t*)&Ql[(rloc + 8) * QP + cb];
            qal[dk][2] = *(const uint32_t*)&Ql[(rloc)     * QP + cb + 8];
            qal[dk][3] = *(const uint32_t*)&Ql[(rloc + 8) * QP + cb + 8];
        }
    }
    __syncthreads();   // Q reads done: stages free for KV

    auto issue = [&](int kt) {
        const int s = kt & 1;
        const uint32_t bar = mb + 8 * s;
        const uint32_t d = sb + s * KV_B;
        MBAR_EXPECT_TX(bar, KV_B);
        const size_t koff = (size_t)(kvh * 32 + kt) * 64 * 136;
        const size_t voff = (size_t)(kvh * 32 + kt) * 128 * 72;
        bulk_g2s(d,         kp + koff, 17408, bar);
        bulk_g2s(d + 17408, vp + voff, 18432, bar);
    };
    if (tid == 0) { issue(0); issue(1); }

    float oacc[16][4];
#pragma unroll
    for (int n = 0; n < 16; n++)
#pragma unroll
        for (int i = 0; i < 4; i++) oacc[n][i] = 0.0f;
    float m0 = -1e30f, m1 = -1e30f, l0 = 0.0f, l1 = 0.0f;

    for (int kt = 0; kt < nkt; kt++) {
        const int s = kt & 1;
        MBAR_WAIT(mb + 8 * s, (kt >> 1) & 1);
        const __half* Kp  = (const __half*)(smA + s * KV_B);
        const __half* Vtp = (const __half*)(smA + s * KV_B + 17408);
        const int k0 = kt * KTI;

        float sc[8][4];
#pragma unroll
        for (int j = 0; j < 8; j++)
#pragma unroll
            for (int i = 0; i < 4; i++) sc[j][i] = 0.0f;

#pragma unroll
        for (int dk = 0; dk < 8; dk++) {
            const int cb = dk * 16 + lc * 2;
#pragma unroll
            for (int j = 0; j < 8; j++) {
                const int krow = j * 8 + lg;
                uint32_t b0 = *(const uint32_t*)&Kp[krow * QP + cb];
                uint32_t b1 = *(const uint32_t*)&Kp[krow * QP + cb + 8];
                mma16816h(sc[j], qah[dk], b0, b1);
                mma16816h(sc[j], qal[dk], b0, b1);
            }
        }

        const bool dm = (kt >= 2 * qt);
        if (dm) {
#pragma unroll
            for (int j = 0; j < 8; j++) {
                const int keyb = k0 + j * 8 + lc * 2;
#pragma unroll
                for (int i = 0; i < 4; i++) {
                    const int key = keyb + (i & 1);
                    const int qr  = q0 + rloc + ((i >> 1) << 3);
                    if (key > qr) sc[j][i] = -1e30f;
                }
            }
        }

        float mx0 = -1e30f, mx1 = -1e30f;
#pragma unroll
        for (int j = 0; j < 8; j++) {
            mx0 = fmaxf(mx0, fmaxf(sc[j][0], sc[j][1]));
            mx1 = fmaxf(mx1, fmaxf(sc[j][2], sc[j][3]));
        }
        mx0 = fmaxf(mx0, __shfl_xor_sync(0xffffffffu, mx0, 1));
        mx0 = fmaxf(mx0, __shfl_xor_sync(0xffffffffu, mx0, 2));
        mx1 = fmaxf(mx1, __shfl_xor_sync(0xffffffffu, mx1, 1));
        mx1 = fmaxf(mx1, __shfl_xor_sync(0xffffffffu, mx1, 2));

        const float mn0 = fmaxf(m0, mx0), mn1 = fmaxf(m1, mx1);
        const float a0 = __expf(m0 - mn0), a1 = __expf(m1 - mn1);
        m0 = mn0; m1 = mn1;
        l0 *= a0; l1 *= a1;
#pragma unroll
        for (int n = 0; n < 16; n++) {
            oacc[n][0] *= a0; oacc[n][1] *= a0;
            oacc[n][2] *= a1; oacc[n][3] *= a1;
        }

        float rs0 = 0.0f, rs1 = 0.0f;
#pragma unroll
        for (int j = 0; j < 8; j++) {
            sc[j][0] = __expf(sc[j][0] - mn0); rs0 += sc[j][0];
            sc[j][1] = __expf(sc[j][1] - mn0); rs0 += sc[j][1];
            sc[j][2] = __expf(sc[j][2] - mn1); rs1 += sc[j][2];
            sc[j][3] = __expf(sc[j][3] - mn1); rs1 += sc[j][3];
        }
        rs0 += __shfl_xor_sync(0xffffffffu, rs0, 1);
        rs0 += __shfl_xor_sync(0xffffffffu, rs0, 2);
        rs1 += __shfl_xor_sync(0xffffffffu, rs1, 1);
        rs1 += __shfl_xor_sync(0xffffffffu, rs1, 2);
        l0 += rs0; l1 += rs1;

        uint32_t pah[4][4], pal[4][4];
#pragma unroll
        for (int k4 = 0; k4 < 4; k4++) {
            const int j0 = 2 * k4, j1 = 2 * k4 + 1;
            split2pack_h(sc[j0][0], sc[j0][1], pah[k4][0], pal[k4][0]);
            split2pack_h(sc[j0][2], sc[j0][3], pah[k4][1], pal[k4][1]);
            split2pack_h(sc[j1][0], sc[j1][1], pah[k4][2], pal[k4][2]);
            split2pack_h(sc[j1][2], sc[j1][3], pah[k4][3], pal[k4][3]);
        }

#pragma unroll
        for (int k4 = 0; k4 < 4; k4++) {
            const int kb = k4 * 16 + lc * 2;
#pragma unroll
            for (int n = 0; n < 16; n++) {
                const int drow = n * 8 + lg;
                uint32_t b0 = *(const uint32_t*)&Vtp[drow * VP + kb];
                uint32_t b1 = *(const uint32_t*)&Vtp[drow * VP + kb + 8];
                mma16816h(oacc[n], pah[k4], b0, b1);
                mma16816h(oacc[n], pal[k4], b0, b1);
            }
        }

        __syncthreads();
        if (tid == 0 && kt + 2 < nkt) issue(kt + 2);
    }

    // ---- epilogue: normalize, fp16-split, store into packed wo A-images ----
    const float i0 = 1.0f / l0, i1 = 1.0f / l1;
#pragma unroll
    for (int n = 0; n < 16; n++) {
        const int d = n * 8 + lc * 2;
        const int kc = h * 4 + (d >> 5);
        const int col = d & 31;
        uint32_t h0, lo0, h1, lo1;
        split2pack_h(oacc[n][0] * i0, oacc[n][1] * i0, h0, lo0);
        split2pack_h(oacc[n][2] * i1, oacc[n][3] * i1, h1, lo1);
        const size_t off0 = ((size_t)(qt * KC_N + kc) * 128 + rloc)     * 40 + col;
        const size_t off1 = ((size_t)(qt * KC_N + kc) * 128 + rloc + 8) * 40 + col;
        *(uint32_t*)(Ohg + off0) = h0;
        *(uint32_t*)(Olg + off0) = lo0;
        *(uint32_t*)(Ohg + off1) = h1;
        *(uint32_t*)(Olg + off1) = lo1;
    }
}

// ===========================================================================
// Launch
// ===========================================================================
extern "C" void kernel_launch(void* const* d_in, const int* in_sizes, int n_in,
                              void* d_out, int out_size) {
    const float* x  = (const float*)d_in[0];
    const float* wq = (const float*)d_in[1];
    const float* wk = (const float*)d_in[2];
    const float* wv = (const float*)d_in[3];
    const float* wo = (const float*)d_in[4];
    float* out = (float*)d_out;

    const int S = in_sizes[0] / DMODEL;   // 2048

    float *q, *k, *v;
    float2* cs;
    cudaGetSymbolAddress((void**)&q, g_q);
    cudaGetSymbolAddress((void**)&k, g_k);
    cudaGetSymbolAddress((void**)&v, g_v);
    cudaGetSymbolAddress((void**)&cs, g_cs);

    __half *xh, *xl, *oh, *ol, *wq1, *wk1, *wv1, *wo1, *kp1, *vp1;
    cudaGetSymbolAddress((void**)&xh, g_xh);   cudaGetSymbolAddress((void**)&xl, g_xl);
    cudaGetSymbolAddress((void**)&oh, g_oh);   cudaGetSymbolAddress((void**)&ol, g_ol);
    cudaGetSymbolAddress((void**)&wq1, g_wq1); cudaGetSymbolAddress((void**)&wk1, g_wk1);
    cudaGetSymbolAddress((void**)&wv1, g_wv1); cudaGetSymbolAddress((void**)&wo1, g_wo1);
    cudaGetSymbolAddress((void**)&kp1, g_kp1); cudaGetSymbolAddress((void**)&vp1, g_vp1);

    // ---- cos/sin table + packing (16 elems/thread) ----
    build_cs<<<S, 64>>>(cs);
    {
        int n16 = (S * DMODEL) / 16;
        pack_a_split<<<(n16 + 255) / 256, 256>>>((const float4*)x, xh, xl, n16);
    }
    {
        int n16 = (DMODEL * NH * HD) / 16;
        pack_b_f16<<<(n16 + 255) / 256, 256>>>((const float4*)wq, wq1, 12, n16);
        pack_b_f16<<<(n16 + 255) / 256, 256>>>((const float4*)wo, wo1, 12, n16);
    }
    {
        int n16 = (DMODEL * NKV * HD) / 16;
        pack_b_f16<<<(n16 + 255) / 256, 256>>>((const float4*)wk, wk1, 9, n16);
        pack_b_f16<<<(n16 + 255) / 256, 256>>>((const float4*)wv, wv1, 9, n16);
    }

    cudaFuncSetAttribute(gemm_qkv_kernel, cudaFuncAttributeMaxDynamicSharedMemorySize, GEMM_SMEM);
    cudaFuncSetAttribute(gemm_wo_kernel,  cudaFuncAttributeMaxDynamicSharedMemorySize, GEMM_SMEM);

    // ---- QKV projections (fp16 2-term) ----
    gemm_qkv_kernel<<<dim3(40, S / 128), 256, GEMM_SMEM>>>(xh, xl, wq1, wk1, wv1, q, k, v);

    // ---- K RoPE+pack, V pack (q RoPE fused into attention) ----
    rope_k_pack<<<dim3(S, NKV), 64>>>(k, cs, kp1);
    pack_v<<<128, 256>>>(v, vp1);

    // ---- flash attention (fused q-RoPE, fp16 2-term) ----
    cudaFuncSetAttribute(attn_mma, cudaFuncAttributeMaxDynamicSharedMemorySize, ATTN_SMEM);
    attn_mma<<<dim3(S / QTI, NH), 256, ATTN_SMEM>>>(q, cs, kp1, vp1, oh, ol);

    // ---- output projection (fp16 2-term) ----
    gemm_wo_kernel<<<dim3(DMODEL / 128, S / 128), 256, GEMM_SMEM>>>(oh, ol, wo1, out);
}

// round 17
// speedup vs baseline: 10.5627x; 1.0417x over previous
#include <cuda_runtime.h>
#include <cuda_bf16.h>
#include <cuda_fp16.h>
#include <mma.h>
#include <math.h>
#include <stdint.h>

using namespace nvcuda;

#define DMODEL 4096
#define NH 32
#define NKV 4
#define HD 128
#define S_MAX 2048

// fp32 activations (GEMM outputs)
__device__ float g_q[S_MAX * NH * HD];
__device__ float g_k[S_MAX * NKV * HD];
__device__ float g_v[S_MAX * NKV * HD];

// YaRN cos/sin table [S][64]
__device__ float2 g_cs[S_MAX * 64];

// ---- packed smem-image layouts (fp16, BK=64 chunks) ----
// A-image per (by, kc): 128 rows x 72 cols (64 data + 8 pad)
// B-image per (bx, kc): 64 rows x 136 cols (128 data + 8 pad)
#define A_IMG 9216              // elems (128*72)
#define B_IMG 8704              // elems (64*136)
#define KC64 64                 // K chunks (4096/64)

__device__ __half g_xh[16 * KC64 * A_IMG],  g_xl[16 * KC64 * A_IMG];
__device__ __half g_oh[16 * KC64 * A_IMG],  g_ol[16 * KC64 * A_IMG];
__device__ __half g_wq1[32 * KC64 * B_IMG];
__device__ __half g_wk1[4 * KC64 * B_IMG];
__device__ __half g_wv1[4 * KC64 * B_IMG];
__device__ __half g_wo1[32 * KC64 * B_IMG];
__device__ __half g_kp1[4 * 32 * 64 * 136];
__device__ __half g_vp1[4 * 32 * 128 * 72];

// ===========================================================================
// helpers
// ===========================================================================
__device__ __forceinline__ uint32_t smem_u32(const void* p) {
    return (uint32_t)__cvta_generic_to_shared(p);
}
#define MBAR_INIT(addr, cnt) \
    asm volatile("mbarrier.init.shared.b64 [%0], %1;" :: "r"(addr), "r"(cnt) : "memory")
#define MBAR_EXPECT_TX(addr, tx) \
    asm volatile("mbarrier.arrive.expect_tx.shared.b64 _, [%0], %1;" :: "r"(addr), "r"(tx) : "memory")
#define MBAR_WAIT(addr, par) do {                                              \
    uint32_t _m = (uint32_t)(addr), _p = (uint32_t)(par), _d;                  \
    asm volatile("{\n\t.reg .pred p;\n\t"                                      \
        "mbarrier.try_wait.parity.acquire.cta.shared::cta.b64 p, [%1], %2;\n\t"\
        "selp.b32 %0, 1, 0, p;\n\t}" : "=r"(_d) : "r"(_m), "r"(_p) : "memory");\
    if (!_d) {                                                                 \
        asm volatile("{\n\t.reg .pred P1;\n\t"                                 \
            "WL_%=:\n\t"                                                       \
            "mbarrier.try_wait.parity.acquire.cta.shared::cta.b64 P1, [%0], %1, 0x989680;\n\t" \
            "@P1 bra.uni WD_%=;\n\t"                                           \
            "bra.uni WL_%=;\n\t"                                               \
            "WD_%=:\n\t}" :: "r"(_m), "r"(_p) : "memory");                     \
    }                                                                          \
} while (0)

__device__ __forceinline__ void bulk_g2s(uint32_t dst, const void* src,
                                         uint32_t bytes, uint32_t mbar) {
    asm volatile(
        "cp.async.bulk.shared::cta.global.mbarrier::complete_tx::bytes [%0], [%1], %2, [%3];"
        :: "r"(dst), "l"(src), "r"(bytes), "r"(mbar) : "memory");
}

__device__ __forceinline__ void split2pack_h(float x, float y,
                                             uint32_t& hi, uint32_t& lo) {
    union { __half2 h2; uint32_t u; } H, L;
    __half hx = __float2half_rn(x);
    __half hy = __float2half_rn(y);
    H.h2 = __halves2half2(hx, hy);
    L.h2 = __halves2half2(__float2half_rn(x - __half2float(hx)),
                          __float2half_rn(y - __half2float(hy)));
    hi = H.u; lo = L.u;
}

__device__ __forceinline__ void split_store4_h(__half* ph, __half* pl, float4 v) {
    union { __half h[4]; uint2 u; } H, L;
    H.h[0] = __float2half_rn(v.x);
    H.h[1] = __float2half_rn(v.y);
    H.h[2] = __float2half_rn(v.z);
    H.h[3] = __float2half_rn(v.w);
    L.h[0] = __float2half_rn(v.x - __half2float(H.h[0]));
    L.h[1] = __float2half_rn(v.y - __half2float(H.h[1]));
    L.h[2] = __float2half_rn(v.z - __half2float(H.h[2]));
    L.h[3] = __float2half_rn(v.w - __half2float(H.h[3]));
    *(uint2*)ph = H.u;
    *(uint2*)pl = L.u;
}

__device__ __forceinline__ void split_store8_h(__half* ph, __half* pl,
                                               float4 a, float4 b) {
    union { __half h[8]; uint4 u; } H, L;
    const float* f[2] = {&a.x, &b.x};
#pragma unroll
    for (int g = 0; g < 2; g++)
#pragma unroll
        for (int i = 0; i < 4; i++) {
            float x = f[g][i];
            __half hx = __float2half_rn(x);
            H.h[g * 4 + i] = hx;
            L.h[g * 4 + i] = __float2half_rn(x - __half2float(hx));
        }
    *(uint4*)ph = H.u;
    *(uint4*)pl = L.u;
}

// ===========================================================================
// Prep kernels (16 elems/thread), BK=64 image layout
// ===========================================================================
// x[2048][4096] fp32 -> A-images [(m>>7)*64 + (k>>6)][m&127][k&63]
__global__ __launch_bounds__(256) void pack_a_split(const float4* __restrict__ x,
                                                    __half* __restrict__ hi,
                                                    __half* __restrict__ lo,
                                                    int n16) {
    int i = blockIdx.x * 256 + threadIdx.x;
    if (i >= n16) return;
    float4 v0 = x[i * 4], v1 = x[i * 4 + 1], v2 = x[i * 4 + 2], v3 = x[i * 4 + 3];
    int e = i * 16;
    int m = e >> 12, k = e & 4095;
    size_t out = ((size_t)((m >> 7) * KC64 + (k >> 6)) * 128 + (m & 127)) * 72 + (k & 63);
    split_store8_h(hi + out,     lo + out,     v0, v1);
    split_store8_h(hi + out + 8, lo + out + 8, v2, v3);
}

// w[K=4096][N] fp32 -> B-images [(n>>7)*64 + (k>>6)][k&63][n&127] (nb = log2 N)
__global__ __launch_bounds__(256) void pack_b_f16(const float4* __restrict__ w,
                                                  __half* __restrict__ o,
                                                  int nb, int n16) {
    int i = blockIdx.x * 256 + threadIdx.x;
    if (i >= n16) return;
    float4 v0 = w[i * 4], v1 = w[i * 4 + 1], v2 = w[i * 4 + 2], v3 = w[i * 4 + 3];
    int e = i * 16;
    int k = e >> nb, n = e & ((1 << nb) - 1);
    size_t out = ((size_t)((n >> 7) * KC64 + (k >> 6)) * 64 + (k & 63)) * 136 + (n & 127);
    union { __half h[8]; uint4 u; } O;
    const float4 vv[4] = {v0, v1, v2, v3};
#pragma unroll
    for (int g = 0; g < 2; g++) {
#pragma unroll
        for (int q = 0; q < 2; q++) {
            const float* f = &vv[g * 2 + q].x;
#pragma unroll
            for (int j = 0; j < 4; j++) O.h[q * 4 + j] = __float2half_rn(f[j]);
        }
        *(uint4*)(o + out + g * 8) = O.u;
    }
}

// ===========================================================================
// YaRN cos/sin table
// ===========================================================================
__device__ __forceinline__ void yarn_cs(int s, int j, float& c, float& sn) {
    const float expo = (float)(2 * j) / 128.0f;
    float invf = 1.0f / powf(10000.0f, expo);
    const float wl = 6.283185307179586f / invf;
    const float r = 163840.0f / wl;
    float gamma = (r - 1.0f) / 31.0f;
    gamma = fminf(fmaxf(gamma, 0.0f), 1.0f);
    invf = invf * ((1.0f - gamma) / 80.0f + gamma);
    const float ang = ((float)s * invf) / 1.19925088f;
    c = cosf(ang);
    sn = sinf(ang);
}

__global__ __launch_bounds__(64) void build_cs(float2* __restrict__ tab) {
    const int s = blockIdx.x, j = threadIdx.x;
    float c, sn;
    yarn_cs(s, j, c, sn);
    tab[s * 64 + j] = make_float2(c, sn);
}

// RoPE k fp32 -> single fp16 packed K-images [kvh][kt][64][136]
__global__ __launch_bounds__(64) void rope_k_pack(const float* __restrict__ kf,
                                                  const float2* __restrict__ tab,
                                                  __half* __restrict__ kp) {
    const int s = blockIdx.x, kvh = blockIdx.y, j = threadIdx.x;
    const float2 cs = tab[s * 64 + j];
    const float* base = kf + ((size_t)s * NKV + kvh) * HD;
    const float x1 = base[j];
    const float x2 = base[j + 64];
    const size_t ob = ((size_t)(kvh * 32 + (s >> 6)) * 64 + (s & 63)) * 136;
    kp[ob + j]      = __float2half_rn(x1 * cs.x - x2 * cs.y);
    kp[ob + j + 64] = __float2half_rn(x2 * cs.x + x1 * cs.y);
}

// v fp32 [S][512] -> transposed single-fp16 packed V-images [kvh][kt][128][72]
__global__ __launch_bounds__(256) void pack_v(const float* __restrict__ v,
                                              __half* __restrict__ vp) {
    __shared__ float tile[64][129];
    const int kt = blockIdx.x & 31, kvh = blockIdx.x >> 5;
    const int tid = threadIdx.x;
    const int s0 = kt * 64;
    for (int idx = tid; idx < 64 * 32; idx += 256) {
        int sl = idx >> 5, d4 = (idx & 31) << 2;
        float4 val = *(const float4*)(v + ((size_t)(s0 + sl) * NKV + kvh) * HD + d4);
        tile[sl][d4]     = val.x;
        tile[sl][d4 + 1] = val.y;
        tile[sl][d4 + 2] = val.z;
        tile[sl][d4 + 3] = val.w;
    }
    __syncthreads();
    const size_t ob = (size_t)(kvh * 32 + kt) * 128 * 72;
    for (int idx = tid; idx < 128 * 64; idx += 256) {
        int d = idx >> 6, c = idx & 63;
        vp[ob + (size_t)d * 72 + c] = __float2half_rn(tile[c][d]);
    }
}

// ===========================================================================
// Bulk-fed fp16 2-term wmma GEMM, BK=64: C = Ahi*B + Alo*B (fp32 accum).
// stage: Ah 18432 | Al 18432 | B 17408 = 54272 B ; 2 stages = 108.5 KB
// ===========================================================================
#define STAGE_B 54272
#define GEMM_SMEM (2 * STAGE_B)

__device__ void gemm2_core(const __half* __restrict__ Ahp,
                           const __half* __restrict__ Alp,
                           const __half* __restrict__ Bp,
                           float* __restrict__ C, int Ntot, int bx, int by,
                           char* sm) {
    __shared__ uint64_t mbv[2];
    const int tid = threadIdx.x;
    const int warp = tid >> 5, wm = warp >> 1, wn = warp & 1;
    const uint32_t sb = smem_u32(sm);
    const uint32_t mb = smem_u32(mbv);

    if (tid == 0) { MBAR_INIT(mb, 1); MBAR_INIT(mb + 8, 1); }
    __syncthreads();

    auto issue = [&](int t) {
        const int s = t & 1;
        const uint32_t bar = mb + 8 * s;
        const uint32_t d = sb + s * STAGE_B;
        MBAR_EXPECT_TX(bar, STAGE_B);
        const size_t aoff = (size_t)(by * KC64 + t) * A_IMG;
        const size_t boff = (size_t)(bx * KC64 + t) * B_IMG;
        bulk_g2s(d,         Ahp + aoff, 18432, bar);
        bulk_g2s(d + 18432, Alp + aoff, 18432, bar);
        bulk_g2s(d + 36864, Bp + boff,  17408, bar);
    };

    wmma::fragment<wmma::accumulator, 16, 16, 16, float> acc[2][4];
#pragma unroll
    for (int i = 0; i < 2; i++)
#pragma unroll
        for (int j = 0; j < 4; j++) wmma::fill_fragment(acc[i][j], 0.0f);

    if (tid == 0) { issue(0); issue(1); }

    for (int t = 0; t < KC64; t++) {
        const int s = t & 1;
        MBAR_WAIT(mb + 8 * s, (t >> 1) & 1);

        __half* p   = (__half*)(sm + s * STAGE_B);
        __half* pAh = p;
        __half* pAl = p + 9216;
        __half* pB  = p + 18432;

#pragma unroll
        for (int kt = 0; kt < 4; kt++) {
            wmma::fragment<wmma::matrix_a, 16, 16, 16, __half, wmma::row_major> ah[2], al[2];
            wmma::fragment<wmma::matrix_b, 16, 16, 16, __half, wmma::row_major> b[4];
#pragma unroll
            for (int i = 0; i < 2; i++) {
                wmma::load_matrix_sync(ah[i], pAh + (wm * 32 + i * 16) * 72 + kt * 16, 72);
                wmma::load_matrix_sync(al[i], pAl + (wm * 32 + i * 16) * 72 + kt * 16, 72);
            }
#pragma unroll
            for (int j = 0; j < 4; j++)
                wmma::load_matrix_sync(b[j], pB + kt * 16 * 136 + wn * 64 + j * 16, 136);
#pragma unroll
            for (int i = 0; i < 2; i++)
#pragma unroll
                for (int j = 0; j < 4; j++) {
                    wmma::mma_sync(acc[i][j], ah[i], b[j], acc[i][j]);
                    wmma::mma_sync(acc[i][j], al[i], b[j], acc[i][j]);
                }
        }
        __syncthreads();
        if (tid == 0 && t + 2 < KC64) issue(t + 2);
    }

    const size_t arow0 = (size_t)by * 128;
    const size_t bcol0 = (size_t)bx * 128;
#pragma unroll
    for (int i = 0; i < 2; i++)
#pragma unroll
        for (int j = 0; j < 4; j++)
            wmma::store_matrix_sync(
                &C[(arow0 + wm * 32 + i * 16) * Ntot + bcol0 + wn * 64 + j * 16],
                acc[i][j], Ntot, wmma::mem_row_major);
}

__global__ __launch_bounds__(256, 2) void gemm_qkv_kernel(
    const __half* __restrict__ xh, const __half* __restrict__ xl,
    const __half* __restrict__ wq1, const __half* __restrict__ wk1,
    const __half* __restrict__ wv1,
    float* __restrict__ q, float* __restrict__ k, float* __restrict__ v) {
    extern __shared__ char sm[];
    const int bx = blockIdx.x;
    if (bx < 32)
        gemm2_core(xh, xl, wq1, q, NH * HD, bx, blockIdx.y, sm);
    else if (bx < 36)
        gemm2_core(xh, xl, wk1, k, NKV * HD, bx - 32, blockIdx.y, sm);
    else
        gemm2_core(xh, xl, wv1, v, NKV * HD, bx - 36, blockIdx.y, sm);
}

__global__ __launch_bounds__(256, 2) void gemm_wo_kernel(
    const __half* __restrict__ Ahp, const __half* __restrict__ Alp,
    const __half* __restrict__ Bp, float* __restrict__ C) {
    extern __shared__ char sm[];
    gemm2_core(Ahp, Alp, Bp, C, DMODEL, blockIdx.x, blockIdx.y, sm);
}

// ===========================================================================
// Bulk-fed causal GQA flash attention (fp16 2-term) with fused q-RoPE.
// ===========================================================================
#define QTI 128
#define KTI 64
#define QP  136
#define VP  72
#define KV_B 35840
#define ATTN_SMEM (2 * KV_B)

__device__ __forceinline__ void mma16816h(float* c, const uint32_t* a,
                                          uint32_t b0, uint32_t b1) {
    asm volatile(
        "mma.sync.aligned.m16n8k16.row.col.f32.f16.f16.f32 "
        "{%0,%1,%2,%3}, {%4,%5,%6,%7}, {%8,%9}, {%0,%1,%2,%3};\n"
        : "+f"(c[0]), "+f"(c[1]), "+f"(c[2]), "+f"(c[3])
        : "r"(a[0]), "r"(a[1]), "r"(a[2]), "r"(a[3]), "r"(b0), "r"(b1));
}

__global__ __launch_bounds__(256) void attn_mma(const float* __restrict__ Qg,
                                                const float2* __restrict__ tab,
                                                const __half* __restrict__ kp,
                                                const __half* __restrict__ vp,
                                                __half* __restrict__ Ohg,
                                                __half* __restrict__ Olg) {
    extern __shared__ char smA[];
    __shared__ uint64_t mbv[2];

    const int qt   = gridDim.x - 1 - blockIdx.x;   // big tiles first
    const int h    = blockIdx.y;
    const int kvh  = h >> 3;
    const int tid  = threadIdx.x;
    const int warp = tid >> 5;
    const int lane = tid & 31;
    const int lg   = lane >> 2;
    const int lc   = lane & 3;
    const int q0   = qt * QTI;
    const int rloc = warp * 16 + lg;
    const float scale = 0.08838834764831845f;
    const uint32_t sb = smem_u32(smA);
    const uint32_t mb = smem_u32(mbv);
    const int nkt = 2 * qt + 2;

    if (tid == 0) { MBAR_INIT(mb, 1); MBAR_INIT(mb + 8, 1); }

    // ---- Q tile: load un-roped q, apply RoPE (table) + scale, split fp16 ----
    {
        __half* Qh = (__half*)smA;
        __half* Ql = (__half*)(smA + 34816);
        for (int i = tid; i < QTI * 16; i += 256) {
            int r = i >> 4, j4 = (i & 15) << 2;
            const float* qrow = Qg + ((size_t)(q0 + r) * NH + h) * HD;
            float4 x1 = *(const float4*)(qrow + j4);
            float4 x2 = *(const float4*)(qrow + j4 + 64);
            const float2* cs = tab + (size_t)(q0 + r) * 64 + j4;
            float4 r1, r2;
#pragma unroll
            for (int jj = 0; jj < 4; jj++) {
                float2 c = cs[jj];
                float a = (&x1.x)[jj], b = (&x2.x)[jj];
                (&r1.x)[jj] = (a * c.x - b * c.y) * scale;
                (&r2.x)[jj] = (b * c.x + a * c.y) * scale;
            }
            split_store4_h(Qh + r * QP + j4,      Ql + r * QP + j4,      r1);
            split_store4_h(Qh + r * QP + j4 + 64, Ql + r * QP + j4 + 64, r2);
        }
    }
    __syncthreads();

    uint32_t qah[8][4], qal[8][4];
    {
        const __half* Qh = (const __half*)smA;
        const __half* Ql = (const __half*)(smA + 34816);
#pragma unroll
        for (int dk = 0; dk < 8; dk++) {
            const int cb = dk * 16 + lc * 2;
            qah[dk][0] = *(const uint32_t*)&Qh[(rloc)     * QP + cb];
            qah[dk][1] = *(const uint32_t*)&Qh[(rloc + 8) * QP + cb];
            qah[dk][2] = *(const uint32_t*)&Qh[(rloc)     * QP + cb + 8];
            qah[dk][3] = *(const uint32_t*)&Qh[(rloc + 8) * QP + cb + 8];
            qal[dk][0] = *(const uint32_t*)&Ql[(rloc)     * QP + cb];
            qal[dk][1] = *(const uint32_t*)&Ql[(rloc + 8) * QP + cb];
            qal[dk][2] = *(const uint32_t*)&Ql[(rloc)     * QP + cb + 8];
            qal[dk][3] = *(const uint32_t*)&Ql[(rloc + 8) * QP + cb + 8];
        }
    }
    __syncthreads();   // Q reads done: stages free for KV

    auto issue = [&](int kt) {
        const int s = kt & 1;
        const uint32_t bar = mb + 8 * s;
        const uint32_t d = sb + s * KV_B;
        MBAR_EXPECT_TX(bar, KV_B);
        const size_t koff = (size_t)(kvh * 32 + kt) * 64 * 136;
        const size_t voff = (size_t)(kvh * 32 + kt) * 128 * 72;
        bulk_g2s(d,         kp + koff, 17408, bar);
        bulk_g2s(d + 17408, vp + voff, 18432, bar);
    };
    if (tid == 0) { issue(0); issue(1); }

    float oacc[16][4];
#pragma unroll
    for (int n = 0; n < 16; n++)
#pragma unroll
        for (int i = 0; i < 4; i++) oacc[n][i] = 0.0f;
    float m0 = -1e30f, m1 = -1e30f, l0 = 0.0f, l1 = 0.0f;

    for (int kt = 0; kt < nkt; kt++) {
        const int s = kt & 1;
        MBAR_WAIT(mb + 8 * s, (kt >> 1) & 1);
        const __half* Kp  = (const __half*)(smA + s * KV_B);
        const __half* Vtp = (const __half*)(smA + s * KV_B + 17408);
        const int k0 = kt * KTI;

        float sc[8][4];
#pragma unroll
        for (int j = 0; j < 8; j++)
#pragma unroll
            for (int i = 0; i < 4; i++) sc[j][i] = 0.0f;

#pragma unroll
        for (int dk = 0; dk < 8; dk++) {
            const int cb = dk * 16 + lc * 2;
#pragma unroll
            for (int j = 0; j < 8; j++) {
                const int krow = j * 8 + lg;
                uint32_t b0 = *(const uint32_t*)&Kp[krow * QP + cb];
                uint32_t b1 = *(const uint32_t*)&Kp[krow * QP + cb + 8];
                mma16816h(sc[j], qah[dk], b0, b1);
                mma16816h(sc[j], qal[dk], b0, b1);
            }
        }

        const bool dm = (kt >= 2 * qt);
        if (dm) {
#pragma unroll
            for (int j = 0; j < 8; j++) {
                const int keyb = k0 + j * 8 + lc * 2;
#pragma unroll
                for (int i = 0; i < 4; i++) {
                    const int key = keyb + (i & 1);
                    const int qr  = q0 + rloc + ((i >> 1) << 3);
                    if (key > qr) sc[j][i] = -1e30f;
                }
            }
        }

        float mx0 = -1e30f, mx1 = -1e30f;
#pragma unroll
        for (int j = 0; j < 8; j++) {
            mx0 = fmaxf(mx0, fmaxf(sc[j][0], sc[j][1]));
            mx1 = fmaxf(mx1, fmaxf(sc[j][2], sc[j][3]));
        }
        mx0 = fmaxf(mx0, __shfl_xor_sync(0xffffffffu, mx0, 1));
        mx0 = fmaxf(mx0, __shfl_xor_sync(0xffffffffu, mx0, 2));
        mx1 = fmaxf(mx1, __shfl_xor_sync(0xffffffffu, mx1, 1));
        mx1 = fmaxf(mx1, __shfl_xor_sync(0xffffffffu, mx1, 2));

        const float mn0 = fmaxf(m0, mx0), mn1 = fmaxf(m1, mx1);
        const float a0 = __expf(m0 - mn0), a1 = __expf(m1 - mn1);
        m0 = mn0; m1 = mn1;
        l0 *= a0; l1 *= a1;
#pragma unroll
        for (int n = 0; n < 16; n++) {
            oacc[n][0] *= a0; oacc[n][1] *= a0;
            oacc[n][2] *= a1; oacc[n][3] *= a1;
        }

        float rs0 = 0.0f, rs1 = 0.0f;
#pragma unroll
        for (int j = 0; j < 8; j++) {
            sc[j][0] = __expf(sc[j][0] - mn0); rs0 += sc[j][0];
            sc[j][1] = __expf(sc[j][1] - mn0); rs0 += sc[j][1];
            sc[j][2] = __expf(sc[j][2] - mn1); rs1 += sc[j][2];
            sc[j][3] = __expf(sc[j][3] - mn1); rs1 += sc[j][3];
        }
        rs0 += __shfl_xor_sync(0xffffffffu, rs0, 1);
        rs0 += __shfl_xor_sync(0xffffffffu, rs0, 2);
        rs1 += __shfl_xor_sync(0xffffffffu, rs1, 1);
        rs1 += __shfl_xor_sync(0xffffffffu, rs1, 2);
        l0 += rs0; l1 += rs1;

        uint32_t pah[4][4], pal[4][4];
#pragma unroll
        for (int k4 = 0; k4 < 4; k4++) {
            const int j0 = 2 * k4, j1 = 2 * k4 + 1;
            split2pack_h(sc[j0][0], sc[j0][1], pah[k4][0], pal[k4][0]);
            split2pack_h(sc[j0][2], sc[j0][3], pah[k4][1], pal[k4][1]);
            split2pack_h(sc[j1][0], sc[j1][1], pah[k4][2], pal[k4][2]);
            split2pack_h(sc[j1][2], sc[j1][3], pah[k4][3], pal[k4][3]);
        }

#pragma unroll
        for (int k4 = 0; k4 < 4; k4++) {
            const int kb = k4 * 16 + lc * 2;
#pragma unroll
            for (int n = 0; n < 16; n++) {
                const int drow = n * 8 + lg;
                uint32_t b0 = *(const uint32_t*)&Vtp[drow * VP + kb];
                uint32_t b1 = *(const uint32_t*)&Vtp[drow * VP + kb + 8];
                mma16816h(oacc[n], pah[k4], b0, b1);
                mma16816h(oacc[n], pal[k4], b0, b1);
            }
        }

        __syncthreads();
        if (tid == 0 && kt + 2 < nkt) issue(kt + 2);
    }

    // ---- epilogue: normalize, fp16-split, store into packed wo A-images ----
    // BK=64 A-image: kc = h*2 + (d>>6), col = d&63
    const float i0 = 1.0f / l0, i1 = 1.0f / l1;
#pragma unroll
    for (int n = 0; n < 16; n++) {
        const int d = n * 8 + lc * 2;
        const int kc = h * 2 + (d >> 6);
        const int col = d & 63;
        uint32_t h0, lo0, h1, lo1;
        split2pack_h(oacc[n][0] * i0, oacc[n][1] * i0, h0, lo0);
        split2pack_h(oacc[n][2] * i1, oacc[n][3] * i1, h1, lo1);
        const size_t off0 = ((size_t)(qt * KC64 + kc) * 128 + rloc)     * 72 + col;
        const size_t off1 = ((size_t)(qt * KC64 + kc) * 128 + rloc + 8) * 72 + col;
        *(uint32_t*)(Ohg + off0) = h0;
        *(uint32_t*)(Olg + off0) = lo0;
        *(uint32_t*)(Ohg + off1) = h1;
        *(uint32_t*)(Olg + off1) = lo1;
    }
}

// ===========================================================================
// Launch
// ===========================================================================
extern "C" void kernel_launch(void* const* d_in, const int* in_sizes, int n_in,
                              void* d_out, int out_size) {
    const float* x  = (const float*)d_in[0];
    const float* wq = (const float*)d_in[1];
    const float* wk = (const float*)d_in[2];
    const float* wv = (const float*)d_in[3];
    const float* wo = (const float*)d_in[4];
    float* out = (float*)d_out;

    const int S = in_sizes[0] / DMODEL;   // 2048

    float *q, *k, *v;
    float2* cs;
    cudaGetSymbolAddress((void**)&q, g_q);
    cudaGetSymbolAddress((void**)&k, g_k);
    cudaGetSymbolAddress((void**)&v, g_v);
    cudaGetSymbolAddress((void**)&cs, g_cs);

    __half *xh, *xl, *oh, *ol, *wq1, *wk1, *wv1, *wo1, *kp1, *vp1;
    cudaGetSymbolAddress((void**)&xh, g_xh);   cudaGetSymbolAddress((void**)&xl, g_xl);
    cudaGetSymbolAddress((void**)&oh, g_oh);   cudaGetSymbolAddress((void**)&ol, g_ol);
    cudaGetSymbolAddress((void**)&wq1, g_wq1); cudaGetSymbolAddress((void**)&wk1, g_wk1);
    cudaGetSymbolAddress((void**)&wv1, g_wv1); cudaGetSymbolAddress((void**)&wo1, g_wo1);
    cudaGetSymbolAddress((void**)&kp1, g_kp1); cudaGetSymbolAddress((void**)&vp1, g_vp1);

    // ---- cos/sin table + packing ----
    build_cs<<<S, 64>>>(cs);
    {
        int n16 = (S * DMODEL) / 16;
        pack_a_split<<<(n16 + 255) / 256, 256>>>((const float4*)x, xh, xl, n16);
    }
    {
        int n16 = (DMODEL * NH * HD) / 16;
        pack_b_f16<<<(n16 + 255) / 256, 256>>>((const float4*)wq, wq1, 12, n16);
        pack_b_f16<<<(n16 + 255) / 256, 256>>>((const float4*)wo, wo1, 12, n16);
    }
    {
        int n16 = (DMODEL * NKV * HD) / 16;
        pack_b_f16<<<(n16 + 255) / 256, 256>>>((const float4*)wk, wk1, 9, n16);
        pack_b_f16<<<(n16 + 255) / 256, 256>>>((const float4*)wv, wv1, 9, n16);
    }

    cudaFuncSetAttribute(gemm_qkv_kernel, cudaFuncAttributeMaxDynamicSharedMemorySize, GEMM_SMEM);
    cudaFuncSetAttribute(gemm_wo_kernel,  cudaFuncAttributeMaxDynamicSharedMemorySize, GEMM_SMEM);

    // ---- QKV projections (fp16 2-term, BK=64) ----
    gemm_qkv_kernel<<<dim3(40, S / 128), 256, GEMM_SMEM>>>(xh, xl, wq1, wk1, wv1, q, k, v);

    // ---- K RoPE+pack, V pack ----
    rope_k_pack<<<dim3(S, NKV), 64>>>(k, cs, kp1);
    pack_v<<<128, 256>>>(v, vp1);

    // ---- flash attention (fused q-RoPE, fp16 2-term) ----
    cudaFuncSetAttribute(attn_mma, cudaFuncAttributeMaxDynamicSharedMemorySize, ATTN_SMEM);
    attn_mma<<<dim3(S / QTI, NH), 256, ATTN_SMEM>>>(q, cs, kp1, vp1, oh, ol);

    // ---- output projection (fp16 2-term, BK=64) ----
    gemm_wo_kernel<<<dim3(DMODEL / 128, S / 128), 256, GEMM_SMEM>>>(oh, ol, wo1, out);
}